// round 1
// baseline (speedup 1.0000x reference)
#include <cuda_runtime.h>
#include <math.h>

#define FULLMASK 0xffffffffu

// ---------------------------------------------------------------------------
// Layout: 4 lanes per batch element (g = tid & 3), 64 amplitudes per thread.
// Qubit -> bit mapping (our private layout; only consistency matters):
//   q0 -> lane bit 0 (mask 1 in g)     q2 -> lane bit 1 (mask 2 in g)
//   q1 -> reg bit 5 (32)   q3 -> reg bit 4 (16)  q4 -> reg bit 3 (8)
//   q5 -> reg bit 2 (4)    q6 -> reg bit 1 (2)   q7 -> reg bit 0 (1)
// State is REAL during the 4 RY/CNOT cycles; complex only in the CRX/U3 layers.
// ---------------------------------------------------------------------------

template<int TM>
__device__ __forceinline__ void ry_reg(float (&a)[64], float c, float s) {
#pragma unroll
  for (int r = 0; r < 64; ++r) if (!(r & TM)) {
    float v0 = a[r], v1 = a[r + TM];
    a[r]      = c * v0 - s * v1;
    a[r + TM] = s * v0 + c * v1;
  }
}

template<int LM>
__device__ __forceinline__ void ry_lane(float (&a)[64], float c, float sg) {
#pragma unroll
  for (int r = 0; r < 64; ++r) {
    float p = __shfl_xor_sync(FULLMASK, a[r], LM);
    a[r] = c * a[r] + sg * p;
  }
}

// Fused: RY on lane-qubit LM immediately followed by CNOT(control=reg bit CM,
// target=lane-qubit LM). One exchange serves both gates.
template<int LM, int CM>
__device__ __forceinline__ void ry_lane_cnot(float (&a)[64], float c, float sg) {
#pragma unroll
  for (int r = 0; r < 64; ++r) {
    float p = __shfl_xor_sync(FULLMASK, a[r], LM);
    float mynew = c * a[r] + sg * p;   // my post-RY value
    float pnew  = c * p - sg * a[r];   // partner's post-RY value
    if (r & CM) a[r] = pnew;           // CNOT: control=1 amps take the swap
    else        a[r] = mynew;
  }
}

template<int CM, int TM>
__device__ __forceinline__ void cnot_rr(float (&a)[64]) {
#pragma unroll
  for (int r = 0; r < 64; ++r) if ((r & CM) && !(r & TM)) {
    float t = a[r]; a[r] = a[r + TM]; a[r + TM] = t;  // pure register rename
  }
}

template<int TM>
__device__ __forceinline__ void cnot_lr(float (&a)[64], bool f) {
#pragma unroll
  for (int r = 0; r < 64; ++r) if (!(r & TM)) {
    float v0 = a[r], v1 = a[r + TM];
    a[r]      = f ? v1 : v0;
    a[r + TM] = f ? v0 : v1;
  }
}

template<int CM, int LM>
__device__ __forceinline__ void cnot_rl(float (&a)[64]) {
#pragma unroll
  for (int r = 0; r < 64; ++r) if (r & CM)
    a[r] = __shfl_xor_sync(FULLMASK, a[r], LM);
}

// ---- complex-phase gates --------------------------------------------------
// CRX(theta): acts on control=1 amps: v0' = c v0 + s v1, v1' = s v0 + c v1
// with s = -i*sin(theta/2): (s*v).re = sh*v.im, (s*v).im = -sh*v.re

template<int CM, int TM>
__device__ __forceinline__ void crx_rr(float (&ar)[64], float (&ai)[64], float c, float sh) {
#pragma unroll
  for (int r = 0; r < 64; ++r) if ((r & CM) && !(r & TM)) {
    int r1 = r + TM;
    float v0r = ar[r], v0i = ai[r], v1r = ar[r1], v1i = ai[r1];
    ar[r]  = c * v0r + sh * v1i;
    ai[r]  = c * v0i - sh * v1r;
    ar[r1] = c * v1r + sh * v0i;
    ai[r1] = c * v1i - sh * v0r;
  }
}

template<int TM>
__device__ __forceinline__ void crx_lr(float (&ar)[64], float (&ai)[64], bool f, float c, float sh) {
  if (f) {
#pragma unroll
    for (int r = 0; r < 64; ++r) if (!(r & TM)) {
      int r1 = r + TM;
      float v0r = ar[r], v0i = ai[r], v1r = ar[r1], v1i = ai[r1];
      ar[r]  = c * v0r + sh * v1i;
      ai[r]  = c * v0i - sh * v1r;
      ar[r1] = c * v1r + sh * v0i;
      ai[r1] = c * v1i - sh * v0r;
    }
  }
}

template<int CM, int LM>
__device__ __forceinline__ void crx_rl(float (&ar)[64], float (&ai)[64], float c, float sh) {
#pragma unroll
  for (int r = 0; r < 64; ++r) if (r & CM) {
    float pr = __shfl_xor_sync(FULLMASK, ar[r], LM);
    float pi = __shfl_xor_sync(FULLMASK, ai[r], LM);
    // symmetric off-diagonal: new = c*mine + s*partner for both target bits
    ar[r] = c * ar[r] + sh * pi;
    ai[r] = c * ai[r] - sh * pr;
  }
}

template<int TM>
__device__ __forceinline__ void u3_reg(float (&ar)[64], float (&ai)[64],
    float m00r, float m01r, float m01i,
    float m10r, float m10i, float m11r, float m11i) {
#pragma unroll
  for (int r = 0; r < 64; ++r) if (!(r & TM)) {
    int r1 = r + TM;
    float v0r = ar[r], v0i = ai[r], v1r = ar[r1], v1i = ai[r1];
    ar[r]  = m00r * v0r + m01r * v1r - m01i * v1i;
    ai[r]  = m00r * v0i + m01r * v1i + m01i * v1r;
    ar[r1] = m10r * v0r - m10i * v0i + m11r * v1r - m11i * v1i;
    ai[r1] = m10r * v0i + m10i * v0r + m11r * v1i + m11i * v1r;
  }
}

__global__ void __launch_bounds__(128)
qcnn_kernel(const float* __restrict__ x,
            const float* __restrict__ crx_theta,
            const float* __restrict__ u3_params,
            const float* __restrict__ w1,
            const float* __restrict__ b1,
            const float* __restrict__ w2,
            const float* __restrict__ b2,
            float* __restrict__ out, int B)
{
  int tid  = blockIdx.x * blockDim.x + threadIdx.x;
  int elem = tid >> 2;
  if (elem >= B) return;
  int g = tid & 3;

  // --- angles (RY params reused across all 4 cycles) ---
  const float4* x4 = reinterpret_cast<const float4*>(x);
  float4 xa = x4[elem * 2 + 0];
  float4 xb = x4[elem * 2 + 1];
  float xv[8] = {xa.x, xa.y, xa.z, xa.w, xb.x, xb.y, xb.z, xb.w};
  float cq[8], sq[8];
#pragma unroll
  for (int q = 0; q < 8; ++q) sincosf(0.5f * xv[q], &sq[q], &cq[q]);

  bool g0 = (g & 1) != 0;
  bool g1 = (g & 2) != 0;
  float sg0 = g0 ? sq[0] : -sq[0];
  float sg2 = g1 ? sq[2] : -sq[2];

  // --- cycle 1: RYs on |0..0> == product state, built by doubling ---
  float sr[64];
  sr[0] = (g0 ? sq[0] : cq[0]) * (g1 ? sq[2] : cq[2]);
#pragma unroll
  for (int i = 0; i < 1;  ++i) { sr[i+1]  = sr[i]*sq[7]; sr[i] *= cq[7]; }
#pragma unroll
  for (int i = 0; i < 2;  ++i) { sr[i+2]  = sr[i]*sq[6]; sr[i] *= cq[6]; }
#pragma unroll
  for (int i = 0; i < 4;  ++i) { sr[i+4]  = sr[i]*sq[5]; sr[i] *= cq[5]; }
#pragma unroll
  for (int i = 0; i < 8;  ++i) { sr[i+8]  = sr[i]*sq[4]; sr[i] *= cq[4]; }
#pragma unroll
  for (int i = 0; i < 16; ++i) { sr[i+16] = sr[i]*sq[3]; sr[i] *= cq[3]; }
#pragma unroll
  for (int i = 0; i < 32; ++i) { sr[i+32] = sr[i]*sq[1]; sr[i] *= cq[1]; }

  // cycle 1 CNOT ring: (0,1)(1,2)(2,3)(3,4)(4,5)(5,6)(6,7)(7,0)
  cnot_lr<32>(sr, g0);      // (0,1): lane0 ctrl -> reg32
  cnot_rl<32, 2>(sr);       // (1,2): reg32 ctrl -> lane1
  cnot_lr<16>(sr, g1);      // (2,3)
  cnot_rr<16, 8>(sr);       // (3,4)
  cnot_rr<8, 4>(sr);        // (4,5)
  cnot_rr<4, 2>(sr);        // (5,6)
  cnot_rr<2, 1>(sr);        // (6,7)
  cnot_rl<1, 1>(sr);        // (7,0): reg1 ctrl -> lane0

  // --- cycles 2..4 (RY(2) legally commuted past CNOT(0,1) to fuse with CNOT(1,2)) ---
#pragma unroll
  for (int cy = 0; cy < 3; ++cy) {
    ry_lane<1>(sr, cq[0], sg0);            // RY q0 (lane0 exchange)
    ry_reg<32>(sr, cq[1], sq[1]);          // RY q1
    ry_reg<16>(sr, cq[3], sq[3]);          // RY q3
    ry_reg<8>(sr, cq[4], sq[4]);           // RY q4
    ry_reg<4>(sr, cq[5], sq[5]);           // RY q5
    ry_reg<2>(sr, cq[6], sq[6]);           // RY q6
    ry_reg<1>(sr, cq[7], sq[7]);           // RY q7
    cnot_lr<32>(sr, g0);                   // CNOT(0,1)
    ry_lane_cnot<2, 32>(sr, cq[2], sg2);   // RY q2 fused with CNOT(1,2)
    cnot_lr<16>(sr, g1);                   // CNOT(2,3)
    cnot_rr<16, 8>(sr);                    // CNOT(3,4)
    cnot_rr<8, 4>(sr);                     // CNOT(4,5)
    cnot_rr<4, 2>(sr);                     // CNOT(5,6)
    cnot_rr<2, 1>(sr);                     // CNOT(6,7)
    cnot_rl<1, 1>(sr);                     // CNOT(7,0)
  }

  // --- layers (complex from here) ---
  float si[64];
#pragma unroll
  for (int r = 0; r < 64; ++r) si[r] = 0.0f;

  float m00r, m01r, m01i, m10r, m10i, m11r, m11i;

  { // layer 0 : CRX pairs (0,1)(2,3)(4,5)(6,7) then (1,2)(3,4)(5,6); U3 on 1,3,5,7
    float cc, sh; sincosf(0.5f * crx_theta[0], &sh, &cc);
    crx_lr<32>(sr, si, g0, cc, sh);    // (0,1)
    crx_lr<16>(sr, si, g1, cc, sh);    // (2,3)
    crx_rr<8, 4>(sr, si, cc, sh);      // (4,5)
    crx_rr<2, 1>(sr, si, cc, sh);      // (6,7)
    crx_rl<32, 2>(sr, si, cc, sh);     // (1,2): reg32 ctrl -> lane1 target
    crx_rr<16, 8>(sr, si, cc, sh);     // (3,4)
    crx_rr<4, 2>(sr, si, cc, sh);      // (5,6)

    float uth = u3_params[0], uph = u3_params[1], ulm = u3_params[2];
    float ct, st;  sincosf(0.5f * uth, &st, &ct);
    float clm, slm; sincosf(ulm, &slm, &clm);
    float cph, sph; sincosf(uph, &sph, &cph);
    float cpl, spl; sincosf(uph + ulm, &spl, &cpl);
    m00r = ct;
    m01r = -clm * st; m01i = -slm * st;
    m10r =  cph * st; m10i =  sph * st;
    m11r =  cpl * ct; m11i =  spl * ct;
    u3_reg<32>(sr, si, m00r, m01r, m01i, m10r, m10i, m11r, m11i);  // q1
    u3_reg<16>(sr, si, m00r, m01r, m01i, m10r, m10i, m11r, m11i);  // q3
    u3_reg<4>(sr, si, m00r, m01r, m01i, m10r, m10i, m11r, m11i);   // q5
    u3_reg<1>(sr, si, m00r, m01r, m01i, m10r, m10i, m11r, m11i);   // q7
  }

  { // layer 1 : active [1,3,5,7]; CRX (1,3)(5,7) then (3,5); U3 on 3,7 — all register-local
    float cc, sh; sincosf(0.5f * crx_theta[1], &sh, &cc);
    crx_rr<32, 16>(sr, si, cc, sh);    // (1,3)
    crx_rr<4, 1>(sr, si, cc, sh);      // (5,7)
    crx_rr<16, 4>(sr, si, cc, sh);     // (3,5)

    float uth = u3_params[3], uph = u3_params[4], ulm = u3_params[5];
    float ct, st;  sincosf(0.5f * uth, &st, &ct);
    float clm, slm; sincosf(ulm, &slm, &clm);
    float cph, sph; sincosf(uph, &sph, &cph);
    float cpl, spl; sincosf(uph + ulm, &spl, &cpl);
    m00r = ct;
    m01r = -clm * st; m01i = -slm * st;
    m10r =  cph * st; m10i =  sph * st;
    m11r =  cpl * ct; m11i =  spl * ct;
    u3_reg<16>(sr, si, m00r, m01r, m01i, m10r, m10i, m11r, m11i);  // q3
    u3_reg<1>(sr, si, m00r, m01r, m01i, m10r, m10i, m11r, m11i);   // q7
  }

  // --- expval_z on q3 (reg bit 16) and q7 (reg bit 1) ---
  float z3 = 0.f, z7 = 0.f;
#pragma unroll
  for (int r = 0; r < 64; ++r) {
    float p = sr[r] * sr[r] + si[r] * si[r];
    z3 += (r & 16) ? -p : p;
    z7 += (r & 1)  ? -p : p;
  }
  z3 += __shfl_xor_sync(FULLMASK, z3, 1);
  z3 += __shfl_xor_sync(FULLMASK, z3, 2);
  z7 += __shfl_xor_sync(FULLMASK, z7, 1);
  z7 += __shfl_xor_sync(FULLMASK, z7, 2);

  // --- tiny MLP head: sigmoid(tanh([z3 z7] @ w1 + b1) @ w2 + b2) ---
  if (g == 0) {
    float o = b2[0];
#pragma unroll
    for (int j = 0; j < 10; ++j) {
      float h = tanhf(z3 * w1[j] + z7 * w1[10 + j] + b1[j]);
      o += h * w2[j];
    }
    out[elem] = 1.0f / (1.0f + expf(-o));
  }
}

extern "C" void kernel_launch(void* const* d_in, const int* in_sizes, int n_in,
                              void* d_out, int out_size) {
  const float* x   = (const float*)d_in[0];
  const float* crx = (const float*)d_in[1];
  const float* u3p = (const float*)d_in[2];
  const float* w1  = (const float*)d_in[3];
  const float* b1  = (const float*)d_in[4];
  const float* w2  = (const float*)d_in[5];
  const float* b2  = (const float*)d_in[6];
  float* out = (float*)d_out;

  int B = in_sizes[0] / 8;           // batch elements
  int threads = B * 4;               // 4 lanes per element
  int block = 128;
  int grid = (threads + block - 1) / block;
  qcnn_kernel<<<grid, block>>>(x, crx, u3p, w1, b1, w2, b2, out, B);
}

// round 2
// speedup vs baseline: 1.9912x; 1.9912x over previous
#include <cuda_runtime.h>
#include <math.h>

#define FULLMASK 0xffffffffu

// ---------------------------------------------------------------------------
// Layout: 8 lanes per batch element (g = tid & 7), 32 amplitudes per thread.
// Qubit -> bit mapping:
//   q0 -> lane bit 0 (xor 1)   q2 -> lane bit 1 (xor 2)   q4 -> lane bit 2 (xor 4)
//   q1 -> reg bit 4 (16)  q3 -> reg bit 3 (8)  q5 -> reg bit 2 (4)
//   q6 -> reg bit 1 (2)   q7 -> reg bit 0 (1)
// State is REAL during the 4 RY/CNOT cycles; complex only in the CRX/U3 layers.
// ---------------------------------------------------------------------------

template<int TM>
__device__ __forceinline__ void ry_reg(float (&a)[32], float c, float s) {
#pragma unroll
  for (int r = 0; r < 32; ++r) if (!(r & TM)) {
    float v0 = a[r], v1 = a[r + TM];
    a[r]      = c * v0 - s * v1;
    a[r + TM] = s * v0 + c * v1;
  }
}

template<int LM>
__device__ __forceinline__ void ry_lane(float (&a)[32], float c, float sg) {
#pragma unroll
  for (int r = 0; r < 32; ++r) {
    float p = __shfl_xor_sync(FULLMASK, a[r], LM);
    a[r] = c * a[r] + sg * p;
  }
}

// Fused: RY on lane-qubit LM immediately followed by CNOT(control=reg bit CM,
// target=lane-qubit LM). One exchange serves both gates.
template<int LM, int CM>
__device__ __forceinline__ void ry_lane_cnot(float (&a)[32], float c, float sg) {
#pragma unroll
  for (int r = 0; r < 32; ++r) {
    float p = __shfl_xor_sync(FULLMASK, a[r], LM);
    float mynew = c * a[r] + sg * p;   // my post-RY value
    float pnew  = c * p - sg * a[r];   // partner's post-RY value
    a[r] = (r & CM) ? pnew : mynew;    // CNOT: control=1 amps take the swap
  }
}

template<int CM, int TM>
__device__ __forceinline__ void cnot_rr(float (&a)[32]) {
#pragma unroll
  for (int r = 0; r < 32; ++r) if ((r & CM) && !(r & TM)) {
    float t = a[r]; a[r] = a[r + TM]; a[r + TM] = t;  // register rename
  }
}

template<int TM>
__device__ __forceinline__ void cnot_lr(float (&a)[32], bool f) {
#pragma unroll
  for (int r = 0; r < 32; ++r) if (!(r & TM)) {
    float v0 = a[r], v1 = a[r + TM];
    a[r]      = f ? v1 : v0;
    a[r + TM] = f ? v0 : v1;
  }
}

template<int CM, int LM>
__device__ __forceinline__ void cnot_rl(float (&a)[32]) {
#pragma unroll
  for (int r = 0; r < 32; ++r) if (r & CM)
    a[r] = __shfl_xor_sync(FULLMASK, a[r], LM);
}

// ---- complex-phase gates --------------------------------------------------
// CRX(theta) on control=1 amps: v0' = c v0 + s v1, v1' = s v0 + c v1
// with s = -i*sin(theta/2): (s*v).re = sh*v.im, (s*v).im = -sh*v.re

template<int CM, int TM>
__device__ __forceinline__ void crx_rr(float (&ar)[32], float (&ai)[32], float c, float sh) {
#pragma unroll
  for (int r = 0; r < 32; ++r) if ((r & CM) && !(r & TM)) {
    int r1 = r + TM;
    float v0r = ar[r], v0i = ai[r], v1r = ar[r1], v1i = ai[r1];
    ar[r]  = c * v0r + sh * v1i;
    ai[r]  = c * v0i - sh * v1r;
    ar[r1] = c * v1r + sh * v0i;
    ai[r1] = c * v1i - sh * v0r;
  }
}

template<int TM>
__device__ __forceinline__ void crx_lr(float (&ar)[32], float (&ai)[32], bool f, float c, float sh) {
  if (f) {
#pragma unroll
    for (int r = 0; r < 32; ++r) if (!(r & TM)) {
      int r1 = r + TM;
      float v0r = ar[r], v0i = ai[r], v1r = ar[r1], v1i = ai[r1];
      ar[r]  = c * v0r + sh * v1i;
      ai[r]  = c * v0i - sh * v1r;
      ar[r1] = c * v1r + sh * v0i;
      ai[r1] = c * v1i - sh * v0r;
    }
  }
}

template<int CM, int LM>
__device__ __forceinline__ void crx_rl(float (&ar)[32], float (&ai)[32], float c, float sh) {
#pragma unroll
  for (int r = 0; r < 32; ++r) if (r & CM) {
    float pr = __shfl_xor_sync(FULLMASK, ar[r], LM);
    float pi = __shfl_xor_sync(FULLMASK, ai[r], LM);
    ar[r] = c * ar[r] + sh * pi;
    ai[r] = c * ai[r] - sh * pr;
  }
}

template<int TM>
__device__ __forceinline__ void u3_reg(float (&ar)[32], float (&ai)[32],
    float m00r, float m01r, float m01i,
    float m10r, float m10i, float m11r, float m11i) {
#pragma unroll
  for (int r = 0; r < 32; ++r) if (!(r & TM)) {
    int r1 = r + TM;
    float v0r = ar[r], v0i = ai[r], v1r = ar[r1], v1i = ai[r1];
    ar[r]  = m00r * v0r + m01r * v1r - m01i * v1i;
    ai[r]  = m00r * v0i + m01r * v1i + m01i * v1r;
    ar[r1] = m10r * v0r - m10i * v0i + m11r * v1r - m11i * v1i;
    ai[r1] = m10r * v0i + m10i * v0r + m11r * v1i + m11i * v1r;
  }
}

__global__ void __launch_bounds__(128, 4)
qcnn_kernel(const float* __restrict__ x,
            const float* __restrict__ crx_theta,
            const float* __restrict__ u3_params,
            const float* __restrict__ w1,
            const float* __restrict__ b1,
            const float* __restrict__ w2,
            const float* __restrict__ b2,
            float* __restrict__ out, int B)
{
  int tid  = blockIdx.x * blockDim.x + threadIdx.x;
  int elem = tid >> 3;
  if (elem >= B) return;
  int g = tid & 7;
  bool g0 = (g & 1) != 0;
  bool g1 = (g & 2) != 0;
  bool g2 = (g & 4) != 0;

  // --- angles: lane q computes sincos for qubit q, then broadcast in-group ---
  float myx = x[elem * 8 + g];                 // perfectly coalesced
  float ms, mc;
  sincosf(0.5f * myx, &ms, &mc);
  float cq[8], sq[8];
#pragma unroll
  for (int q = 0; q < 8; ++q) {
    cq[q] = __shfl_sync(FULLMASK, mc, q, 8);
    sq[q] = __shfl_sync(FULLMASK, ms, q, 8);
  }

  float sg0 = g0 ? sq[0] : -sq[0];
  float sg2 = g1 ? sq[2] : -sq[2];
  float sg4 = g2 ? sq[4] : -sq[4];

  // --- cycle 1: RYs on |0..0> == product state, built by doubling ---
  float sr[32];
  sr[0] = (g0 ? sq[0] : cq[0]) * (g1 ? sq[2] : cq[2]) * (g2 ? sq[4] : cq[4]);
#pragma unroll
  for (int i = 0; i < 1;  ++i) { sr[i+1]  = sr[i]*sq[7]; sr[i] *= cq[7]; }
#pragma unroll
  for (int i = 0; i < 2;  ++i) { sr[i+2]  = sr[i]*sq[6]; sr[i] *= cq[6]; }
#pragma unroll
  for (int i = 0; i < 4;  ++i) { sr[i+4]  = sr[i]*sq[5]; sr[i] *= cq[5]; }
#pragma unroll
  for (int i = 0; i < 8;  ++i) { sr[i+8]  = sr[i]*sq[3]; sr[i] *= cq[3]; }
#pragma unroll
  for (int i = 0; i < 16; ++i) { sr[i+16] = sr[i]*sq[1]; sr[i] *= cq[1]; }

  // cycle 1 CNOT ring: (0,1)(1,2)(2,3)(3,4)(4,5)(5,6)(6,7)(7,0)
  cnot_lr<16>(sr, g0);      // (0,1): lane0 ctrl -> reg16
  cnot_rl<16, 2>(sr);       // (1,2): reg16 ctrl -> lane1
  cnot_lr<8>(sr, g1);       // (2,3): lane1 ctrl -> reg8
  cnot_rl<8, 4>(sr);        // (3,4): reg8 ctrl -> lane2
  cnot_lr<4>(sr, g2);       // (4,5): lane2 ctrl -> reg4
  cnot_rr<4, 2>(sr);        // (5,6)
  cnot_rr<2, 1>(sr);        // (6,7)
  cnot_rl<1, 1>(sr);        // (7,0): reg1 ctrl -> lane0

  // --- cycles 2..4 (RY(q2), RY(q4) commuted down to fuse with their CNOTs) ---
#pragma unroll
  for (int cy = 0; cy < 3; ++cy) {
    ry_lane<1>(sr, cq[0], sg0);            // RY q0
    ry_reg<16>(sr, cq[1], sq[1]);          // RY q1
    ry_reg<8>(sr, cq[3], sq[3]);           // RY q3
    ry_reg<4>(sr, cq[5], sq[5]);           // RY q5
    ry_reg<2>(sr, cq[6], sq[6]);           // RY q6
    ry_reg<1>(sr, cq[7], sq[7]);           // RY q7
    cnot_lr<16>(sr, g0);                   // CNOT(0,1)
    ry_lane_cnot<2, 16>(sr, cq[2], sg2);   // RY q2 fused with CNOT(1,2)
    cnot_lr<8>(sr, g1);                    // CNOT(2,3)
    ry_lane_cnot<4, 8>(sr, cq[4], sg4);    // RY q4 fused with CNOT(3,4)
    cnot_lr<4>(sr, g2);                    // CNOT(4,5)
    cnot_rr<4, 2>(sr);                     // CNOT(5,6)
    cnot_rr<2, 1>(sr);                     // CNOT(6,7)
    cnot_rl<1, 1>(sr);                     // CNOT(7,0)
  }

  // --- layers (complex from here) ---
  float si[32];
#pragma unroll
  for (int r = 0; r < 32; ++r) si[r] = 0.0f;

  float m00r, m01r, m01i, m10r, m10i, m11r, m11i;

  { // layer 0 : CRX (0,1)(2,3)(4,5)(6,7) then (1,2)(3,4)(5,6); U3 on 1,3,5,7
    float cc, sh; sincosf(0.5f * crx_theta[0], &sh, &cc);
    crx_lr<16>(sr, si, g0, cc, sh);    // (0,1): lane0 ctrl -> reg16
    crx_lr<8>(sr, si, g1, cc, sh);     // (2,3): lane1 ctrl -> reg8
    crx_lr<4>(sr, si, g2, cc, sh);     // (4,5): lane2 ctrl -> reg4
    crx_rr<2, 1>(sr, si, cc, sh);      // (6,7)
    crx_rl<16, 2>(sr, si, cc, sh);     // (1,2): reg16 ctrl -> lane1 target
    crx_rl<8, 4>(sr, si, cc, sh);      // (3,4): reg8 ctrl -> lane2 target
    crx_rr<4, 2>(sr, si, cc, sh);      // (5,6)

    float uth = u3_params[0], uph = u3_params[1], ulm = u3_params[2];
    float ct, st;  sincosf(0.5f * uth, &st, &ct);
    float clm, slm; sincosf(ulm, &slm, &clm);
    float cph, sph; sincosf(uph, &sph, &cph);
    float cpl, spl; sincosf(uph + ulm, &spl, &cpl);
    m00r = ct;
    m01r = -clm * st; m01i = -slm * st;
    m10r =  cph * st; m10i =  sph * st;
    m11r =  cpl * ct; m11i =  spl * ct;
    u3_reg<16>(sr, si, m00r, m01r, m01i, m10r, m10i, m11r, m11i);  // q1
    u3_reg<8>(sr, si, m00r, m01r, m01i, m10r, m10i, m11r, m11i);   // q3
    u3_reg<4>(sr, si, m00r, m01r, m01i, m10r, m10i, m11r, m11i);   // q5
    u3_reg<1>(sr, si, m00r, m01r, m01i, m10r, m10i, m11r, m11i);   // q7
  }

  { // layer 1 : active [1,3,5,7]; CRX (1,3)(5,7) then (3,5); U3 on 3,7 — register-local
    float cc, sh; sincosf(0.5f * crx_theta[1], &sh, &cc);
    crx_rr<16, 8>(sr, si, cc, sh);     // (1,3)
    crx_rr<4, 1>(sr, si, cc, sh);      // (5,7)
    crx_rr<8, 4>(sr, si, cc, sh);      // (3,5)

    float uth = u3_params[3], uph = u3_params[4], ulm = u3_params[5];
    float ct, st;  sincosf(0.5f * uth, &st, &ct);
    float clm, slm; sincosf(ulm, &slm, &clm);
    float cph, sph; sincosf(uph, &sph, &cph);
    float cpl, spl; sincosf(uph + ulm, &spl, &cpl);
    m00r = ct;
    m01r = -clm * st; m01i = -slm * st;
    m10r =  cph * st; m10i =  sph * st;
    m11r =  cpl * ct; m11i =  spl * ct;
    u3_reg<8>(sr, si, m00r, m01r, m01i, m10r, m10i, m11r, m11i);   // q3
    u3_reg<1>(sr, si, m00r, m01r, m01i, m10r, m10i, m11r, m11i);   // q7
  }

  // --- expval_z on q3 (reg bit 8) and q7 (reg bit 1) ---
  float z3 = 0.f, z7 = 0.f;
#pragma unroll
  for (int r = 0; r < 32; ++r) {
    float p = sr[r] * sr[r] + si[r] * si[r];
    z3 += (r & 8) ? -p : p;
    z7 += (r & 1) ? -p : p;
  }
  z3 += __shfl_xor_sync(FULLMASK, z3, 1);
  z3 += __shfl_xor_sync(FULLMASK, z3, 2);
  z3 += __shfl_xor_sync(FULLMASK, z3, 4);
  z7 += __shfl_xor_sync(FULLMASK, z7, 1);
  z7 += __shfl_xor_sync(FULLMASK, z7, 2);
  z7 += __shfl_xor_sync(FULLMASK, z7, 4);

  // --- tiny MLP head: sigmoid(tanh([z3 z7] @ w1 + b1) @ w2 + b2) ---
  if (g == 0) {
    float o = b2[0];
#pragma unroll
    for (int j = 0; j < 10; ++j) {
      float h = tanhf(z3 * w1[j] + z7 * w1[10 + j] + b1[j]);
      o += h * w2[j];
    }
    out[elem] = 1.0f / (1.0f + expf(-o));
  }
}

extern "C" void kernel_launch(void* const* d_in, const int* in_sizes, int n_in,
                              void* d_out, int out_size) {
  const float* x   = (const float*)d_in[0];
  const float* crx = (const float*)d_in[1];
  const float* u3p = (const float*)d_in[2];
  const float* w1  = (const float*)d_in[3];
  const float* b1  = (const float*)d_in[4];
  const float* w2  = (const float*)d_in[5];
  const float* b2  = (const float*)d_in[6];
  float* out = (float*)d_out;

  int B = in_sizes[0] / 8;           // batch elements
  int threads = B * 8;               // 8 lanes per element
  int block = 128;
  int grid = (threads + block - 1) / block;
  qcnn_kernel<<<grid, block>>>(x, crx, u3p, w1, b1, w2, b2, out, B);
}

// round 3
// speedup vs baseline: 2.0923x; 1.0508x over previous
#include <cuda_runtime.h>
#include <math.h>

#define FULLMASK 0xffffffffu
typedef unsigned long long u64;

// ---- packed f32x2 primitives (sm_103a FFMA2 path; ptxas won't emit from C++) ----
__device__ __forceinline__ u64 pk(float lo, float hi) {
  u64 r; asm("mov.b64 %0, {%1,%2};" : "=l"(r) : "f"(lo), "f"(hi)); return r;
}
__device__ __forceinline__ void unpk(u64 v, float& lo, float& hi) {
  asm("mov.b64 {%0,%1}, %2;" : "=f"(lo), "=f"(hi) : "l"(v));
}
__device__ __forceinline__ u64 swp(u64 v) {
  float l, h; unpk(v, l, h); return pk(h, l);
}
__device__ __forceinline__ u64 f2fma(u64 a, u64 b, u64 c) {
  u64 d; asm("fma.rn.f32x2 %0, %1, %2, %3;" : "=l"(d) : "l"(a), "l"(b), "l"(c)); return d;
}
__device__ __forceinline__ u64 f2mul(u64 a, u64 b) {
  u64 d; asm("mul.rn.f32x2 %0, %1, %2;" : "=l"(d) : "l"(a), "l"(b)); return d;
}

// ---------------------------------------------------------------------------
// Layout: 8 lanes per element (g = tid&7), 32 amps/thread.
// Amp index r (5 bits): bit4=q1(16) bit3=q3(8) bit2=q5(4) bit1=q6(2) bit0=q7(1)
// Lane bits: q0 -> lane xor 1, q2 -> lane xor 2, q4 -> lane xor 4.
// CYCLE PHASE (state real): packed P[16] along q7: P[k]=(a[2k], a[2k+1]),
//   k bits: bit3=q1, bit2=q3, bit1=q5, bit0=q6.
// LAYER PHASE: packed C[32] as (re, im).
// ---------------------------------------------------------------------------

// RY on reg qubit with k-mask TMk (q7 spectator -> fully packed)
template<int TMk>
__device__ __forceinline__ void ry_reg_p(u64 (&P)[16], u64 cc, u64 ss, u64 ssn) {
#pragma unroll
  for (int k = 0; k < 16; ++k) if (!(k & TMk)) {
    u64 A = P[k], B = P[k + TMk];
    P[k]       = f2fma(cc, A, f2mul(ssn, B));
    P[k + TMk] = f2fma(cc, B, f2mul(ss, A));
  }
}

// RY on q7 (the packed axis): within-pair rotation
__device__ __forceinline__ void ry_q7_p(u64 (&P)[16], u64 cc, u64 s_ns_p) {
  // s_ns_p = (-s, +s): lo' = c*lo - s*hi ; hi' = s*lo + c*hi
#pragma unroll
  for (int k = 0; k < 16; ++k) {
    u64 v = P[k];
    P[k] = f2fma(cc, v, f2mul(s_ns_p, swp(v)));
  }
}

// RY on lane qubit LM
template<int LM>
__device__ __forceinline__ void ry_lane_p(u64 (&P)[16], u64 cc, u64 sgg) {
#pragma unroll
  for (int k = 0; k < 16; ++k) {
    u64 p = __shfl_xor_sync(FULLMASK, P[k], LM);
    P[k] = f2fma(cc, P[k], f2mul(sgg, p));
  }
}

// Fused RY(lane LM) + CNOT(control = k-bit KM, target = lane LM)
template<int LM, int KM>
__device__ __forceinline__ void ry_lane_cnot_p(u64 (&P)[16], u64 cc, u64 sgg, u64 sggn) {
#pragma unroll
  for (int k = 0; k < 16; ++k) {
    u64 p = __shfl_xor_sync(FULLMASK, P[k], LM);
    if (k & KM) P[k] = f2fma(cc, p, f2mul(sggn, P[k]));  // partner's post-RY value
    else        P[k] = f2fma(cc, P[k], f2mul(sgg, p));   // my post-RY value
  }
}

// CNOT(lane ctrl flag f, reg target k-mask TMk): conditional pair swap
template<int TMk>
__device__ __forceinline__ void condswap(u64 (&P)[16], bool f) {
#pragma unroll
  for (int k = 0; k < 16; ++k) if (!(k & TMk)) {
    u64 A = P[k], B = P[k + TMk];
    P[k]       = f ? B : A;
    P[k + TMk] = f ? A : B;
  }
}

__global__ void __launch_bounds__(128, 4)
qcnn_kernel(const float* __restrict__ x,
            const float* __restrict__ crx_theta,
            const float* __restrict__ u3_params,
            const float* __restrict__ w1,
            const float* __restrict__ b1,
            const float* __restrict__ w2,
            const float* __restrict__ b2,
            float* __restrict__ out, int B)
{
  int tid  = blockIdx.x * blockDim.x + threadIdx.x;
  int elem = tid >> 3;
  if (elem >= B) return;
  int g = tid & 7;
  bool g0 = (g & 1) != 0;
  bool g1 = (g & 2) != 0;
  bool g2 = (g & 4) != 0;

  // --- angles: lane q computes sincos for qubit q, broadcast within group ---
  float myx = x[elem * 8 + g];
  float ms, mc;
  sincosf(0.5f * myx, &ms, &mc);
  float cq[8], sq[8];
#pragma unroll
  for (int q = 0; q < 8; ++q) {
    cq[q] = __shfl_sync(FULLMASK, mc, q, 8);
    sq[q] = __shfl_sync(FULLMASK, ms, q, 8);
  }

  float sg0 = g0 ? sq[0] : -sq[0];
  float sg2 = g1 ? sq[2] : -sq[2];
  float sg4 = g2 ? sq[4] : -sq[4];

  // --- cycle 1: product state via doubling over k bits (q6,q5,q3,q1) ---
  float b[16];
  b[0] = (g0 ? sq[0] : cq[0]) * (g1 ? sq[2] : cq[2]) * (g2 ? sq[4] : cq[4]);
#pragma unroll
  for (int i = 0; i < 1; ++i) { b[i+1] = b[i]*sq[6]; b[i] *= cq[6]; }
#pragma unroll
  for (int i = 0; i < 2; ++i) { b[i+2] = b[i]*sq[5]; b[i] *= cq[5]; }
#pragma unroll
  for (int i = 0; i < 4; ++i) { b[i+4] = b[i]*sq[3]; b[i] *= cq[3]; }
#pragma unroll
  for (int i = 0; i < 8; ++i) { b[i+8] = b[i]*sq[1]; b[i] *= cq[1]; }

  u64 P[16];
  {
    u64 c7s7 = pk(cq[7], sq[7]);
#pragma unroll
    for (int k = 0; k < 16; ++k) P[k] = f2mul(pk(b[k], b[k]), c7s7);
  }

  // cycle 1 CNOT ring: (0,1)(1,2)(2,3)(3,4)(4,5)(5,6)(6,7)(7,0)
  condswap<8>(P, g0);                       // (0,1): lane0 ctrl -> q1
#pragma unroll
  for (int k = 0; k < 16; ++k) if (k & 8)   // (1,2): q1 ctrl -> lane1 target
    P[k] = __shfl_xor_sync(FULLMASK, P[k], 2);
  condswap<4>(P, g1);                       // (2,3)
#pragma unroll
  for (int k = 0; k < 16; ++k) if (k & 4)   // (3,4): q3 ctrl -> lane2 target
    P[k] = __shfl_xor_sync(FULLMASK, P[k], 4);
  condswap<2>(P, g2);                       // (4,5)
#pragma unroll
  for (int k = 0; k < 16; ++k)              // (5,6): q5 ctrl -> q6 (rename)
    if ((k & 2) && !(k & 1)) { u64 t = P[k]; P[k] = P[k+1]; P[k+1] = t; }
#pragma unroll
  for (int k = 0; k < 16; ++k) if (k & 1)   // (6,7): q6 ctrl -> q7 (in-pack swap)
    P[k] = swp(P[k]);
#pragma unroll
  for (int k = 0; k < 16; ++k) {            // (7,0): q7 ctrl -> lane0 target
    float l, h; unpk(P[k], l, h);
    h = __shfl_xor_sync(FULLMASK, h, 1);
    P[k] = pk(l, h);
  }

  // --- cycles 2..4 (RY q2, q4 commuted down to fuse with their CNOTs) ---
  {
    u64 cc0 = pk(cq[0], cq[0]), sgg0 = pk(sg0, sg0);
    u64 cc1 = pk(cq[1], cq[1]), ss1 = pk(sq[1], sq[1]), sn1 = pk(-sq[1], -sq[1]);
    u64 cc3 = pk(cq[3], cq[3]), ss3 = pk(sq[3], sq[3]), sn3 = pk(-sq[3], -sq[3]);
    u64 cc5 = pk(cq[5], cq[5]), ss5 = pk(sq[5], sq[5]), sn5 = pk(-sq[5], -sq[5]);
    u64 cc6 = pk(cq[6], cq[6]), ss6 = pk(sq[6], sq[6]), sn6 = pk(-sq[6], -sq[6]);
    u64 cc7 = pk(cq[7], cq[7]), s7pm = pk(-sq[7], sq[7]);
    u64 cc2 = pk(cq[2], cq[2]), sgg2 = pk(sg2, sg2), sgg2n = pk(-sg2, -sg2);
    u64 cc4 = pk(cq[4], cq[4]), sgg4 = pk(sg4, sg4), sgg4n = pk(-sg4, -sg4);

#pragma unroll
    for (int cy = 0; cy < 3; ++cy) {
      ry_lane_p<1>(P, cc0, sgg0);                 // RY q0
      ry_reg_p<8>(P, cc1, ss1, sn1);              // RY q1
      ry_reg_p<4>(P, cc3, ss3, sn3);              // RY q3
      ry_reg_p<2>(P, cc5, ss5, sn5);              // RY q5
      ry_reg_p<1>(P, cc6, ss6, sn6);              // RY q6
      ry_q7_p(P, cc7, s7pm);                      // RY q7
      condswap<8>(P, g0);                         // CNOT(0,1)
      ry_lane_cnot_p<2, 8>(P, cc2, sgg2, sgg2n);  // RY q2 + CNOT(1,2)
      condswap<4>(P, g1);                         // CNOT(2,3)
      ry_lane_cnot_p<4, 4>(P, cc4, sgg4, sgg4n);  // RY q4 + CNOT(3,4)
      condswap<2>(P, g2);                         // CNOT(4,5)
#pragma unroll
      for (int k = 0; k < 16; ++k)                // CNOT(5,6) rename
        if ((k & 2) && !(k & 1)) { u64 t = P[k]; P[k] = P[k+1]; P[k+1] = t; }
#pragma unroll
      for (int k = 0; k < 16; ++k) if (k & 1)     // CNOT(6,7) in-pack swap
        P[k] = swp(P[k]);
#pragma unroll
      for (int k = 0; k < 16; ++k) {              // CNOT(7,0)
        float l, h; unpk(P[k], l, h);
        h = __shfl_xor_sync(FULLMASK, h, 1);
        P[k] = pk(l, h);
      }
    }
  }

  // --- transition to complex: C[r] = (re, im) packed ---
  u64 C[32];
#pragma unroll
  for (int k = 0; k < 16; ++k) {
    float l, h; unpk(P[k], l, h);
    C[2 * k]     = pk(l, 0.0f);
    C[2 * k + 1] = pk(h, 0.0f);
  }

  // --- layer 0 : CRX (0,1)(2,3)(4,5)(6,7) then (1,2)(3,4)(5,6); U3 on 1,3,5,7
  {
    float cc, sh; sincosf(0.5f * crx_theta[0], &sh, &cc);
    u64 cc2v = pk(cc, cc), shpm = pk(sh, -sh);
    // CRX pair: C[r0] = cc*v0 + (sh,-sh)*swap(v1); C[r1] = cc*v1 + (sh,-sh)*swap(v0)

    // (0,1): lane0 ctrl -> reg q1 (bit 16)
    if (g0) {
#pragma unroll
      for (int r = 0; r < 32; ++r) if (!(r & 16)) {
        u64 v0 = C[r], v1 = C[r + 16];
        C[r]      = f2fma(cc2v, v0, f2mul(shpm, swp(v1)));
        C[r + 16] = f2fma(cc2v, v1, f2mul(shpm, swp(v0)));
      }
    }
    // (2,3): lane1 ctrl -> reg q3 (bit 8)
    if (g1) {
#pragma unroll
      for (int r = 0; r < 32; ++r) if (!(r & 8)) {
        u64 v0 = C[r], v1 = C[r + 8];
        C[r]     = f2fma(cc2v, v0, f2mul(shpm, swp(v1)));
        C[r + 8] = f2fma(cc2v, v1, f2mul(shpm, swp(v0)));
      }
    }
    // (4,5): lane2 ctrl -> reg q5 (bit 4)
    if (g2) {
#pragma unroll
      for (int r = 0; r < 32; ++r) if (!(r & 4)) {
        u64 v0 = C[r], v1 = C[r + 4];
        C[r]     = f2fma(cc2v, v0, f2mul(shpm, swp(v1)));
        C[r + 4] = f2fma(cc2v, v1, f2mul(shpm, swp(v0)));
      }
    }
    // (6,7): reg q6 ctrl (bit 2) -> reg q7 target (bit 1)
#pragma unroll
    for (int r = 0; r < 32; ++r) if ((r & 2) && !(r & 1)) {
      u64 v0 = C[r], v1 = C[r + 1];
      C[r]     = f2fma(cc2v, v0, f2mul(shpm, swp(v1)));
      C[r + 1] = f2fma(cc2v, v1, f2mul(shpm, swp(v0)));
    }
    // (1,2): reg q1 ctrl (bit 16) -> lane1 target
#pragma unroll
    for (int r = 0; r < 32; ++r) if (r & 16) {
      u64 p = __shfl_xor_sync(FULLMASK, C[r], 2);
      C[r] = f2fma(cc2v, C[r], f2mul(shpm, swp(p)));
    }
    // (3,4): reg q3 ctrl (bit 8) -> lane2 target
#pragma unroll
    for (int r = 0; r < 32; ++r) if (r & 8) {
      u64 p = __shfl_xor_sync(FULLMASK, C[r], 4);
      C[r] = f2fma(cc2v, C[r], f2mul(shpm, swp(p)));
    }
    // (5,6): reg q5 ctrl (bit 4) -> reg q6 target (bit 2)
#pragma unroll
    for (int r = 0; r < 32; ++r) if ((r & 4) && !(r & 2)) {
      u64 v0 = C[r], v1 = C[r + 2];
      C[r]     = f2fma(cc2v, v0, f2mul(shpm, swp(v1)));
      C[r + 2] = f2fma(cc2v, v1, f2mul(shpm, swp(v0)));
    }

    // U3(layer 0) on q1(16), q3(8), q5(4), q7(1)
    float uth = u3_params[0], uph = u3_params[1], ulm = u3_params[2];
    float ct, st;  sincosf(0.5f * uth, &st, &ct);
    float clm, slm; sincosf(ulm, &slm, &clm);
    float cph, sph; sincosf(uph, &sph, &cph);
    float cpl, spl; sincosf(uph + ulm, &spl, &cpl);
    u64 m00  = pk(ct, ct);
    u64 m01r = pk(-clm * st, -clm * st);
    u64 m01i = pk(slm * st, -slm * st);    // (-m01i, +m01i) with m01i=-slm*st
    u64 m10r = pk(cph * st, cph * st);
    u64 m10i = pk(-sph * st, sph * st);    // (-m10i, +m10i) with m10i=sph*st
    u64 m11r = pk(cpl * ct, cpl * ct);
    u64 m11i = pk(-spl * ct, spl * ct);    // (-m11i, +m11i) with m11i=spl*ct

#pragma unroll
    for (int tmi = 0; tmi < 4; ++tmi) {
      const int TM = (tmi == 0) ? 16 : (tmi == 1) ? 8 : (tmi == 2) ? 4 : 1;
#pragma unroll
      for (int r = 0; r < 32; ++r) if (!(r & TM)) {
        u64 v0 = C[r], v1 = C[r + TM];
        u64 v0s = swp(v0), v1s = swp(v1);
        C[r]      = f2fma(m00, v0, f2fma(m01r, v1, f2mul(m01i, v1s)));
        C[r + TM] = f2fma(m10r, v0, f2fma(m10i, v0s, f2fma(m11r, v1, f2mul(m11i, v1s))));
      }
    }
  }

  // --- layer 1 : active [1,3,5,7]; CRX (1,3)(5,7) then (3,5); U3 on 3,7 ---
  {
    float cc, sh; sincosf(0.5f * crx_theta[1], &sh, &cc);
    u64 cc2v = pk(cc, cc), shpm = pk(sh, -sh);
    // (1,3): ctrl bit 16, target bit 8
#pragma unroll
    for (int r = 0; r < 32; ++r) if ((r & 16) && !(r & 8)) {
      u64 v0 = C[r], v1 = C[r + 8];
      C[r]     = f2fma(cc2v, v0, f2mul(shpm, swp(v1)));
      C[r + 8] = f2fma(cc2v, v1, f2mul(shpm, swp(v0)));
    }
    // (5,7): ctrl bit 4, target bit 1
#pragma unroll
    for (int r = 0; r < 32; ++r) if ((r & 4) && !(r & 1)) {
      u64 v0 = C[r], v1 = C[r + 1];
      C[r]     = f2fma(cc2v, v0, f2mul(shpm, swp(v1)));
      C[r + 1] = f2fma(cc2v, v1, f2mul(shpm, swp(v0)));
    }
    // (3,5): ctrl bit 8, target bit 4
#pragma unroll
    for (int r = 0; r < 32; ++r) if ((r & 8) && !(r & 4)) {
      u64 v0 = C[r], v1 = C[r + 4];
      C[r]     = f2fma(cc2v, v0, f2mul(shpm, swp(v1)));
      C[r + 4] = f2fma(cc2v, v1, f2mul(shpm, swp(v0)));
    }

    float uth = u3_params[3], uph = u3_params[4], ulm = u3_params[5];
    float ct, st;  sincosf(0.5f * uth, &st, &ct);
    float clm, slm; sincosf(ulm, &slm, &clm);
    float cph, sph; sincosf(uph, &sph, &cph);
    float cpl, spl; sincosf(uph + ulm, &spl, &cpl);
    u64 m00  = pk(ct, ct);
    u64 m01r = pk(-clm * st, -clm * st);
    u64 m01i = pk(slm * st, -slm * st);
    u64 m10r = pk(cph * st, cph * st);
    u64 m10i = pk(-sph * st, sph * st);
    u64 m11r = pk(cpl * ct, cpl * ct);
    u64 m11i = pk(-spl * ct, spl * ct);

#pragma unroll
    for (int tmi = 0; tmi < 2; ++tmi) {
      const int TM = (tmi == 0) ? 8 : 1;
#pragma unroll
      for (int r = 0; r < 32; ++r) if (!(r & TM)) {
        u64 v0 = C[r], v1 = C[r + TM];
        u64 v0s = swp(v0), v1s = swp(v1);
        C[r]      = f2fma(m00, v0, f2fma(m01r, v1, f2mul(m01i, v1s)));
        C[r + TM] = f2fma(m10r, v0, f2fma(m10i, v0s, f2fma(m11r, v1, f2mul(m11i, v1s))));
      }
    }
  }

  // --- expval_z on q3 (bit 8) and q7 (bit 1) ---
  float z3 = 0.f, z7 = 0.f;
#pragma unroll
  for (int r = 0; r < 32; ++r) {
    u64 sq2 = f2mul(C[r], C[r]);
    float rr, ii; unpk(sq2, rr, ii);
    float p = rr + ii;
    z3 = (r & 8) ? (z3 - p) : (z3 + p);
    z7 = (r & 1) ? (z7 - p) : (z7 + p);
  }
  z3 += __shfl_xor_sync(FULLMASK, z3, 1);
  z3 += __shfl_xor_sync(FULLMASK, z3, 2);
  z3 += __shfl_xor_sync(FULLMASK, z3, 4);
  z7 += __shfl_xor_sync(FULLMASK, z7, 1);
  z7 += __shfl_xor_sync(FULLMASK, z7, 2);
  z7 += __shfl_xor_sync(FULLMASK, z7, 4);

  // --- MLP head ---
  if (g == 0) {
    float o = b2[0];
#pragma unroll
    for (int j = 0; j < 10; ++j) {
      float h = tanhf(z3 * w1[j] + z7 * w1[10 + j] + b1[j]);
      o += h * w2[j];
    }
    out[elem] = 1.0f / (1.0f + expf(-o));
  }
}

extern "C" void kernel_launch(void* const* d_in, const int* in_sizes, int n_in,
                              void* d_out, int out_size) {
  const float* x   = (const float*)d_in[0];
  const float* crx = (const float*)d_in[1];
  const float* u3p = (const float*)d_in[2];
  const float* w1  = (const float*)d_in[3];
  const float* b1  = (const float*)d_in[4];
  const float* w2  = (const float*)d_in[5];
  const float* b2  = (const float*)d_in[6];
  float* out = (float*)d_out;

  int B = in_sizes[0] / 8;
  int threads = B * 8;
  int block = 128;
  int grid = (threads + block - 1) / block;
  qcnn_kernel<<<grid, block>>>(x, crx, u3p, w1, b1, w2, b2, out, B);
}

// round 5
// speedup vs baseline: 2.2494x; 1.0751x over previous
#include <cuda_runtime.h>
#include <math.h>

#define FULLMASK 0xffffffffu
typedef unsigned long long u64;

// ---- packed f32x2 primitives (sm_103a; ptxas won't emit these from C++) ----
__device__ __forceinline__ u64 pk(float lo, float hi) {
  u64 r; asm("mov.b64 %0, {%1,%2};" : "=l"(r) : "f"(lo), "f"(hi)); return r;
}
__device__ __forceinline__ void unpk(u64 v, float& lo, float& hi) {
  asm("mov.b64 {%0,%1}, %2;" : "=f"(lo), "=f"(hi) : "l"(v));
}
__device__ __forceinline__ u64 swp(u64 v) {
  float l, h; unpk(v, l, h); return pk(h, l);
}
__device__ __forceinline__ u64 f2fma(u64 a, u64 b, u64 c) {
  u64 d; asm("fma.rn.f32x2 %0, %1, %2, %3;" : "=l"(d) : "l"(a), "l"(b), "l"(c)); return d;
}
__device__ __forceinline__ u64 f2mul(u64 a, u64 b) {
  u64 d; asm("mul.rn.f32x2 %0, %1, %2;" : "=l"(d) : "l"(a), "l"(b)); return d;
}
__device__ __forceinline__ u64 f2add(u64 a, u64 b) {
  u64 d; asm("add.rn.f32x2 %0, %1, %2;" : "=l"(d) : "l"(a), "l"(b)); return d;
}

// ---------------------------------------------------------------------------
// Layout: 8 lanes per element (g = tid&7).
// Lane bits: q0 -> lane xor 1, q2 -> lane xor 2, q4 -> lane xor 4.
// Packed axis: q7.  k index (4 bits): bit3=q1(8), bit2=q3(4), bit1=q5(2), bit0=q6(1).
// CYCLE PHASE (real): P[16] packed pairs (q7=0, q7=1).
// LAYER PHASE: Cr[16], Ci[16] same indexing — complex mults need NO in-pair swaps
// except for gates targeting q7 itself.
// ---------------------------------------------------------------------------

template<int TMk>
__device__ __forceinline__ void ry_reg_p(u64 (&P)[16], u64 cc, u64 ss, u64 ssn) {
#pragma unroll
  for (int k = 0; k < 16; ++k) if (!(k & TMk)) {
    u64 A = P[k], B = P[k + TMk];
    P[k]       = f2fma(cc, A, f2mul(ssn, B));
    P[k + TMk] = f2fma(cc, B, f2mul(ss, A));
  }
}

__device__ __forceinline__ void ry_q7_p(u64 (&P)[16], u64 cc, u64 s_ns_p) {
#pragma unroll
  for (int k = 0; k < 16; ++k) {
    u64 v = P[k];
    P[k] = f2fma(cc, v, f2mul(s_ns_p, swp(v)));
  }
}

template<int LM>
__device__ __forceinline__ void ry_lane_p(u64 (&P)[16], u64 cc, u64 sgg) {
#pragma unroll
  for (int k = 0; k < 16; ++k) {
    u64 p = __shfl_xor_sync(FULLMASK, P[k], LM);
    P[k] = f2fma(cc, P[k], f2mul(sgg, p));
  }
}

template<int LM, int KM>
__device__ __forceinline__ void ry_lane_cnot_p(u64 (&P)[16], u64 cc, u64 sgg, u64 sggn) {
#pragma unroll
  for (int k = 0; k < 16; ++k) {
    u64 p = __shfl_xor_sync(FULLMASK, P[k], LM);
    if (k & KM) P[k] = f2fma(cc, p, f2mul(sggn, P[k]));
    else        P[k] = f2fma(cc, P[k], f2mul(sgg, p));
  }
}

template<int TMk>
__device__ __forceinline__ void condswap(u64 (&P)[16], bool f) {
#pragma unroll
  for (int k = 0; k < 16; ++k) if (!(k & TMk)) {
    u64 A = P[k], B = P[k + TMk];
    P[k]       = f ? B : A;
    P[k + TMk] = f ? A : B;
  }
}

// CRX on register-pair target (ctrl may be folded into ccp/shp/shn = identity):
// pairs (k, k+TMk) restricted by compile-time predicate via caller loops.
// re0' = cc*re0 + sh*im1 ; im0' = cc*im0 - sh*re1 ; symmetric for 1.
#define CRX_PAIR(Cr0, Ci0, Cr1, Ci1, ccp, shp, shn)                 \
  {                                                                 \
    u64 _r0 = (Cr0), _i0 = (Ci0), _r1 = (Cr1), _i1 = (Ci1);         \
    (Cr0) = f2fma((ccp), _r0, f2mul((shp), _i1));                   \
    (Ci0) = f2fma((ccp), _i0, f2mul((shn), _r1));                   \
    (Cr1) = f2fma((ccp), _r1, f2mul((shp), _i0));                   \
    (Ci1) = f2fma((ccp), _i1, f2mul((shn), _r0));                   \
  }

// U3 on register-pair target (m00 real).
#define U3_PAIR(Cr0, Ci0, Cr1, Ci1)                                             \
  {                                                                             \
    u64 _r0 = (Cr0), _i0 = (Ci0), _r1 = (Cr1), _i1 = (Ci1);                     \
    (Cr0) = f2fma(pm00r, _r0, f2fma(pm01r, _r1, f2mul(pm01in, _i1)));           \
    (Ci0) = f2fma(pm00r, _i0, f2fma(pm01r, _i1, f2mul(pm01ip, _r1)));           \
    (Cr1) = f2fma(pm10r, _r0, f2fma(pm10in, _i0,                                \
              f2fma(pm11r, _r1, f2mul(pm11in, _i1))));                          \
    (Ci1) = f2fma(pm10r, _i0, f2fma(pm10ip, _r0,                                \
              f2fma(pm11r, _i1, f2mul(pm11ip, _r1))));                          \
  }

__global__ void __launch_bounds__(128, 4)
qcnn_kernel(const float* __restrict__ x,
            const float* __restrict__ crx_theta,
            const float* __restrict__ u3_params,
            const float* __restrict__ w1,
            const float* __restrict__ b1,
            const float* __restrict__ w2,
            const float* __restrict__ b2,
            float* __restrict__ out, int B)
{
  int tid  = blockIdx.x * blockDim.x + threadIdx.x;
  int elem = tid >> 3;
  if (elem >= B) return;
  int g = tid & 7;
  bool g0 = (g & 1) != 0;
  bool g1 = (g & 2) != 0;
  bool g2 = (g & 4) != 0;

  // --- angles: lane q computes sincos for qubit q, broadcast within group ---
  float myx = x[elem * 8 + g];
  float ms, mc;
  sincosf(0.5f * myx, &ms, &mc);
  float cq[8], sq[8];
#pragma unroll
  for (int q = 0; q < 8; ++q) {
    cq[q] = __shfl_sync(FULLMASK, mc, q, 8);
    sq[q] = __shfl_sync(FULLMASK, ms, q, 8);
  }

  float sg0 = g0 ? sq[0] : -sq[0];
  float sg2 = g1 ? sq[2] : -sq[2];
  float sg4 = g2 ? sq[4] : -sq[4];

  // --- cycle 1: product state via doubling over k bits (q6,q5,q3,q1) ---
  float b[16];
  b[0] = (g0 ? sq[0] : cq[0]) * (g1 ? sq[2] : cq[2]) * (g2 ? sq[4] : cq[4]);
#pragma unroll
  for (int i = 0; i < 1; ++i) { b[i+1] = b[i]*sq[6]; b[i] *= cq[6]; }
#pragma unroll
  for (int i = 0; i < 2; ++i) { b[i+2] = b[i]*sq[5]; b[i] *= cq[5]; }
#pragma unroll
  for (int i = 0; i < 4; ++i) { b[i+4] = b[i]*sq[3]; b[i] *= cq[3]; }
#pragma unroll
  for (int i = 0; i < 8; ++i) { b[i+8] = b[i]*sq[1]; b[i] *= cq[1]; }

  u64 P[16];
  {
    u64 c7s7 = pk(cq[7], sq[7]);
#pragma unroll
    for (int k = 0; k < 16; ++k) P[k] = f2mul(pk(b[k], b[k]), c7s7);
  }

  // cycle 1 CNOT ring: (0,1)(1,2)(2,3)(3,4)(4,5)(5,6)(6,7)(7,0)
  condswap<8>(P, g0);
#pragma unroll
  for (int k = 0; k < 16; ++k) if (k & 8)
    P[k] = __shfl_xor_sync(FULLMASK, P[k], 2);
  condswap<4>(P, g1);
#pragma unroll
  for (int k = 0; k < 16; ++k) if (k & 4)
    P[k] = __shfl_xor_sync(FULLMASK, P[k], 4);
  condswap<2>(P, g2);
#pragma unroll
  for (int k = 0; k < 16; ++k)
    if ((k & 2) && !(k & 1)) { u64 t = P[k]; P[k] = P[k+1]; P[k+1] = t; }
#pragma unroll
  for (int k = 0; k < 16; ++k) if (k & 1)
    P[k] = swp(P[k]);
#pragma unroll
  for (int k = 0; k < 16; ++k) {
    float l, h; unpk(P[k], l, h);
    h = __shfl_xor_sync(FULLMASK, h, 1);
    P[k] = pk(l, h);
  }

  // --- cycles 2..4 ---
  {
    u64 cc0 = pk(cq[0], cq[0]), sgg0 = pk(sg0, sg0);
    u64 cc1 = pk(cq[1], cq[1]), ss1 = pk(sq[1], sq[1]), sn1 = pk(-sq[1], -sq[1]);
    u64 cc3 = pk(cq[3], cq[3]), ss3 = pk(sq[3], sq[3]), sn3 = pk(-sq[3], -sq[3]);
    u64 cc5 = pk(cq[5], cq[5]), ss5 = pk(sq[5], sq[5]), sn5 = pk(-sq[5], -sq[5]);
    u64 cc6 = pk(cq[6], cq[6]), ss6 = pk(sq[6], sq[6]), sn6 = pk(-sq[6], -sq[6]);
    u64 cc7 = pk(cq[7], cq[7]), s7pm = pk(-sq[7], sq[7]);
    u64 cc2 = pk(cq[2], cq[2]), sgg2 = pk(sg2, sg2), sgg2n = pk(-sg2, -sg2);
    u64 cc4 = pk(cq[4], cq[4]), sgg4 = pk(sg4, sg4), sgg4n = pk(-sg4, -sg4);

#pragma unroll
    for (int cy = 0; cy < 3; ++cy) {
      ry_lane_p<1>(P, cc0, sgg0);
      ry_reg_p<8>(P, cc1, ss1, sn1);
      ry_reg_p<4>(P, cc3, ss3, sn3);
      ry_reg_p<2>(P, cc5, ss5, sn5);
      ry_reg_p<1>(P, cc6, ss6, sn6);
      ry_q7_p(P, cc7, s7pm);
      condswap<8>(P, g0);
      ry_lane_cnot_p<2, 8>(P, cc2, sgg2, sgg2n);
      condswap<4>(P, g1);
      ry_lane_cnot_p<4, 4>(P, cc4, sgg4, sgg4n);
      condswap<2>(P, g2);
#pragma unroll
      for (int k = 0; k < 16; ++k)
        if ((k & 2) && !(k & 1)) { u64 t = P[k]; P[k] = P[k+1]; P[k+1] = t; }
#pragma unroll
      for (int k = 0; k < 16; ++k) if (k & 1)
        P[k] = swp(P[k]);
#pragma unroll
      for (int k = 0; k < 16; ++k) {
        float l, h; unpk(P[k], l, h);
        h = __shfl_xor_sync(FULLMASK, h, 1);
        P[k] = pk(l, h);
      }
    }
  }

  // =================== LAYER PHASE (split re/im, packed over q7) ===========
  u64 Cr[16], Ci[16];

  // --- layer 0 ---
  {
    float cc, sh; sincosf(0.5f * crx_theta[0], &sh, &cc);
    u64 ccp  = pk(cc, cc);
    u64 shpp = pk(sh, sh), shnn = pk(-sh, -sh);

    // CRX(0,1) on REAL state: lane0 ctrl, target q1 (k bit 3). Branchless.
    {
      float ccl = g0 ? cc : 1.0f;
      float shl = g0 ? -sh : 0.0f;
      u64 cclp = pk(ccl, ccl), shlp = pk(shl, shl);
#pragma unroll
      for (int k = 0; k < 16; ++k) {
        Cr[k] = f2mul(cclp, P[k]);
        Ci[k] = f2mul(shlp, P[k ^ 8]);
      }
    }

    // CRX(2,3): lane1 ctrl, target q3 (k bit 2). Branchless lane consts.
    {
      float ccl = g1 ? cc : 1.0f;
      float shl = g1 ? sh : 0.0f;
      u64 cclp = pk(ccl, ccl), sp = pk(shl, shl), sn = pk(-shl, -shl);
#pragma unroll
      for (int k = 0; k < 16; ++k) if (!(k & 4))
        CRX_PAIR(Cr[k], Ci[k], Cr[k+4], Ci[k+4], cclp, sp, sn);
    }

    // CRX(4,5): lane2 ctrl, target q5 (k bit 1).
    {
      float ccl = g2 ? cc : 1.0f;
      float shl = g2 ? sh : 0.0f;
      u64 cclp = pk(ccl, ccl), sp = pk(shl, shl), sn = pk(-shl, -shl);
#pragma unroll
      for (int k = 0; k < 16; ++k) if (!(k & 2))
        CRX_PAIR(Cr[k], Ci[k], Cr[k+2], Ci[k+2], cclp, sp, sn);
    }

    // CRX(6,7): ctrl q6 (k bit 0), target q7 (pack axis): in-pair with swap.
#pragma unroll
    for (int k = 0; k < 16; ++k) if (k & 1) {
      u64 r = Cr[k], i = Ci[k];
      Cr[k] = f2fma(ccp, r, f2mul(shpp, swp(i)));
      Ci[k] = f2fma(ccp, i, f2mul(shnn, swp(r)));
    }

    // CRX(1,2): ctrl q1 (k bit 3), target lane1.
#pragma unroll
    for (int k = 0; k < 16; ++k) if (k & 8) {
      u64 pr = __shfl_xor_sync(FULLMASK, Cr[k], 2);
      u64 pi = __shfl_xor_sync(FULLMASK, Ci[k], 2);
      Cr[k] = f2fma(ccp, Cr[k], f2mul(shpp, pi));
      Ci[k] = f2fma(ccp, Ci[k], f2mul(shnn, pr));
    }

    // CRX(3,4): ctrl q3 (k bit 2), target lane2.
#pragma unroll
    for (int k = 0; k < 16; ++k) if (k & 4) {
      u64 pr = __shfl_xor_sync(FULLMASK, Cr[k], 4);
      u64 pi = __shfl_xor_sync(FULLMASK, Ci[k], 4);
      Cr[k] = f2fma(ccp, Cr[k], f2mul(shpp, pi));
      Ci[k] = f2fma(ccp, Ci[k], f2mul(shnn, pr));
    }

    // CRX(5,6): ctrl q5 (k bit 1), target q6 (k bit 0).
#pragma unroll
    for (int k = 0; k < 16; ++k) if ((k & 2) && !(k & 1))
      CRX_PAIR(Cr[k], Ci[k], Cr[k+1], Ci[k+1], ccp, shpp, shnn);

    // U3(layer 0) on q1(8), q3(4), q5(2), q7(pack)
    float uth = u3_params[0], uph = u3_params[1], ulm = u3_params[2];
    float ct, st;  sincosf(0.5f * uth, &st, &ct);
    float clm, slm; sincosf(ulm, &slm, &clm);
    float cph, sph; sincosf(uph, &sph, &cph);
    float cpl, spl; sincosf(uph + ulm, &spl, &cpl);
    float m00r = ct;
    float m01r = -clm * st, m01i = -slm * st;
    float m10r =  cph * st, m10i =  sph * st;
    float m11r =  cpl * ct, m11i =  spl * ct;
    u64 pm00r = pk(m00r, m00r);
    u64 pm01r = pk(m01r, m01r), pm01ip = pk(m01i, m01i), pm01in = pk(-m01i, -m01i);
    u64 pm10r = pk(m10r, m10r), pm10ip = pk(m10i, m10i), pm10in = pk(-m10i, -m10i);
    u64 pm11r = pk(m11r, m11r), pm11ip = pk(m11i, m11i), pm11in = pk(-m11i, -m11i);

#pragma unroll
    for (int k = 0; k < 16; ++k) if (!(k & 8))
      U3_PAIR(Cr[k], Ci[k], Cr[k+8], Ci[k+8]);
#pragma unroll
    for (int k = 0; k < 16; ++k) if (!(k & 4))
      U3_PAIR(Cr[k], Ci[k], Cr[k+4], Ci[k+4]);
#pragma unroll
    for (int k = 0; k < 16; ++k) if (!(k & 2))
      U3_PAIR(Cr[k], Ci[k], Cr[k+2], Ci[k+2]);

    // U3 on q7 (pack axis): 4-term packed form.
    {
      u64 aa = pk(m00r, m11r), bb = pk(m01r, m10r);
      u64 cr_ci = pk(0.0f, -m11i), cr_si = pk(-m01i, -m10i);
      u64 ci_cr = pk(0.0f,  m11i), ci_sr = pk( m01i,  m10i);
#pragma unroll
      for (int k = 0; k < 16; ++k) {
        u64 sr_ = swp(Cr[k]), si_ = swp(Ci[k]);
        u64 nr = f2fma(aa, Cr[k], f2fma(bb, sr_, f2fma(cr_ci, Ci[k], f2mul(cr_si, si_))));
        u64 ni = f2fma(aa, Ci[k], f2fma(bb, si_, f2fma(ci_cr, Cr[k], f2mul(ci_sr, sr_))));
        Cr[k] = nr; Ci[k] = ni;
      }
    }
  }

  // --- layer 1 : active [1,3,5,7]; CRX (1,3)(5,7) then (3,5); U3 on 3,7 ---
  {
    float cc, sh; sincosf(0.5f * crx_theta[1], &sh, &cc);
    u64 ccp  = pk(cc, cc);
    u64 shpp = pk(sh, sh), shnn = pk(-sh, -sh);

    // CRX(1,3): ctrl q1 (k bit 3), target q3 (k bit 2)
#pragma unroll
    for (int k = 0; k < 16; ++k) if ((k & 8) && !(k & 4))
      CRX_PAIR(Cr[k], Ci[k], Cr[k+4], Ci[k+4], ccp, shpp, shnn);

    // CRX(5,7): ctrl q5 (k bit 1), target q7 (pack axis)
#pragma unroll
    for (int k = 0; k < 16; ++k) if (k & 2) {
      u64 r = Cr[k], i = Ci[k];
      Cr[k] = f2fma(ccp, r, f2mul(shpp, swp(i)));
      Ci[k] = f2fma(ccp, i, f2mul(shnn, swp(r)));
    }

    // CRX(3,5): ctrl q3 (k bit 2), target q5 (k bit 1)
#pragma unroll
    for (int k = 0; k < 16; ++k) if ((k & 4) && !(k & 2))
      CRX_PAIR(Cr[k], Ci[k], Cr[k+2], Ci[k+2], ccp, shpp, shnn);

    float uth = u3_params[3], uph = u3_params[4], ulm = u3_params[5];
    float ct, st;  sincosf(0.5f * uth, &st, &ct);
    float clm, slm; sincosf(ulm, &slm, &clm);
    float cph, sph; sincosf(uph, &sph, &cph);
    float cpl, spl; sincosf(uph + ulm, &spl, &cpl);
    float m00r = ct;
    float m01r = -clm * st, m01i = -slm * st;
    float m10r =  cph * st, m10i =  sph * st;
    float m11r =  cpl * ct, m11i =  spl * ct;
    u64 pm00r = pk(m00r, m00r);
    u64 pm01r = pk(m01r, m01r), pm01ip = pk(m01i, m01i), pm01in = pk(-m01i, -m01i);
    u64 pm10r = pk(m10r, m10r), pm10ip = pk(m10i, m10i), pm10in = pk(-m10i, -m10i);
    u64 pm11r = pk(m11r, m11r), pm11ip = pk(m11i, m11i), pm11in = pk(-m11i, -m11i);

    // U3 q3 (k bit 2)
#pragma unroll
    for (int k = 0; k < 16; ++k) if (!(k & 4))
      U3_PAIR(Cr[k], Ci[k], Cr[k+4], Ci[k+4]);

    // U3 q7 (pack axis)
    {
      u64 aa = pk(m00r, m11r), bb = pk(m01r, m10r);
      u64 cr_ci = pk(0.0f, -m11i), cr_si = pk(-m01i, -m10i);
      u64 ci_cr = pk(0.0f,  m11i), ci_sr = pk( m01i,  m10i);
#pragma unroll
      for (int k = 0; k < 16; ++k) {
        u64 sr_ = swp(Cr[k]), si_ = swp(Ci[k]);
        u64 nr = f2fma(aa, Cr[k], f2fma(bb, sr_, f2fma(cr_ci, Ci[k], f2mul(cr_si, si_))));
        u64 ni = f2fma(aa, Ci[k], f2fma(bb, si_, f2fma(ci_cr, Cr[k], f2mul(ci_sr, sr_))));
        Cr[k] = nr; Ci[k] = ni;
      }
    }
  }

  // --- expval_z on q3 (k bit 2) and q7 (pack slot) ---
  u64 accP = pk(0.0f, 0.0f), accN = accP;
#pragma unroll
  for (int k = 0; k < 16; ++k) {
    u64 pp = f2fma(Cr[k], Cr[k], f2mul(Ci[k], Ci[k]));
    if (k & 4) accN = f2add(accN, pp);
    else       accP = f2add(accP, pp);
  }
  float pl, ph, nl, nh;
  unpk(accP, pl, ph); unpk(accN, nl, nh);
  float z3 = (pl - nl) + (ph - nh);
  float z7 = (pl + nl) - (ph + nh);

  z3 += __shfl_xor_sync(FULLMASK, z3, 1);
  z3 += __shfl_xor_sync(FULLMASK, z3, 2);
  z3 += __shfl_xor_sync(FULLMASK, z3, 4);
  z7 += __shfl_xor_sync(FULLMASK, z7, 1);
  z7 += __shfl_xor_sync(FULLMASK, z7, 2);
  z7 += __shfl_xor_sync(FULLMASK, z7, 4);

  // --- MLP head ---
  if (g == 0) {
    float o = b2[0];
#pragma unroll
    for (int j = 0; j < 10; ++j) {
      float h = tanhf(z3 * w1[j] + z7 * w1[10 + j] + b1[j]);
      o += h * w2[j];
    }
    out[elem] = 1.0f / (1.0f + expf(-o));
  }
}

extern "C" void kernel_launch(void* const* d_in, const int* in_sizes, int n_in,
                              void* d_out, int out_size) {
  const float* x   = (const float*)d_in[0];
  const float* crx = (const float*)d_in[1];
  const float* u3p = (const float*)d_in[2];
  const float* w1  = (const float*)d_in[3];
  const float* b1  = (const float*)d_in[4];
  const float* w2  = (const float*)d_in[5];
  const float* b2  = (const float*)d_in[6];
  float* out = (float*)d_out;

  int B = in_sizes[0] / 8;
  int threads = B * 8;
  int block = 128;
  int grid = (threads + block - 1) / block;
  qcnn_kernel<<<grid, block>>>(x, crx, u3p, w1, b1, w2, b2, out, B);
}

// round 6
// speedup vs baseline: 2.5758x; 1.1451x over previous
#include <cuda_runtime.h>
#include <math.h>

#define FULLMASK 0xffffffffu
typedef unsigned long long u64;

// ---- packed f32x2 primitives (sm_103a; ptxas won't emit these from C++) ----
__device__ __forceinline__ u64 pk(float lo, float hi) {
  u64 r; asm("mov.b64 %0, {%1,%2};" : "=l"(r) : "f"(lo), "f"(hi)); return r;
}
__device__ __forceinline__ void unpk(u64 v, float& lo, float& hi) {
  asm("mov.b64 {%0,%1}, %2;" : "=f"(lo), "=f"(hi) : "l"(v));
}
__device__ __forceinline__ u64 swp(u64 v) {
  float l, h; unpk(v, l, h); return pk(h, l);
}
__device__ __forceinline__ u64 f2fma(u64 a, u64 b, u64 c) {
  u64 d; asm("fma.rn.f32x2 %0, %1, %2, %3;" : "=l"(d) : "l"(a), "l"(b), "l"(c)); return d;
}
__device__ __forceinline__ u64 f2mul(u64 a, u64 b) {
  u64 d; asm("mul.rn.f32x2 %0, %1, %2;" : "=l"(d) : "l"(a), "l"(b)); return d;
}
__device__ __forceinline__ u64 f2add(u64 a, u64 b) {
  u64 d; asm("add.rn.f32x2 %0, %1, %2;" : "=l"(d) : "l"(a), "l"(b)); return d;
}

// ---------------------------------------------------------------------------
// Layout: 8 lanes per element (g = tid&7).
// Lane bits: q0 -> lane xor 1, q2 -> lane xor 2, q4 -> lane xor 4.
// Packed axis: q7.  k index: bit3=q1(8), bit2=q3(4), bit1=q5(2), bit0=q6(1).
// CYCLE PHASE (real): P[16] packed (q7=0, q7=1), rotations in TAN form with the
// uniform cos factors deferred into the cycle-1 seed ((prod c)^3).
// LAYER PHASE: Cr[16], Ci[16]; U3 in tan form, ct factors deferred into z (G^2).
// ---------------------------------------------------------------------------

// RY in tan form on reg qubit: v0' = v0 - t*v1 ; v1' = v1 + t*v0   (x c deferred)
template<int TMk>
__device__ __forceinline__ void ry_reg_t(u64 (&P)[16], u64 tt, u64 ttn) {
#pragma unroll
  for (int k = 0; k < 16; ++k) if (!(k & TMk)) {
    u64 A = P[k], B = P[k + TMk];
    P[k]       = f2fma(ttn, B, A);
    P[k + TMk] = f2fma(tt, A, B);
  }
}

// RY tan form on q7 (pack axis): v' = v + (-t,+t) .* swp(v)
__device__ __forceinline__ void ry_q7_t(u64 (&P)[16], u64 t_pm) {
#pragma unroll
  for (int k = 0; k < 16; ++k)
    P[k] = f2fma(t_pm, swp(P[k]), P[k]);
}

// Fused RY(lane LM) + CNOT(ctrl k-bit KM, target lane LM), tan form.
template<int LM, int KM>
__device__ __forceinline__ void ry_lane_cnot_t(u64 (&P)[16], u64 tgg, u64 tggn) {
#pragma unroll
  for (int k = 0; k < 16; ++k) {
    u64 p = __shfl_xor_sync(FULLMASK, P[k], LM);
    if (k & KM) P[k] = f2fma(tggn, P[k], p);   // partner post-RY: p - tg*a
    else        P[k] = f2fma(tgg, p, P[k]);    // mine:           a + tg*p
  }
}

// CNOT(lane ctrl flag f, reg target k-mask TMk): conditional pair swap (ALU SELs)
template<int TMk>
__device__ __forceinline__ void condswap(u64 (&P)[16], bool f) {
#pragma unroll
  for (int k = 0; k < 16; ++k) if (!(k & TMk)) {
    u64 A = P[k], B = P[k + TMk];
    P[k]       = f ? B : A;
    P[k + TMk] = f ? A : B;
  }
}

// CRX pair on register target (full form; c cannot be deferred: control-half only)
#define CRX_PAIR(Cr0, Ci0, Cr1, Ci1, ccp, shp, shn)                 \
  {                                                                 \
    u64 _r0 = (Cr0), _i0 = (Ci0), _r1 = (Cr1), _i1 = (Ci1);         \
    (Cr0) = f2fma((ccp), _r0, f2mul((shp), _i1));                   \
    (Ci0) = f2fma((ccp), _i0, f2mul((shn), _r1));                   \
    (Cr1) = f2fma((ccp), _r1, f2mul((shp), _i0));                   \
    (Ci1) = f2fma((ccp), _i1, f2mul((shn), _r0));                   \
  }

// U3 pair in tan form (ct deferred):
// r0' = r0 - Ar*r1 + Ai*i1 ; i0' = i0 - Ar*i1 - Ai*r1
// r1' = Cc*r0 - Cs*i0 + Er*r1 - Ei*i1 ; i1' = Cc*i0 + Cs*r0 + Er*i1 + Ei*r1
#define U3T_PAIR(Cr0, Ci0, Cr1, Ci1)                                            \
  {                                                                             \
    u64 _r0 = (Cr0), _i0 = (Ci0), _r1 = (Cr1), _i1 = (Ci1);                     \
    (Cr0) = f2fma(pArn, _r1, f2fma(pAip, _i1, _r0));                            \
    (Ci0) = f2fma(pArn, _i1, f2fma(pAin, _r1, _i0));                            \
    (Cr1) = f2fma(pCc, _r0, f2fma(pCsn, _i0, f2fma(pEr, _r1, f2mul(pEin, _i1))));\
    (Ci1) = f2fma(pCc, _i0, f2fma(pCsp, _r0, f2fma(pEr, _i1, f2mul(pEip, _r1))));\
  }

__global__ void __launch_bounds__(128, 4)
qcnn_kernel(const float* __restrict__ x,
            const float* __restrict__ crx_theta,
            const float* __restrict__ u3_params,
            const float* __restrict__ w1,
            const float* __restrict__ b1,
            const float* __restrict__ w2,
            const float* __restrict__ b2,
            float* __restrict__ out, int B)
{
  int tid  = blockIdx.x * blockDim.x + threadIdx.x;
  int elem = tid >> 3;
  if (elem >= B) return;
  int g = tid & 7;
  bool g0 = (g & 1) != 0;
  bool g1 = (g & 2) != 0;
  bool g2 = (g & 4) != 0;

  // --- angles: lane q computes sincos+tan for qubit q, broadcast in-group ---
  float myx = x[elem * 8 + g];
  float ms, mc;
  sincosf(0.5f * myx, &ms, &mc);
  float mt = __fdividef(ms, mc);
  float cq[8], sq[8], tq[8];
#pragma unroll
  for (int q = 0; q < 8; ++q) {
    cq[q] = __shfl_sync(FULLMASK, mc, q, 8);
    sq[q] = __shfl_sync(FULLMASK, ms, q, 8);
    tq[q] = __shfl_sync(FULLMASK, mt, q, 8);
  }

  float tg0 = g0 ? tq[0] : -tq[0];
  float tg2 = g1 ? tq[2] : -tq[2];
  float tg4 = g2 ? tq[4] : -tq[4];

  // deferred cos factor for cycles 2..4: (prod_q c_q)^3
  float cprod = cq[0]*cq[1]*cq[2]*cq[3]*cq[4]*cq[5]*cq[6]*cq[7];
  float F = cprod * cprod * cprod;

  // --- cycle 1: product state via doubling (exact), seeded with F ---
  float b[16];
  b[0] = F * (g0 ? sq[0] : cq[0]) * (g1 ? sq[2] : cq[2]) * (g2 ? sq[4] : cq[4]);
#pragma unroll
  for (int i = 0; i < 1; ++i) { b[i+1] = b[i]*sq[6]; b[i] *= cq[6]; }
#pragma unroll
  for (int i = 0; i < 2; ++i) { b[i+2] = b[i]*sq[5]; b[i] *= cq[5]; }
#pragma unroll
  for (int i = 0; i < 4; ++i) { b[i+4] = b[i]*sq[3]; b[i] *= cq[3]; }
#pragma unroll
  for (int i = 0; i < 8; ++i) { b[i+8] = b[i]*sq[1]; b[i] *= cq[1]; }

  u64 P[16];
  {
    u64 c7s7 = pk(cq[7], sq[7]);
#pragma unroll
    for (int k = 0; k < 16; ++k) P[k] = f2mul(pk(b[k], b[k]), c7s7);
  }

  // cycle 1 CNOT ring WITHOUT final (7,0) — it is fused into next cycle's RY q0
  condswap<8>(P, g0);                       // (0,1)
#pragma unroll
  for (int k = 0; k < 16; ++k) if (k & 8)   // (1,2)
    P[k] = __shfl_xor_sync(FULLMASK, P[k], 2);
  condswap<4>(P, g1);                       // (2,3)
#pragma unroll
  for (int k = 0; k < 16; ++k) if (k & 4)   // (3,4)
    P[k] = __shfl_xor_sync(FULLMASK, P[k], 4);
  condswap<2>(P, g2);                       // (4,5)
#pragma unroll
  for (int k = 0; k < 16; ++k)              // (5,6) rename
    if ((k & 2) && !(k & 1)) { u64 t = P[k]; P[k] = P[k+1]; P[k+1] = t; }
#pragma unroll
  for (int k = 0; k < 16; ++k) if (k & 1)   // (6,7) in-pack swap
    P[k] = swp(P[k]);

  // --- cycles 2..4 (tan form; RY q2,q4 fused with CNOTs; CNOT(7,0) fused with RY q0) ---
  {
    u64 pa0 = pk(1.0f, tg0), pb0 = pk(tg0, 1.0f);  // fused CNOT(7,0)+RY(q0)
    u64 tt1 = pk(tq[1], tq[1]), tn1 = pk(-tq[1], -tq[1]);
    u64 tt3 = pk(tq[3], tq[3]), tn3 = pk(-tq[3], -tq[3]);
    u64 tt5 = pk(tq[5], tq[5]), tn5 = pk(-tq[5], -tq[5]);
    u64 tt6 = pk(tq[6], tq[6]), tn6 = pk(-tq[6], -tq[6]);
    u64 t7pm = pk(-tq[7], tq[7]);
    u64 tgg2 = pk(tg2, tg2), tgg2n = pk(-tg2, -tg2);
    u64 tgg4 = pk(tg4, tg4), tgg4n = pk(-tg4, -tg4);

#pragma unroll
    for (int cy = 0; cy < 3; ++cy) {
      // fused CNOT(7,0) [prev cycle] + RY(q0): one lane0 exchange
#pragma unroll
      for (int k = 0; k < 16; ++k) {
        u64 p = __shfl_xor_sync(FULLMASK, P[k], 1);
        P[k] = f2fma(pa0, P[k], f2mul(pb0, p));
      }
      ry_reg_t<8>(P, tt1, tn1);                    // RY q1
      ry_reg_t<4>(P, tt3, tn3);                    // RY q3
      ry_reg_t<2>(P, tt5, tn5);                    // RY q5
      ry_reg_t<1>(P, tt6, tn6);                    // RY q6
      ry_q7_t(P, t7pm);                            // RY q7
      condswap<8>(P, g0);                          // CNOT(0,1)
      ry_lane_cnot_t<2, 8>(P, tgg2, tgg2n);        // RY q2 + CNOT(1,2)
      condswap<4>(P, g1);                          // CNOT(2,3)
      ry_lane_cnot_t<4, 4>(P, tgg4, tgg4n);        // RY q4 + CNOT(3,4)
      condswap<2>(P, g2);                          // CNOT(4,5)
#pragma unroll
      for (int k = 0; k < 16; ++k)                 // CNOT(5,6) rename
        if ((k & 2) && !(k & 1)) { u64 t = P[k]; P[k] = P[k+1]; P[k+1] = t; }
#pragma unroll
      for (int k = 0; k < 16; ++k) if (k & 1)      // CNOT(6,7) in-pack swap
        P[k] = swp(P[k]);
    }
  }

  // final standalone CNOT(7,0): exchange hi halves across lane0
#pragma unroll
  for (int k = 0; k < 16; ++k) {
    float l, h; unpk(P[k], l, h);
    h = __shfl_xor_sync(FULLMASK, h, 1);
    P[k] = pk(l, h);
  }

  // =================== LAYER PHASE (split re/im, packed over q7) ===========
  u64 Cr[16], Ci[16];
  float ct_l0, ct_l1;

  // --- layer 0 ---
  {
    float cc, sh; sincosf(0.5f * crx_theta[0], &sh, &cc);
    u64 ccp  = pk(cc, cc);
    u64 shpp = pk(sh, sh), shnn = pk(-sh, -sh);

    // CRX(0,1) on REAL state: lane0 ctrl, target q1 (k bit 3). Branchless.
    {
      float ccl = g0 ? cc : 1.0f;
      float shl = g0 ? -sh : 0.0f;
      u64 cclp = pk(ccl, ccl), shlp = pk(shl, shl);
#pragma unroll
      for (int k = 0; k < 16; ++k) {
        Cr[k] = f2mul(cclp, P[k]);
        Ci[k] = f2mul(shlp, P[k ^ 8]);
      }
    }

    // CRX(2,3): lane1 ctrl, target q3 (k bit 2).
    {
      float ccl = g1 ? cc : 1.0f;
      float shl = g1 ? sh : 0.0f;
      u64 cclp = pk(ccl, ccl), sp = pk(shl, shl), sn = pk(-shl, -shl);
#pragma unroll
      for (int k = 0; k < 16; ++k) if (!(k & 4))
        CRX_PAIR(Cr[k], Ci[k], Cr[k+4], Ci[k+4], cclp, sp, sn);
    }

    // CRX(4,5): lane2 ctrl, target q5 (k bit 1).
    {
      float ccl = g2 ? cc : 1.0f;
      float shl = g2 ? sh : 0.0f;
      u64 cclp = pk(ccl, ccl), sp = pk(shl, shl), sn = pk(-shl, -shl);
#pragma unroll
      for (int k = 0; k < 16; ++k) if (!(k & 2))
        CRX_PAIR(Cr[k], Ci[k], Cr[k+2], Ci[k+2], cclp, sp, sn);
    }

    // CRX(6,7): ctrl q6 (k bit 0), target q7 (pack axis).
#pragma unroll
    for (int k = 0; k < 16; ++k) if (k & 1) {
      u64 r = Cr[k], i = Ci[k];
      Cr[k] = f2fma(ccp, r, f2mul(shpp, swp(i)));
      Ci[k] = f2fma(ccp, i, f2mul(shnn, swp(r)));
    }

    // CRX(1,2): ctrl q1 (k bit 3), target lane1.
#pragma unroll
    for (int k = 0; k < 16; ++k) if (k & 8) {
      u64 pr = __shfl_xor_sync(FULLMASK, Cr[k], 2);
      u64 pi = __shfl_xor_sync(FULLMASK, Ci[k], 2);
      Cr[k] = f2fma(ccp, Cr[k], f2mul(shpp, pi));
      Ci[k] = f2fma(ccp, Ci[k], f2mul(shnn, pr));
    }

    // CRX(3,4): ctrl q3 (k bit 2), target lane2.
#pragma unroll
    for (int k = 0; k < 16; ++k) if (k & 4) {
      u64 pr = __shfl_xor_sync(FULLMASK, Cr[k], 4);
      u64 pi = __shfl_xor_sync(FULLMASK, Ci[k], 4);
      Cr[k] = f2fma(ccp, Cr[k], f2mul(shpp, pi));
      Ci[k] = f2fma(ccp, Ci[k], f2mul(shnn, pr));
    }

    // CRX(5,6): ctrl q5 (k bit 1), target q6 (k bit 0).
#pragma unroll
    for (int k = 0; k < 16; ++k) if ((k & 2) && !(k & 1))
      CRX_PAIR(Cr[k], Ci[k], Cr[k+1], Ci[k+1], ccp, shpp, shnn);

    // U3(layer 0) tan form on q1(8), q3(4), q5(2), q7(pack); ct deferred.
    float uth = u3_params[0], uph = u3_params[1], ulm = u3_params[2];
    float ct, st;  sincosf(0.5f * uth, &st, &ct);
    ct_l0 = ct;
    float tu = __fdividef(st, ct);
    float clm, slm; sincosf(ulm, &slm, &clm);
    float cph, sph; sincosf(uph, &sph, &cph);
    float cpl, spl; sincosf(uph + ulm, &spl, &cpl);
    float Ar = clm * tu, Ai = slm * tu;
    float Cc = cph * tu, Cs = sph * tu;
    float Er = cpl,      Ei = spl;
    u64 pArn = pk(-Ar, -Ar), pAip = pk(Ai, Ai), pAin = pk(-Ai, -Ai);
    u64 pCc = pk(Cc, Cc), pCsn = pk(-Cs, -Cs), pCsp = pk(Cs, Cs);
    u64 pEr = pk(Er, Er), pEin = pk(-Ei, -Ei), pEip = pk(Ei, Ei);

#pragma unroll
    for (int k = 0; k < 16; ++k) if (!(k & 8))
      U3T_PAIR(Cr[k], Ci[k], Cr[k+8], Ci[k+8]);
#pragma unroll
    for (int k = 0; k < 16; ++k) if (!(k & 4))
      U3T_PAIR(Cr[k], Ci[k], Cr[k+4], Ci[k+4]);
#pragma unroll
    for (int k = 0; k < 16; ++k) if (!(k & 2))
      U3T_PAIR(Cr[k], Ci[k], Cr[k+2], Ci[k+2]);

    // U3 on q7 (pack axis), tan form.
    {
      u64 pDr = pk(1.0f, Er), pSr = pk(-Ar, Cc);
      u64 pDi = pk(0.0f, -Ei), pSi = pk(Ai, -Cs);
      u64 pDi2 = pk(0.0f, Ei), pSi2 = pk(-Ai, Cs);
#pragma unroll
      for (int k = 0; k < 16; ++k) {
        u64 r = Cr[k], i = Ci[k];
        u64 rs = swp(r), is = swp(i);
        Cr[k] = f2fma(pDr, r, f2fma(pSr, rs, f2fma(pDi, i, f2mul(pSi, is))));
        Ci[k] = f2fma(pDr, i, f2fma(pSr, is, f2fma(pDi2, r, f2mul(pSi2, rs))));
      }
    }
  }

  // --- layer 1 : active [1,3,5,7]; CRX (1,3)(5,7) then (3,5); U3 on 3,7 ---
  {
    float cc, sh; sincosf(0.5f * crx_theta[1], &sh, &cc);
    u64 ccp  = pk(cc, cc);
    u64 shpp = pk(sh, sh), shnn = pk(-sh, -sh);

#pragma unroll
    for (int k = 0; k < 16; ++k) if ((k & 8) && !(k & 4))     // CRX(1,3)
      CRX_PAIR(Cr[k], Ci[k], Cr[k+4], Ci[k+4], ccp, shpp, shnn);

#pragma unroll
    for (int k = 0; k < 16; ++k) if (k & 2) {                 // CRX(5,7)
      u64 r = Cr[k], i = Ci[k];
      Cr[k] = f2fma(ccp, r, f2mul(shpp, swp(i)));
      Ci[k] = f2fma(ccp, i, f2mul(shnn, swp(r)));
    }

#pragma unroll
    for (int k = 0; k < 16; ++k) if ((k & 4) && !(k & 2))     // CRX(3,5)
      CRX_PAIR(Cr[k], Ci[k], Cr[k+2], Ci[k+2], ccp, shpp, shnn);

    float uth = u3_params[3], uph = u3_params[4], ulm = u3_params[5];
    float ct, st;  sincosf(0.5f * uth, &st, &ct);
    ct_l1 = ct;
    float tu = __fdividef(st, ct);
    float clm, slm; sincosf(ulm, &slm, &clm);
    float cph, sph; sincosf(uph, &sph, &cph);
    float cpl, spl; sincosf(uph + ulm, &spl, &cpl);
    float Ar = clm * tu, Ai = slm * tu;
    float Cc = cph * tu, Cs = sph * tu;
    float Er = cpl,      Ei = spl;
    u64 pArn = pk(-Ar, -Ar), pAip = pk(Ai, Ai), pAin = pk(-Ai, -Ai);
    u64 pCc = pk(Cc, Cc), pCsn = pk(-Cs, -Cs), pCsp = pk(Cs, Cs);
    u64 pEr = pk(Er, Er), pEin = pk(-Ei, -Ei), pEip = pk(Ei, Ei);

    // U3 q3 (k bit 2)
#pragma unroll
    for (int k = 0; k < 16; ++k) if (!(k & 4))
      U3T_PAIR(Cr[k], Ci[k], Cr[k+4], Ci[k+4]);

    // U3 q7 (pack axis)
    {
      u64 pDr = pk(1.0f, Er), pSr = pk(-Ar, Cc);
      u64 pDi = pk(0.0f, -Ei), pSi = pk(Ai, -Cs);
      u64 pDi2 = pk(0.0f, Ei), pSi2 = pk(-Ai, Cs);
#pragma unroll
      for (int k = 0; k < 16; ++k) {
        u64 r = Cr[k], i = Ci[k];
        u64 rs = swp(r), is = swp(i);
        Cr[k] = f2fma(pDr, r, f2fma(pSr, rs, f2fma(pDi, i, f2mul(pSi, is))));
        Ci[k] = f2fma(pDr, i, f2fma(pSr, is, f2fma(pDi2, r, f2mul(pSi2, rs))));
      }
    }
  }

  // --- expval_z on q3 (k bit 2) and q7 (pack slot), deferred ct fixed via G^2 ---
  u64 accP = pk(0.0f, 0.0f), accN = accP;
#pragma unroll
  for (int k = 0; k < 16; ++k) {
    u64 pp = f2fma(Cr[k], Cr[k], f2mul(Ci[k], Ci[k]));
    if (k & 4) accN = f2add(accN, pp);
    else       accP = f2add(accP, pp);
  }
  float pl, ph, nl, nh;
  unpk(accP, pl, ph); unpk(accN, nl, nh);
  float z3 = (pl - nl) + (ph - nh);
  float z7 = (pl + nl) - (ph + nh);

  z3 += __shfl_xor_sync(FULLMASK, z3, 1);
  z3 += __shfl_xor_sync(FULLMASK, z3, 2);
  z3 += __shfl_xor_sync(FULLMASK, z3, 4);
  z7 += __shfl_xor_sync(FULLMASK, z7, 1);
  z7 += __shfl_xor_sync(FULLMASK, z7, 2);
  z7 += __shfl_xor_sync(FULLMASK, z7, 4);

  // --- MLP head (apply deferred scale G^2 = (ct0^4 * ct1^2)^2) ---
  if (g == 0) {
    float ct0sq = ct_l0 * ct_l0;
    float Gs = ct0sq * ct0sq * ct_l1 * ct_l1;  // G = ct0^4 ct1^2
    float G2 = Gs * Gs;
    z3 *= G2;
    z7 *= G2;
    float o = b2[0];
#pragma unroll
    for (int j = 0; j < 10; ++j) {
      float h = tanhf(z3 * w1[j] + z7 * w1[10 + j] + b1[j]);
      o += h * w2[j];
    }
    out[elem] = 1.0f / (1.0f + expf(-o));
  }
}

extern "C" void kernel_launch(void* const* d_in, const int* in_sizes, int n_in,
                              void* d_out, int out_size) {
  const float* x   = (const float*)d_in[0];
  const float* crx = (const float*)d_in[1];
  const float* u3p = (const float*)d_in[2];
  const float* w1  = (const float*)d_in[3];
  const float* b1  = (const float*)d_in[4];
  const float* w2  = (const float*)d_in[5];
  const float* b2  = (const float*)d_in[6];
  float* out = (float*)d_out;

  int B = in_sizes[0] / 8;
  int threads = B * 8;
  int block = 128;
  int grid = (threads + block - 1) / block;
  qcnn_kernel<<<grid, block>>>(x, crx, u3p, w1, b1, w2, b2, out, B);
}

// round 7
// speedup vs baseline: 2.7146x; 1.0539x over previous
#include <cuda_runtime.h>
#include <math.h>

#define FULLMASK 0xffffffffu
typedef unsigned long long u64;

// ---- packed f32x2 primitives (sm_103a; ptxas won't emit these from C++) ----
__device__ __forceinline__ u64 pk(float lo, float hi) {
  u64 r; asm("mov.b64 %0, {%1,%2};" : "=l"(r) : "f"(lo), "f"(hi)); return r;
}
__device__ __forceinline__ void unpk(u64 v, float& lo, float& hi) {
  asm("mov.b64 {%0,%1}, %2;" : "=f"(lo), "=f"(hi) : "l"(v));
}
__device__ __forceinline__ u64 swp(u64 v) {
  float l, h; unpk(v, l, h); return pk(h, l);
}
__device__ __forceinline__ u64 f2fma(u64 a, u64 b, u64 c) {
  u64 d; asm("fma.rn.f32x2 %0, %1, %2, %3;" : "=l"(d) : "l"(a), "l"(b), "l"(c)); return d;
}
__device__ __forceinline__ u64 f2mul(u64 a, u64 b) {
  u64 d; asm("mul.rn.f32x2 %0, %1, %2;" : "=l"(d) : "l"(a), "l"(b)); return d;
}
__device__ __forceinline__ u64 f2add(u64 a, u64 b) {
  u64 d; asm("add.rn.f32x2 %0, %1, %2;" : "=l"(d) : "l"(a), "l"(b)); return d;
}

// ---------------------------------------------------------------------------
// Layout: 8 lanes per element (g = tid&7).
// Lane bits: q0 -> lane xor 1, q2 -> lane xor 2, q4 -> lane xor 4.
// PACK AXIS: q6 (lo slot = q6=0, hi slot = q6=1).
// k index (4 bits): bit3=q1(8), bit2=q3(4), bit1=q5(2), bit0=q7(1).
// CYCLE PHASE (real): P[16] packed, TAN-form rotations (uniform cos deferred
// into the cycle-1 seed as (prod c)^3).
// LAYER PHASE: Cr[16], Ci[16]. With pack=q6, ALL U3s and all of layer 1 are
// register-local (q6 is never a layer target except CRX(5,6)).
// ---------------------------------------------------------------------------

template<int TMk>
__device__ __forceinline__ void ry_reg_t(u64 (&P)[16], u64 tt, u64 ttn) {
#pragma unroll
  for (int k = 0; k < 16; ++k) if (!(k & TMk)) {
    u64 A = P[k], B = P[k + TMk];
    P[k]       = f2fma(ttn, B, A);
    P[k + TMk] = f2fma(tt, A, B);
  }
}

// RY tan form on q6 (pack axis): v' = v + (-t,+t) .* swp(v)
__device__ __forceinline__ void ry_pack_t(u64 (&P)[16], u64 t_pm) {
#pragma unroll
  for (int k = 0; k < 16; ++k)
    P[k] = f2fma(t_pm, swp(P[k]), P[k]);
}

// Fused RY(lane LM) + CNOT(ctrl k-bit KM, target lane LM), tan form (RY first).
template<int LM, int KM>
__device__ __forceinline__ void ry_lane_cnot_t(u64 (&P)[16], u64 tgg, u64 tggn) {
#pragma unroll
  for (int k = 0; k < 16; ++k) {
    u64 p = __shfl_xor_sync(FULLMASK, P[k], LM);
    if (k & KM) P[k] = f2fma(tggn, P[k], p);   // partner post-RY: p - tg*a
    else        P[k] = f2fma(tgg, p, P[k]);    // mine:           a + tg*p
  }
}

// Fused CNOT(ctrl k-bit KM, target lane LM) + RY(lane LM)  (CNOT first).
template<int LM, int KM>
__device__ __forceinline__ void cnot_ry_lane_t(u64 (&P)[16], u64 tgg) {
#pragma unroll
  for (int k = 0; k < 16; ++k) {
    u64 p = __shfl_xor_sync(FULLMASK, P[k], LM);
    if (k & KM) P[k] = f2fma(tgg, P[k], p);    // swapped first: p + tg*a
    else        P[k] = f2fma(tgg, p, P[k]);    // a + tg*p
  }
}

template<int TMk>
__device__ __forceinline__ void condswap(u64 (&P)[16], bool f) {
#pragma unroll
  for (int k = 0; k < 16; ++k) if (!(k & TMk)) {
    u64 A = P[k], B = P[k + TMk];
    P[k]       = f ? B : A;
    P[k + TMk] = f ? A : B;
  }
}

// CRX pair on register target.
#define CRX_PAIR(Cr0, Ci0, Cr1, Ci1, ccp, shp, shn)                 \
  {                                                                 \
    u64 _r0 = (Cr0), _i0 = (Ci0), _r1 = (Cr1), _i1 = (Ci1);         \
    (Cr0) = f2fma((ccp), _r0, f2mul((shp), _i1));                   \
    (Ci0) = f2fma((ccp), _i0, f2mul((shn), _r1));                   \
    (Cr1) = f2fma((ccp), _r1, f2mul((shp), _i0));                   \
    (Ci1) = f2fma((ccp), _i1, f2mul((shn), _r0));                   \
  }

// U3 pair in tan form (ct deferred).
#define U3T_PAIR(Cr0, Ci0, Cr1, Ci1)                                            \
  {                                                                             \
    u64 _r0 = (Cr0), _i0 = (Ci0), _r1 = (Cr1), _i1 = (Ci1);                     \
    (Cr0) = f2fma(pArn, _r1, f2fma(pAip, _i1, _r0));                            \
    (Ci0) = f2fma(pArn, _i1, f2fma(pAin, _r1, _i0));                            \
    (Cr1) = f2fma(pCc, _r0, f2fma(pCsn, _i0, f2fma(pEr, _r1, f2mul(pEin, _i1))));\
    (Ci1) = f2fma(pCc, _i0, f2fma(pCsp, _r0, f2fma(pEr, _i1, f2mul(pEip, _r1))));\
  }

__global__ void __launch_bounds__(128, 4)
qcnn_kernel(const float* __restrict__ x,
            const float* __restrict__ crx_theta,
            const float* __restrict__ u3_params,
            const float* __restrict__ w1,
            const float* __restrict__ b1,
            const float* __restrict__ w2,
            const float* __restrict__ b2,
            float* __restrict__ out, int B)
{
  int tid  = blockIdx.x * blockDim.x + threadIdx.x;
  int elem = tid >> 3;
  if (elem >= B) return;
  int g = tid & 7;
  bool g0 = (g & 1) != 0;
  bool g1 = (g & 2) != 0;
  bool g2 = (g & 4) != 0;

  // --- angles: lane q computes sincos+tan for qubit q, broadcast in-group ---
  float myx = x[elem * 8 + g];
  float ms, mc;
  sincosf(0.5f * myx, &ms, &mc);
  float mt = __fdividef(ms, mc);
  float cq[8], sq[8], tq[8];
#pragma unroll
  for (int q = 0; q < 8; ++q) {
    cq[q] = __shfl_sync(FULLMASK, mc, q, 8);
    sq[q] = __shfl_sync(FULLMASK, ms, q, 8);
    tq[q] = __shfl_sync(FULLMASK, mt, q, 8);
  }

  float tg0 = g0 ? tq[0] : -tq[0];
  float tg2 = g1 ? tq[2] : -tq[2];
  float tg4 = g2 ? tq[4] : -tq[4];

  // deferred cos factor for cycles 2..4: (prod_q c_q)^3
  float cprod = cq[0]*cq[1]*cq[2]*cq[3]*cq[4]*cq[5]*cq[6]*cq[7];
  float F = cprod * cprod * cprod;

  // --- cycle 1: product state via doubling (k bits q7,q5,q3,q1), seeded with F ---
  float b[16];
  b[0] = F * (g0 ? sq[0] : cq[0]) * (g1 ? sq[2] : cq[2]) * (g2 ? sq[4] : cq[4]);
#pragma unroll
  for (int i = 0; i < 1; ++i) { b[i+1] = b[i]*sq[7]; b[i] *= cq[7]; }
#pragma unroll
  for (int i = 0; i < 2; ++i) { b[i+2] = b[i]*sq[5]; b[i] *= cq[5]; }
#pragma unroll
  for (int i = 0; i < 4; ++i) { b[i+4] = b[i]*sq[3]; b[i] *= cq[3]; }
#pragma unroll
  for (int i = 0; i < 8; ++i) { b[i+8] = b[i]*sq[1]; b[i] *= cq[1]; }

  u64 P[16];
  {
    u64 c6s6 = pk(cq[6], sq[6]);   // pack axis q6
#pragma unroll
    for (int k = 0; k < 16; ++k) P[k] = f2mul(pk(b[k], b[k]), c6s6);
  }

  // cycle 1 CNOT ring (0,1)(1,2)(2,3)(3,4)(4,5)(5,6)(6,7); (7,0) deferred.
  condswap<8>(P, g0);                       // (0,1): lane0 ctrl -> q1
#pragma unroll
  for (int k = 0; k < 16; ++k) if (k & 8)   // (1,2): q1 ctrl -> lane1
    P[k] = __shfl_xor_sync(FULLMASK, P[k], 2);
  condswap<4>(P, g1);                       // (2,3): lane1 ctrl -> q3
#pragma unroll
  for (int k = 0; k < 16; ++k) if (k & 4)   // (3,4): q3 ctrl -> lane2
    P[k] = __shfl_xor_sync(FULLMASK, P[k], 4);
  condswap<2>(P, g2);                       // (4,5): lane2 ctrl -> q5
#pragma unroll
  for (int k = 0; k < 16; ++k) if (k & 2)   // (5,6): q5 ctrl -> q6 (in-pack swap)
    P[k] = swp(P[k]);
#pragma unroll
  for (int k = 0; k < 16; k += 2) {         // (6,7): q6(pack hi) ctrl -> q7 (k bit 0)
    float l0, h0, l1, h1;
    unpk(P[k], l0, h0); unpk(P[k+1], l1, h1);
    P[k] = pk(l0, h1); P[k+1] = pk(l1, h0);
  }

  // --- cycles 2..4 (tan form) ---
  {
    u64 tgg0 = pk(tg0, tg0);
    u64 tt1 = pk(tq[1], tq[1]), tn1 = pk(-tq[1], -tq[1]);
    u64 tt3 = pk(tq[3], tq[3]), tn3 = pk(-tq[3], -tq[3]);
    u64 tt5 = pk(tq[5], tq[5]), tn5 = pk(-tq[5], -tq[5]);
    u64 tt7 = pk(tq[7], tq[7]), tn7 = pk(-tq[7], -tq[7]);
    u64 t6pm = pk(-tq[6], tq[6]);
    u64 tgg2 = pk(tg2, tg2), tgg2n = pk(-tg2, -tg2);
    u64 tgg4 = pk(tg4, tg4), tgg4n = pk(-tg4, -tg4);

#pragma unroll
    for (int cy = 0; cy < 3; ++cy) {
      // fused CNOT(7,0) [prev cycle; ctrl q7 = k bit 0] + RY(q0)
      cnot_ry_lane_t<1, 1>(P, tgg0);
      ry_reg_t<8>(P, tt1, tn1);                    // RY q1
      ry_reg_t<4>(P, tt3, tn3);                    // RY q3
      ry_reg_t<2>(P, tt5, tn5);                    // RY q5
      ry_reg_t<1>(P, tt7, tn7);                    // RY q7
      ry_pack_t(P, t6pm);                          // RY q6 (pack)
      condswap<8>(P, g0);                          // CNOT(0,1)
      ry_lane_cnot_t<2, 8>(P, tgg2, tgg2n);        // RY q2 + CNOT(1,2)
      condswap<4>(P, g1);                          // CNOT(2,3)
      ry_lane_cnot_t<4, 4>(P, tgg4, tgg4n);        // RY q4 + CNOT(3,4)
      condswap<2>(P, g2);                          // CNOT(4,5)
#pragma unroll
      for (int k = 0; k < 16; ++k) if (k & 2)      // CNOT(5,6): in-pack swap
        P[k] = swp(P[k]);
#pragma unroll
      for (int k = 0; k < 16; k += 2) {            // CNOT(6,7): hi-half exchange
        float l0, h0, l1, h1;
        unpk(P[k], l0, h0); unpk(P[k+1], l1, h1);
        P[k] = pk(l0, h1); P[k+1] = pk(l1, h0);
      }
    }
  }

  // final standalone CNOT(7,0): ctrl q7 (k bit 0), target lane0
#pragma unroll
  for (int k = 0; k < 16; ++k) if (k & 1)
    P[k] = __shfl_xor_sync(FULLMASK, P[k], 1);

  // =================== LAYER PHASE (split re/im, packed over q6) ===========
  u64 Cr[16], Ci[16];
  float ct_l0, ct_l1;

  // --- layer 0 : CRX (0,1)(2,3)(4,5)(6,7) then (1,2)(3,4)(5,6); U3 on 1,3,5,7
  {
    float cc, sh; sincosf(0.5f * crx_theta[0], &sh, &cc);
    u64 ccp  = pk(cc, cc);
    u64 shpp = pk(sh, sh), shnn = pk(-sh, -sh);

    // CRX(0,1) on REAL state: lane0 ctrl, target q1 (k bit 3). Branchless.
    {
      float ccl = g0 ? cc : 1.0f;
      float shl = g0 ? -sh : 0.0f;
      u64 cclp = pk(ccl, ccl), shlp = pk(shl, shl);
#pragma unroll
      for (int k = 0; k < 16; ++k) {
        Cr[k] = f2mul(cclp, P[k]);
        Ci[k] = f2mul(shlp, P[k ^ 8]);
      }
    }

    // CRX(2,3): lane1 ctrl, target q3 (k bit 2). Branchless lane consts.
    {
      float ccl = g1 ? cc : 1.0f;
      float shl = g1 ? sh : 0.0f;
      u64 cclp = pk(ccl, ccl), sp = pk(shl, shl), sn = pk(-shl, -shl);
#pragma unroll
      for (int k = 0; k < 16; ++k) if (!(k & 4))
        CRX_PAIR(Cr[k], Ci[k], Cr[k+4], Ci[k+4], cclp, sp, sn);
    }

    // CRX(4,5): lane2 ctrl, target q5 (k bit 1).
    {
      float ccl = g2 ? cc : 1.0f;
      float shl = g2 ? sh : 0.0f;
      u64 cclp = pk(ccl, ccl), sp = pk(shl, shl), sn = pk(-shl, -shl);
#pragma unroll
      for (int k = 0; k < 16; ++k) if (!(k & 2))
        CRX_PAIR(Cr[k], Ci[k], Cr[k+2], Ci[k+2], cclp, sp, sn);
    }

    // CRX(6,7): ctrl q6 = pack HI slot, target q7 (k bit 0).
    // Masked packed constants apply the gate to the hi slot only — no swaps.
    {
      u64 cc_m = pk(1.0f, cc), sp_m = pk(0.0f, sh), sn_m = pk(0.0f, -sh);
#pragma unroll
      for (int k = 0; k < 16; ++k) if (!(k & 1))
        CRX_PAIR(Cr[k], Ci[k], Cr[k+1], Ci[k+1], cc_m, sp_m, sn_m);
    }

    // CRX(1,2): ctrl q1 (k bit 3), target lane1.
#pragma unroll
    for (int k = 0; k < 16; ++k) if (k & 8) {
      u64 pr = __shfl_xor_sync(FULLMASK, Cr[k], 2);
      u64 pi = __shfl_xor_sync(FULLMASK, Ci[k], 2);
      Cr[k] = f2fma(ccp, Cr[k], f2mul(shpp, pi));
      Ci[k] = f2fma(ccp, Ci[k], f2mul(shnn, pr));
    }

    // CRX(3,4): ctrl q3 (k bit 2), target lane2.
#pragma unroll
    for (int k = 0; k < 16; ++k) if (k & 4) {
      u64 pr = __shfl_xor_sync(FULLMASK, Cr[k], 4);
      u64 pi = __shfl_xor_sync(FULLMASK, Ci[k], 4);
      Cr[k] = f2fma(ccp, Cr[k], f2mul(shpp, pi));
      Ci[k] = f2fma(ccp, Ci[k], f2mul(shnn, pr));
    }

    // CRX(5,6): ctrl q5 (k bit 1), target q6 (pack axis): in-pack with swap.
#pragma unroll
    for (int k = 0; k < 16; ++k) if (k & 2) {
      u64 r = Cr[k], i = Ci[k];
      Cr[k] = f2fma(ccp, r, f2mul(shpp, swp(i)));
      Ci[k] = f2fma(ccp, i, f2mul(shnn, swp(r)));
    }

    // U3(layer 0) tan form on q1(8), q3(4), q5(2), q7(1) — ALL register pairs.
    float uth = u3_params[0], uph = u3_params[1], ulm = u3_params[2];
    float ct, st;  sincosf(0.5f * uth, &st, &ct);
    ct_l0 = ct;
    float tu = __fdividef(st, ct);
    float clm, slm; sincosf(ulm, &slm, &clm);
    float cph, sph; sincosf(uph, &sph, &cph);
    float cpl, spl; sincosf(uph + ulm, &spl, &cpl);
    float Ar = clm * tu, Ai = slm * tu;
    float Cc = cph * tu, Cs = sph * tu;
    float Er = cpl,      Ei = spl;
    u64 pArn = pk(-Ar, -Ar), pAip = pk(Ai, Ai), pAin = pk(-Ai, -Ai);
    u64 pCc = pk(Cc, Cc), pCsn = pk(-Cs, -Cs), pCsp = pk(Cs, Cs);
    u64 pEr = pk(Er, Er), pEin = pk(-Ei, -Ei), pEip = pk(Ei, Ei);

#pragma unroll
    for (int k = 0; k < 16; ++k) if (!(k & 8))
      U3T_PAIR(Cr[k], Ci[k], Cr[k+8], Ci[k+8]);
#pragma unroll
    for (int k = 0; k < 16; ++k) if (!(k & 4))
      U3T_PAIR(Cr[k], Ci[k], Cr[k+4], Ci[k+4]);
#pragma unroll
    for (int k = 0; k < 16; ++k) if (!(k & 2))
      U3T_PAIR(Cr[k], Ci[k], Cr[k+2], Ci[k+2]);
#pragma unroll
    for (int k = 0; k < 16; ++k) if (!(k & 1))
      U3T_PAIR(Cr[k], Ci[k], Cr[k+1], Ci[k+1]);
  }

  // --- layer 1 : active [1,3,5,7]; fully register-local now ---
  {
    float cc, sh; sincosf(0.5f * crx_theta[1], &sh, &cc);
    u64 ccp  = pk(cc, cc);
    u64 shpp = pk(sh, sh), shnn = pk(-sh, -sh);

#pragma unroll
    for (int k = 0; k < 16; ++k) if ((k & 8) && !(k & 4))     // CRX(1,3)
      CRX_PAIR(Cr[k], Ci[k], Cr[k+4], Ci[k+4], ccp, shpp, shnn);
#pragma unroll
    for (int k = 0; k < 16; ++k) if ((k & 2) && !(k & 1))     // CRX(5,7)
      CRX_PAIR(Cr[k], Ci[k], Cr[k+1], Ci[k+1], ccp, shpp, shnn);
#pragma unroll
    for (int k = 0; k < 16; ++k) if ((k & 4) && !(k & 2))     // CRX(3,5)
      CRX_PAIR(Cr[k], Ci[k], Cr[k+2], Ci[k+2], ccp, shpp, shnn);

    float uth = u3_params[3], uph = u3_params[4], ulm = u3_params[5];
    float ct, st;  sincosf(0.5f * uth, &st, &ct);
    ct_l1 = ct;
    float tu = __fdividef(st, ct);
    float clm, slm; sincosf(ulm, &slm, &clm);
    float cph, sph; sincosf(uph, &sph, &cph);
    float cpl, spl; sincosf(uph + ulm, &spl, &cpl);
    float Ar = clm * tu, Ai = slm * tu;
    float Cc = cph * tu, Cs = sph * tu;
    float Er = cpl,      Ei = spl;
    u64 pArn = pk(-Ar, -Ar), pAip = pk(Ai, Ai), pAin = pk(-Ai, -Ai);
    u64 pCc = pk(Cc, Cc), pCsn = pk(-Cs, -Cs), pCsp = pk(Cs, Cs);
    u64 pEr = pk(Er, Er), pEin = pk(-Ei, -Ei), pEip = pk(Ei, Ei);

    // U3 q3 (k bit 2)
#pragma unroll
    for (int k = 0; k < 16; ++k) if (!(k & 4))
      U3T_PAIR(Cr[k], Ci[k], Cr[k+4], Ci[k+4]);
    // U3 q7 (k bit 0)
#pragma unroll
    for (int k = 0; k < 16; ++k) if (!(k & 1))
      U3T_PAIR(Cr[k], Ci[k], Cr[k+1], Ci[k+1]);
  }

  // --- expval_z on q3 (k bit 2) and q7 (k bit 0); pack axis q6 sums freely ---
  u64 acc0 = pk(0.f, 0.f), acc1 = acc0, acc2 = acc0, acc3 = acc0;
#pragma unroll
  for (int k = 0; k < 16; ++k) {
    u64 pp = f2fma(Cr[k], Cr[k], f2mul(Ci[k], Ci[k]));
    int idx = ((k & 4) ? 2 : 0) | (k & 1);
    if      (idx == 0) acc0 = f2add(acc0, pp);
    else if (idx == 1) acc1 = f2add(acc1, pp);
    else if (idx == 2) acc2 = f2add(acc2, pp);
    else               acc3 = f2add(acc3, pp);
  }
  float l, h, s0, s1, s2, s3;
  unpk(acc0, l, h); s0 = l + h;
  unpk(acc1, l, h); s1 = l + h;
  unpk(acc2, l, h); s2 = l + h;
  unpk(acc3, l, h); s3 = l + h;
  float z3 = (s0 + s1) - (s2 + s3);   // sign by q3 (k bit 2)
  float z7 = (s0 + s2) - (s1 + s3);   // sign by q7 (k bit 0)

  z3 += __shfl_xor_sync(FULLMASK, z3, 1);
  z3 += __shfl_xor_sync(FULLMASK, z3, 2);
  z3 += __shfl_xor_sync(FULLMASK, z3, 4);
  z7 += __shfl_xor_sync(FULLMASK, z7, 1);
  z7 += __shfl_xor_sync(FULLMASK, z7, 2);
  z7 += __shfl_xor_sync(FULLMASK, z7, 4);

  // --- MLP head (apply deferred U3 scale G^2, G = ct0^4 * ct1^2) ---
  if (g == 0) {
    float ct0sq = ct_l0 * ct_l0;
    float Gs = ct0sq * ct0sq * ct_l1 * ct_l1;
    float G2 = Gs * Gs;
    z3 *= G2;
    z7 *= G2;
    float o = b2[0];
#pragma unroll
    for (int j = 0; j < 10; ++j) {
      float hh = tanhf(z3 * w1[j] + z7 * w1[10 + j] + b1[j]);
      o += hh * w2[j];
    }
    out[elem] = 1.0f / (1.0f + expf(-o));
  }
}

extern "C" void kernel_launch(void* const* d_in, const int* in_sizes, int n_in,
                              void* d_out, int out_size) {
  const float* x   = (const float*)d_in[0];
  const float* crx = (const float*)d_in[1];
  const float* u3p = (const float*)d_in[2];
  const float* w1  = (const float*)d_in[3];
  const float* b1  = (const float*)d_in[4];
  const float* w2  = (const float*)d_in[5];
  const float* b2  = (const float*)d_in[6];
  float* out = (float*)d_out;

  int B = in_sizes[0] / 8;
  int threads = B * 8;
  int block = 128;
  int grid = (threads + block - 1) / block;
  qcnn_kernel<<<grid, block>>>(x, crx, u3p, w1, b1, w2, b2, out, B);
}

// round 8
// speedup vs baseline: 2.8523x; 1.0508x over previous
#include <cuda_runtime.h>
#include <math.h>

#define FULLMASK 0xffffffffu
typedef unsigned long long u64;

// ---- packed f32x2 primitives (sm_103a; ptxas won't emit these from C++) ----
__device__ __forceinline__ u64 pk(float lo, float hi) {
  u64 r; asm("mov.b64 %0, {%1,%2};" : "=l"(r) : "f"(lo), "f"(hi)); return r;
}
__device__ __forceinline__ void unpk(u64 v, float& lo, float& hi) {
  asm("mov.b64 {%0,%1}, %2;" : "=f"(lo), "=f"(hi) : "l"(v));
}
__device__ __forceinline__ u64 swp(u64 v) {
  float l, h; unpk(v, l, h); return pk(h, l);
}
__device__ __forceinline__ u64 f2fma(u64 a, u64 b, u64 c) {
  u64 d; asm("fma.rn.f32x2 %0, %1, %2, %3;" : "=l"(d) : "l"(a), "l"(b), "l"(c)); return d;
}
__device__ __forceinline__ u64 f2mul(u64 a, u64 b) {
  u64 d; asm("mul.rn.f32x2 %0, %1, %2;" : "=l"(d) : "l"(a), "l"(b)); return d;
}
__device__ __forceinline__ u64 f2add(u64 a, u64 b) {
  u64 d; asm("add.rn.f32x2 %0, %1, %2;" : "=l"(d) : "l"(a), "l"(b)); return d;
}

// ---------------------------------------------------------------------------
// Layout: 8 lanes per element (g = tid&7).
// Lane bits: q0 -> lane xor 1, q2 -> lane xor 2, q4 -> lane xor 4.
// PACK AXIS: q6 (lo slot = q6=0, hi slot = q6=1).
// k index (4 bits): bit3=q1(8), bit2=q3(4), bit1=q5(2), bit0=q7(1).
// CYCLE PHASE (real): P[16] packed, TAN-form rotations (uniform cos deferred
// into the cycle-1 seed as (prod c)^3).
// LAYER PHASE: Cr[16], Ci[16]; U3 tan form with ct deferred (fixed via G^2).
// ---------------------------------------------------------------------------

template<int TMk>
__device__ __forceinline__ void ry_reg_t(u64 (&P)[16], u64 tt, u64 ttn) {
#pragma unroll
  for (int k = 0; k < 16; ++k) if (!(k & TMk)) {
    u64 A = P[k], B = P[k + TMk];
    P[k]       = f2fma(ttn, B, A);
    P[k + TMk] = f2fma(tt, A, B);
  }
}

// RY tan form on q6 (pack axis)
__device__ __forceinline__ void ry_pack_t(u64 (&P)[16], u64 t_pm) {
#pragma unroll
  for (int k = 0; k < 16; ++k)
    P[k] = f2fma(t_pm, swp(P[k]), P[k]);
}

// Fused RY(lane LM) + CNOT(ctrl k-bit KM, target lane LM), tan form (RY first).
template<int LM, int KM>
__device__ __forceinline__ void ry_lane_cnot_t(u64 (&P)[16], u64 tgg, u64 tggn) {
#pragma unroll
  for (int k = 0; k < 16; ++k) {
    u64 p = __shfl_xor_sync(FULLMASK, P[k], LM);
    if (k & KM) P[k] = f2fma(tggn, P[k], p);
    else        P[k] = f2fma(tgg, p, P[k]);
  }
}

// Fused CNOT(ctrl k-bit KM, target lane LM) + RY(lane LM)  (CNOT first).
template<int LM, int KM>
__device__ __forceinline__ void cnot_ry_lane_t(u64 (&P)[16], u64 tgg) {
#pragma unroll
  for (int k = 0; k < 16; ++k) {
    u64 p = __shfl_xor_sync(FULLMASK, P[k], LM);
    if (k & KM) P[k] = f2fma(tgg, P[k], p);
    else        P[k] = f2fma(tgg, p, P[k]);
  }
}

template<int TMk>
__device__ __forceinline__ void condswap(u64 (&P)[16], bool f) {
#pragma unroll
  for (int k = 0; k < 16; ++k) if (!(k & TMk)) {
    u64 A = P[k], B = P[k + TMk];
    P[k]       = f ? B : A;
    P[k + TMk] = f ? A : B;
  }
}

#define CRX_PAIR(Cr0, Ci0, Cr1, Ci1, ccp, shp, shn)                 \
  {                                                                 \
    u64 _r0 = (Cr0), _i0 = (Ci0), _r1 = (Cr1), _i1 = (Ci1);         \
    (Cr0) = f2fma((ccp), _r0, f2mul((shp), _i1));                   \
    (Ci0) = f2fma((ccp), _i0, f2mul((shn), _r1));                   \
    (Cr1) = f2fma((ccp), _r1, f2mul((shp), _i0));                   \
    (Ci1) = f2fma((ccp), _i1, f2mul((shn), _r0));                   \
  }

#define U3T_PAIR(Cr0, Ci0, Cr1, Ci1)                                            \
  {                                                                             \
    u64 _r0 = (Cr0), _i0 = (Ci0), _r1 = (Cr1), _i1 = (Ci1);                     \
    (Cr0) = f2fma(pArn, _r1, f2fma(pAip, _i1, _r0));                            \
    (Ci0) = f2fma(pArn, _i1, f2fma(pAin, _r1, _i0));                            \
    (Cr1) = f2fma(pCc, _r0, f2fma(pCsn, _i0, f2fma(pEr, _r1, f2mul(pEin, _i1))));\
    (Ci1) = f2fma(pCc, _i0, f2fma(pCsp, _r0, f2fma(pEr, _i1, f2mul(pEip, _r1))));\
  }

__global__ void __launch_bounds__(128, 5)
qcnn_kernel(const float* __restrict__ x,
            const float* __restrict__ crx_theta,
            const float* __restrict__ u3_params,
            const float* __restrict__ w1,
            const float* __restrict__ b1,
            const float* __restrict__ w2,
            const float* __restrict__ b2,
            float* __restrict__ out, int B)
{
  int tid  = blockIdx.x * blockDim.x + threadIdx.x;
  int elem = tid >> 3;
  if (elem >= B) return;
  int g = tid & 7;
  bool g0 = (g & 1) != 0;
  bool g1 = (g & 2) != 0;
  bool g2 = (g & 4) != 0;

  // --- angles: lane q computes sincos+tan for qubit q, broadcast in-group ---
  float myx = x[elem * 8 + g];
  float ms, mc;
  sincosf(0.5f * myx, &ms, &mc);
  float mt = __fdividef(ms, mc);

  float tq[8];
#pragma unroll
  for (int q = 0; q < 8; ++q) tq[q] = __shfl_sync(FULLMASK, mt, q, 8);

  // seed products: consume cq/sq immediately so they die before the t-packs live
  float b[16];
  u64 P[16];
  {
    float cq[8], sq[8];
#pragma unroll
    for (int q = 0; q < 8; ++q) {
      cq[q] = __shfl_sync(FULLMASK, mc, q, 8);
      sq[q] = __shfl_sync(FULLMASK, ms, q, 8);
    }
    // deferred cos factor for cycles 2..4: (prod_q c_q)^3
    float cprod = cq[0]*cq[1]*cq[2]*cq[3]*cq[4]*cq[5]*cq[6]*cq[7];
    float F = cprod * cprod * cprod;

    b[0] = F * (g0 ? sq[0] : cq[0]) * (g1 ? sq[2] : cq[2]) * (g2 ? sq[4] : cq[4]);
#pragma unroll
    for (int i = 0; i < 1; ++i) { b[i+1] = b[i]*sq[7]; b[i] *= cq[7]; }
#pragma unroll
    for (int i = 0; i < 2; ++i) { b[i+2] = b[i]*sq[5]; b[i] *= cq[5]; }
#pragma unroll
    for (int i = 0; i < 4; ++i) { b[i+4] = b[i]*sq[3]; b[i] *= cq[3]; }
#pragma unroll
    for (int i = 0; i < 8; ++i) { b[i+8] = b[i]*sq[1]; b[i] *= cq[1]; }

    u64 c6s6 = pk(cq[6], sq[6]);   // pack axis q6
#pragma unroll
    for (int k = 0; k < 16; ++k) P[k] = f2mul(pk(b[k], b[k]), c6s6);
  }

  float tg0 = g0 ? tq[0] : -tq[0];
  float tg2 = g1 ? tq[2] : -tq[2];
  float tg4 = g2 ? tq[4] : -tq[4];

  // cycle 1 CNOT ring (0,1)(1,2)(2,3)(3,4)(4,5)(5,6)(6,7); (7,0) deferred.
  condswap<8>(P, g0);                       // (0,1)
#pragma unroll
  for (int k = 0; k < 16; ++k) if (k & 8)   // (1,2)
    P[k] = __shfl_xor_sync(FULLMASK, P[k], 2);
  condswap<4>(P, g1);                       // (2,3)
#pragma unroll
  for (int k = 0; k < 16; ++k) if (k & 4)   // (3,4)
    P[k] = __shfl_xor_sync(FULLMASK, P[k], 4);
  condswap<2>(P, g2);                       // (4,5)
#pragma unroll
  for (int k = 0; k < 16; ++k) if (k & 2)   // (5,6): in-pack swap
    P[k] = swp(P[k]);
#pragma unroll
  for (int k = 0; k < 16; k += 2) {         // (6,7): pack-hi ctrl -> q7 (k bit 0)
    float l0, h0, l1, h1;
    unpk(P[k], l0, h0); unpk(P[k+1], l1, h1);
    P[k] = pk(l0, h1); P[k+1] = pk(l1, h0);
  }

  // --- cycles 2..4 (tan form) ---
  {
    u64 tgg0 = pk(tg0, tg0);
    u64 tt1 = pk(tq[1], tq[1]), tn1 = pk(-tq[1], -tq[1]);
    u64 tt3 = pk(tq[3], tq[3]), tn3 = pk(-tq[3], -tq[3]);
    u64 tt5 = pk(tq[5], tq[5]), tn5 = pk(-tq[5], -tq[5]);
    u64 tt7 = pk(tq[7], tq[7]), tn7 = pk(-tq[7], -tq[7]);
    u64 t6pm = pk(-tq[6], tq[6]);
    u64 tgg2 = pk(tg2, tg2), tgg2n = pk(-tg2, -tg2);
    u64 tgg4 = pk(tg4, tg4), tgg4n = pk(-tg4, -tg4);

#pragma unroll
    for (int cy = 0; cy < 3; ++cy) {
      cnot_ry_lane_t<1, 1>(P, tgg0);               // CNOT(7,0)[prev] + RY q0
      ry_reg_t<8>(P, tt1, tn1);                    // RY q1
      ry_reg_t<4>(P, tt3, tn3);                    // RY q3
      ry_reg_t<2>(P, tt5, tn5);                    // RY q5
      ry_reg_t<1>(P, tt7, tn7);                    // RY q7
      ry_pack_t(P, t6pm);                          // RY q6 (pack)
      condswap<8>(P, g0);                          // CNOT(0,1)
      ry_lane_cnot_t<2, 8>(P, tgg2, tgg2n);        // RY q2 + CNOT(1,2)
      condswap<4>(P, g1);                          // CNOT(2,3)
      ry_lane_cnot_t<4, 4>(P, tgg4, tgg4n);        // RY q4 + CNOT(3,4)
      condswap<2>(P, g2);                          // CNOT(4,5)
#pragma unroll
      for (int k = 0; k < 16; ++k) if (k & 2)      // CNOT(5,6)
        P[k] = swp(P[k]);
#pragma unroll
      for (int k = 0; k < 16; k += 2) {            // CNOT(6,7)
        float l0, h0, l1, h1;
        unpk(P[k], l0, h0); unpk(P[k+1], l1, h1);
        P[k] = pk(l0, h1); P[k+1] = pk(l1, h0);
      }
    }
  }

  // final standalone CNOT(7,0): ctrl q7 (k bit 0), target lane0
#pragma unroll
  for (int k = 0; k < 16; ++k) if (k & 1)
    P[k] = __shfl_xor_sync(FULLMASK, P[k], 1);

  // =================== LAYER PHASE (split re/im, packed over q6) ===========
  u64 Cr[16], Ci[16];
  float ct_l0, ct_l1;

  // --- layer 0 ---
  {
    float cc, sh; sincosf(0.5f * crx_theta[0], &sh, &cc);
    u64 ccp  = pk(cc, cc);
    u64 shpp = pk(sh, sh), shnn = pk(-sh, -sh);

    // CRX(0,1) on REAL state: lane0 ctrl, target q1 (k bit 3). Branchless.
    {
      float ccl = g0 ? cc : 1.0f;
      float shl = g0 ? -sh : 0.0f;
      u64 cclp = pk(ccl, ccl), shlp = pk(shl, shl);
#pragma unroll
      for (int k = 0; k < 16; ++k) {
        Cr[k] = f2mul(cclp, P[k]);
        Ci[k] = f2mul(shlp, P[k ^ 8]);
      }
    }

    // CRX(2,3): lane1 ctrl, target q3 (k bit 2).
    {
      float ccl = g1 ? cc : 1.0f;
      float shl = g1 ? sh : 0.0f;
      u64 cclp = pk(ccl, ccl), sp = pk(shl, shl), sn = pk(-shl, -shl);
#pragma unroll
      for (int k = 0; k < 16; ++k) if (!(k & 4))
        CRX_PAIR(Cr[k], Ci[k], Cr[k+4], Ci[k+4], cclp, sp, sn);
    }

    // CRX(4,5): lane2 ctrl, target q5 (k bit 1).
    {
      float ccl = g2 ? cc : 1.0f;
      float shl = g2 ? sh : 0.0f;
      u64 cclp = pk(ccl, ccl), sp = pk(shl, shl), sn = pk(-shl, -shl);
#pragma unroll
      for (int k = 0; k < 16; ++k) if (!(k & 2))
        CRX_PAIR(Cr[k], Ci[k], Cr[k+2], Ci[k+2], cclp, sp, sn);
    }

    // CRX(6,7): ctrl q6 = pack HI slot, target q7 (k bit 0): masked constants.
    {
      u64 cc_m = pk(1.0f, cc), sp_m = pk(0.0f, sh), sn_m = pk(0.0f, -sh);
#pragma unroll
      for (int k = 0; k < 16; ++k) if (!(k & 1))
        CRX_PAIR(Cr[k], Ci[k], Cr[k+1], Ci[k+1], cc_m, sp_m, sn_m);
    }

    // CRX(1,2): ctrl q1 (k bit 3), target lane1.
#pragma unroll
    for (int k = 0; k < 16; ++k) if (k & 8) {
      u64 pr = __shfl_xor_sync(FULLMASK, Cr[k], 2);
      u64 pi = __shfl_xor_sync(FULLMASK, Ci[k], 2);
      Cr[k] = f2fma(ccp, Cr[k], f2mul(shpp, pi));
      Ci[k] = f2fma(ccp, Ci[k], f2mul(shnn, pr));
    }

    // CRX(3,4): ctrl q3 (k bit 2), target lane2.
#pragma unroll
    for (int k = 0; k < 16; ++k) if (k & 4) {
      u64 pr = __shfl_xor_sync(FULLMASK, Cr[k], 4);
      u64 pi = __shfl_xor_sync(FULLMASK, Ci[k], 4);
      Cr[k] = f2fma(ccp, Cr[k], f2mul(shpp, pi));
      Ci[k] = f2fma(ccp, Ci[k], f2mul(shnn, pr));
    }

    // CRX(5,6): ctrl q5 (k bit 1), target q6 (pack axis).
#pragma unroll
    for (int k = 0; k < 16; ++k) if (k & 2) {
      u64 r = Cr[k], i = Ci[k];
      Cr[k] = f2fma(ccp, r, f2mul(shpp, swp(i)));
      Ci[k] = f2fma(ccp, i, f2mul(shnn, swp(r)));
    }

    // U3(layer 0) tan form on q1(8), q3(4), q5(2), q7(1) — all register pairs.
    float uth = u3_params[0], uph = u3_params[1], ulm = u3_params[2];
    float ct, st;  sincosf(0.5f * uth, &st, &ct);
    ct_l0 = ct;
    float tu = __fdividef(st, ct);
    float clm, slm; sincosf(ulm, &slm, &clm);
    float cph, sph; sincosf(uph, &sph, &cph);
    float cpl, spl; sincosf(uph + ulm, &spl, &cpl);
    float Ar = clm * tu, Ai = slm * tu;
    float Cc = cph * tu, Cs = sph * tu;
    float Er = cpl,      Ei = spl;
    u64 pArn = pk(-Ar, -Ar), pAip = pk(Ai, Ai), pAin = pk(-Ai, -Ai);
    u64 pCc = pk(Cc, Cc), pCsn = pk(-Cs, -Cs), pCsp = pk(Cs, Cs);
    u64 pEr = pk(Er, Er), pEin = pk(-Ei, -Ei), pEip = pk(Ei, Ei);

#pragma unroll
    for (int k = 0; k < 16; ++k) if (!(k & 8))
      U3T_PAIR(Cr[k], Ci[k], Cr[k+8], Ci[k+8]);
#pragma unroll
    for (int k = 0; k < 16; ++k) if (!(k & 4))
      U3T_PAIR(Cr[k], Ci[k], Cr[k+4], Ci[k+4]);
#pragma unroll
    for (int k = 0; k < 16; ++k) if (!(k & 2))
      U3T_PAIR(Cr[k], Ci[k], Cr[k+2], Ci[k+2]);
#pragma unroll
    for (int k = 0; k < 16; ++k) if (!(k & 1))
      U3T_PAIR(Cr[k], Ci[k], Cr[k+1], Ci[k+1]);
  }

  // --- layer 1 : fully register-local ---
  {
    float cc, sh; sincosf(0.5f * crx_theta[1], &sh, &cc);
    u64 ccp  = pk(cc, cc);
    u64 shpp = pk(sh, sh), shnn = pk(-sh, -sh);

#pragma unroll
    for (int k = 0; k < 16; ++k) if ((k & 8) && !(k & 4))     // CRX(1,3)
      CRX_PAIR(Cr[k], Ci[k], Cr[k+4], Ci[k+4], ccp, shpp, shnn);
#pragma unroll
    for (int k = 0; k < 16; ++k) if ((k & 2) && !(k & 1))     // CRX(5,7)
      CRX_PAIR(Cr[k], Ci[k], Cr[k+1], Ci[k+1], ccp, shpp, shnn);
#pragma unroll
    for (int k = 0; k < 16; ++k) if ((k & 4) && !(k & 2))     // CRX(3,5)
      CRX_PAIR(Cr[k], Ci[k], Cr[k+2], Ci[k+2], ccp, shpp, shnn);

    float uth = u3_params[3], uph = u3_params[4], ulm = u3_params[5];
    float ct, st;  sincosf(0.5f * uth, &st, &ct);
    ct_l1 = ct;
    float tu = __fdividef(st, ct);
    float clm, slm; sincosf(ulm, &slm, &clm);
    float cph, sph; sincosf(uph, &sph, &cph);
    float cpl, spl; sincosf(uph + ulm, &spl, &cpl);
    float Ar = clm * tu, Ai = slm * tu;
    float Cc = cph * tu, Cs = sph * tu;
    float Er = cpl,      Ei = spl;
    u64 pArn = pk(-Ar, -Ar), pAip = pk(Ai, Ai), pAin = pk(-Ai, -Ai);
    u64 pCc = pk(Cc, Cc), pCsn = pk(-Cs, -Cs), pCsp = pk(Cs, Cs);
    u64 pEr = pk(Er, Er), pEin = pk(-Ei, -Ei), pEip = pk(Ei, Ei);

#pragma unroll
    for (int k = 0; k < 16; ++k) if (!(k & 4))                // U3 q3
      U3T_PAIR(Cr[k], Ci[k], Cr[k+4], Ci[k+4]);
#pragma unroll
    for (int k = 0; k < 16; ++k) if (!(k & 1))                // U3 q7
      U3T_PAIR(Cr[k], Ci[k], Cr[k+1], Ci[k+1]);
  }

  // --- expval_z on q3 (k bit 2) and q7 (k bit 0) ---
  u64 acc0 = pk(0.f, 0.f), acc1 = acc0, acc2 = acc0, acc3 = acc0;
#pragma unroll
  for (int k = 0; k < 16; ++k) {
    u64 pp = f2fma(Cr[k], Cr[k], f2mul(Ci[k], Ci[k]));
    int idx = ((k & 4) ? 2 : 0) | (k & 1);
    if      (idx == 0) acc0 = f2add(acc0, pp);
    else if (idx == 1) acc1 = f2add(acc1, pp);
    else if (idx == 2) acc2 = f2add(acc2, pp);
    else               acc3 = f2add(acc3, pp);
  }
  float l, h, s0, s1, s2, s3;
  unpk(acc0, l, h); s0 = l + h;
  unpk(acc1, l, h); s1 = l + h;
  unpk(acc2, l, h); s2 = l + h;
  unpk(acc3, l, h); s3 = l + h;
  float z3 = (s0 + s1) - (s2 + s3);
  float z7 = (s0 + s2) - (s1 + s3);

  z3 += __shfl_xor_sync(FULLMASK, z3, 1);
  z3 += __shfl_xor_sync(FULLMASK, z3, 2);
  z3 += __shfl_xor_sync(FULLMASK, z3, 4);
  z7 += __shfl_xor_sync(FULLMASK, z7, 1);
  z7 += __shfl_xor_sync(FULLMASK, z7, 2);
  z7 += __shfl_xor_sync(FULLMASK, z7, 4);

  // --- MLP head (apply deferred U3 scale G^2, G = ct0^4 * ct1^2) ---
  if (g == 0) {
    float ct0sq = ct_l0 * ct_l0;
    float Gs = ct0sq * ct0sq * ct_l1 * ct_l1;
    float G2 = Gs * Gs;
    z3 *= G2;
    z7 *= G2;
    float o = b2[0];
#pragma unroll
    for (int j = 0; j < 10; ++j) {
      float hh = tanhf(z3 * w1[j] + z7 * w1[10 + j] + b1[j]);
      o += hh * w2[j];
    }
    out[elem] = 1.0f / (1.0f + expf(-o));
  }
}

extern "C" void kernel_launch(void* const* d_in, const int* in_sizes, int n_in,
                              void* d_out, int out_size) {
  const float* x   = (const float*)d_in[0];
  const float* crx = (const float*)d_in[1];
  const float* u3p = (const float*)d_in[2];
  const float* w1  = (const float*)d_in[3];
  const float* b1  = (const float*)d_in[4];
  const float* w2  = (const float*)d_in[5];
  const float* b2  = (const float*)d_in[6];
  float* out = (float*)d_out;

  int B = in_sizes[0] / 8;
  int threads = B * 8;
  int block = 128;
  int grid = (threads + block - 1) / block;
  qcnn_kernel<<<grid, block>>>(x, crx, u3p, w1, b1, w2, b2, out, B);
}

// round 10
// speedup vs baseline: 2.9310x; 1.0276x over previous
#include <cuda_runtime.h>
#include <math.h>

#define FULLMASK 0xffffffffu
typedef unsigned long long u64;

// ---- packed f32x2 primitives (sm_103a; ptxas won't emit these from C++) ----
__device__ __forceinline__ u64 pk(float lo, float hi) {
  u64 r; asm("mov.b64 %0, {%1,%2};" : "=l"(r) : "f"(lo), "f"(hi)); return r;
}
__device__ __forceinline__ void unpk(u64 v, float& lo, float& hi) {
  asm("mov.b64 {%0,%1}, %2;" : "=f"(lo), "=f"(hi) : "l"(v));
}
__device__ __forceinline__ u64 swp(u64 v) {
  float l, h; unpk(v, l, h); return pk(h, l);
}
__device__ __forceinline__ u64 f2fma(u64 a, u64 b, u64 c) {
  u64 d; asm("fma.rn.f32x2 %0, %1, %2, %3;" : "=l"(d) : "l"(a), "l"(b), "l"(c)); return d;
}
__device__ __forceinline__ u64 f2mul(u64 a, u64 b) {
  u64 d; asm("mul.rn.f32x2 %0, %1, %2;" : "=l"(d) : "l"(a), "l"(b)); return d;
}
__device__ __forceinline__ u64 f2add(u64 a, u64 b) {
  u64 d; asm("add.rn.f32x2 %0, %1, %2;" : "=l"(d) : "l"(a), "l"(b)); return d;
}

// ---------------------------------------------------------------------------
// Layout: 8 lanes per element (g = tid&7).
// Lane bits: q0 -> xor 1, q2 -> xor 2, q4 -> xor 4.  PACK AXIS: q6.
// k index: bit3=q1(8), bit2=q3(4), bit1=q5(2), bit0=q7(1).
// CYCLE PHASE (real): tan-form RY, cos deferred into seed^3 (validated R6-R8).
// LAYER PHASE: tan-form CRX with cos weights routed correctly:
//   q0 ctrl  -> lane weight at expval
//   q1/q3/q5 ctrl (L0) -> absorbed into that qubit's U3 column (A,E *= c0)
//   q2/q4 ctrl -> ratio-adjusted th in CRX(1,2)/(3,4), lane weight at expval
//   q6 ctrl  -> slot-adjusted th in CRX(5,6), hi-slot c0^2 fold at expval
//   L1: q1 -> expval c1^2 (k&8); q5 -> split-th CRX(3,5), expval c1^2 (k&2);
//       q3 -> absorbed into U3(q3) L1 column (A,E *= c1)
// U3 tan form, ct deferred via G^2 (unchanged).
// ---------------------------------------------------------------------------

template<int TMk>
__device__ __forceinline__ void ry_reg_t(u64 (&P)[16], u64 tt, u64 ttn) {
#pragma unroll
  for (int k = 0; k < 16; ++k) if (!(k & TMk)) {
    u64 A = P[k], B = P[k + TMk];
    P[k]       = f2fma(ttn, B, A);
    P[k + TMk] = f2fma(tt, A, B);
  }
}

template<int LM, int KM>
__device__ __forceinline__ void ry_lane_cnot_t(u64 (&P)[16], u64 tgg, u64 tggn) {
#pragma unroll
  for (int k = 0; k < 16; ++k) {
    u64 p = __shfl_xor_sync(FULLMASK, P[k], LM);
    if (k & KM) P[k] = f2fma(tggn, P[k], p);
    else        P[k] = f2fma(tgg, p, P[k]);
  }
}

template<int LM, int KM>
__device__ __forceinline__ void cnot_ry_lane_t(u64 (&P)[16], u64 tgg) {
#pragma unroll
  for (int k = 0; k < 16; ++k) {
    u64 p = __shfl_xor_sync(FULLMASK, P[k], LM);
    if (k & KM) P[k] = f2fma(tgg, P[k], p);
    else        P[k] = f2fma(tgg, p, P[k]);
  }
}

template<int TMk>
__device__ __forceinline__ void condswap(u64 (&P)[16], bool f) {
#pragma unroll
  for (int k = 0; k < 16; ++k) if (!(k & TMk)) {
    u64 A = P[k], B = P[k + TMk];
    P[k]       = f ? B : A;
    P[k + TMk] = f ? A : B;
  }
}

// Fused RY(q6, pack) + CNOT(ctrl q5 = k bit 1, target q6).
__device__ __forceinline__ void ry_pack_cnot56(u64 (&P)[16], u64 t6pm, u64 t6mp) {
#pragma unroll
  for (int k = 0; k < 16; ++k) {
    if (k & 2) P[k] = f2fma(t6mp, P[k], swp(P[k]));
    else       P[k] = f2fma(t6pm, swp(P[k]), P[k]);
  }
}

// Fused RY(q7 = k bit 0) + CNOT(ctrl q6 = pack hi, target q7).
__device__ __forceinline__ void ry_q7_cnot67(u64 (&P)[16], u64 tt7, u64 tn7) {
#pragma unroll
  for (int k = 0; k < 16; k += 2) {
    u64 A = P[k], B = P[k + 1];
    u64 X = f2fma(tn7, B, A);
    u64 Y = f2fma(tt7, A, B);
    float xl, xh, yl, yh;
    unpk(X, xl, xh); unpk(Y, yl, yh);
    P[k]     = pk(xl, yh);
    P[k + 1] = pk(yl, xh);
  }
}

// tan-form CRX pair on register target: 4 FMAs (cos deferred).
#define CRXT_PAIR(Cr0, Ci0, Cr1, Ci1, thp, thn)                     \
  {                                                                 \
    u64 _r0 = (Cr0), _i0 = (Ci0), _r1 = (Cr1), _i1 = (Ci1);         \
    (Cr0) = f2fma((thp), _i1, _r0);                                 \
    (Ci0) = f2fma((thn), _r1, _i0);                                 \
    (Cr1) = f2fma((thp), _i0, _r1);                                 \
    (Ci1) = f2fma((thn), _r0, _i1);                                 \
  }

// tan-form CRX pair with DIFFERENT th per output (weight-ratio corrected).
#define CRXT_PAIR2(Cr0, Ci0, Cr1, Ci1, tup, tun, tdp, tdn)          \
  {                                                                 \
    u64 _r0 = (Cr0), _i0 = (Ci0), _r1 = (Cr1), _i1 = (Ci1);         \
    (Cr0) = f2fma((tup), _i1, _r0);                                 \
    (Ci0) = f2fma((tun), _r1, _i0);                                 \
    (Cr1) = f2fma((tdp), _i0, _r1);                                 \
    (Ci1) = f2fma((tdn), _r0, _i1);                                 \
  }

// U3 pair in tan form; constants passed explicitly (scaled vs unscaled sets).
#define U3T_PAIR(Cr0, Ci0, Cr1, Ci1, Arn, Aip, Ain, Cc_, Csn, Csp, Er_, Ein, Eip) \
  {                                                                             \
    u64 _r0 = (Cr0), _i0 = (Ci0), _r1 = (Cr1), _i1 = (Ci1);                     \
    (Cr0) = f2fma(Arn, _r1, f2fma(Aip, _i1, _r0));                              \
    (Ci0) = f2fma(Arn, _i1, f2fma(Ain, _r1, _i0));                              \
    (Cr1) = f2fma(Cc_, _r0, f2fma(Csn, _i0, f2fma(Er_, _r1, f2mul(Ein, _i1)))); \
    (Ci1) = f2fma(Cc_, _i0, f2fma(Csp, _r0, f2fma(Er_, _i1, f2mul(Eip, _r1)))); \
  }

__global__ void __launch_bounds__(128, 5)
qcnn_kernel(const float* __restrict__ x,
            const float* __restrict__ crx_theta,
            const float* __restrict__ u3_params,
            const float* __restrict__ w1,
            const float* __restrict__ b1,
            const float* __restrict__ w2,
            const float* __restrict__ b2,
            float* __restrict__ out, int B)
{
  int tid  = blockIdx.x * blockDim.x + threadIdx.x;
  int elem = tid >> 3;
  if (elem >= B) return;
  int g = tid & 7;
  bool g0 = (g & 1) != 0;
  bool g1 = (g & 2) != 0;
  bool g2 = (g & 4) != 0;

  // --- angles ---
  float myx = x[elem * 8 + g];
  float ms, mc;
  sincosf(0.5f * myx, &ms, &mc);
  float mt = __fdividef(ms, mc);

  float tq[8];
#pragma unroll
  for (int q = 0; q < 8; ++q) tq[q] = __shfl_sync(FULLMASK, mt, q, 8);

  u64 P[16];
  {
    float cq[8], sq[8];
#pragma unroll
    for (int q = 0; q < 8; ++q) {
      cq[q] = __shfl_sync(FULLMASK, mc, q, 8);
      sq[q] = __shfl_sync(FULLMASK, ms, q, 8);
    }
    float cprod = cq[0]*cq[1]*cq[2]*cq[3]*cq[4]*cq[5]*cq[6]*cq[7];
    float F = cprod * cprod * cprod;

    float b[16];
    b[0] = F * (g0 ? sq[0] : cq[0]) * (g1 ? sq[2] : cq[2]) * (g2 ? sq[4] : cq[4]);
#pragma unroll
    for (int i = 0; i < 1; ++i) { b[i+1] = b[i]*sq[7]; b[i] *= cq[7]; }
#pragma unroll
    for (int i = 0; i < 2; ++i) { b[i+2] = b[i]*sq[5]; b[i] *= cq[5]; }
#pragma unroll
    for (int i = 0; i < 4; ++i) { b[i+4] = b[i]*sq[3]; b[i] *= cq[3]; }
#pragma unroll
    for (int i = 0; i < 8; ++i) { b[i+8] = b[i]*sq[1]; b[i] *= cq[1]; }

    u64 c6s6 = pk(cq[6], sq[6]);
#pragma unroll
    for (int k = 0; k < 16; ++k) P[k] = f2mul(pk(b[k], b[k]), c6s6);
  }

  float tg0 = g0 ? tq[0] : -tq[0];
  float tg2 = g1 ? tq[2] : -tq[2];
  float tg4 = g2 ? tq[4] : -tq[4];

  // cycle 1 CNOT ring (0,1)..(6,7); (7,0) deferred into cycle 2's RY q0.
  condswap<8>(P, g0);
#pragma unroll
  for (int k = 0; k < 16; ++k) if (k & 8)
    P[k] = __shfl_xor_sync(FULLMASK, P[k], 2);
  condswap<4>(P, g1);
#pragma unroll
  for (int k = 0; k < 16; ++k) if (k & 4)
    P[k] = __shfl_xor_sync(FULLMASK, P[k], 4);
  condswap<2>(P, g2);
#pragma unroll
  for (int k = 0; k < 16; ++k) if (k & 2)
    P[k] = swp(P[k]);
#pragma unroll
  for (int k = 0; k < 16; k += 2) {
    float l0, h0, l1, h1;
    unpk(P[k], l0, h0); unpk(P[k+1], l1, h1);
    P[k] = pk(l0, h1); P[k+1] = pk(l1, h0);
  }

  // --- cycles 2..4 (tan form, fused — validated identities) ---
  {
    u64 tgg0 = pk(tg0, tg0);
    u64 tt1 = pk(tq[1], tq[1]), tn1 = pk(-tq[1], -tq[1]);
    u64 tt3 = pk(tq[3], tq[3]), tn3 = pk(-tq[3], -tq[3]);
    u64 tt5 = pk(tq[5], tq[5]), tn5 = pk(-tq[5], -tq[5]);
    u64 tt7 = pk(tq[7], tq[7]), tn7 = pk(-tq[7], -tq[7]);
    u64 t6pm = pk(-tq[6], tq[6]), t6mp = pk(tq[6], -tq[6]);
    u64 tgg2 = pk(tg2, tg2), tgg2n = pk(-tg2, -tg2);
    u64 tgg4 = pk(tg4, tg4), tgg4n = pk(-tg4, -tg4);

#pragma unroll
    for (int cy = 0; cy < 3; ++cy) {
      cnot_ry_lane_t<1, 1>(P, tgg0);               // CNOT(7,0)[prev] + RY q0
      ry_reg_t<8>(P, tt1, tn1);                    // RY q1
      condswap<8>(P, g0);                          // CNOT(0,1)
      ry_lane_cnot_t<2, 8>(P, tgg2, tgg2n);        // RY q2 + CNOT(1,2)
      ry_reg_t<4>(P, tt3, tn3);                    // RY q3
      condswap<4>(P, g1);                          // CNOT(2,3)
      ry_lane_cnot_t<4, 4>(P, tgg4, tgg4n);        // RY q4 + CNOT(3,4)
      ry_reg_t<2>(P, tt5, tn5);                    // RY q5
      condswap<2>(P, g2);                          // CNOT(4,5)
      ry_pack_cnot56(P, t6pm, t6mp);               // RY q6 + CNOT(5,6)
      ry_q7_cnot67(P, tt7, tn7);                   // RY q7 + CNOT(6,7)
    }
  }

  // final standalone CNOT(7,0)
#pragma unroll
  for (int k = 0; k < 16; ++k) if (k & 1)
    P[k] = __shfl_xor_sync(FULLMASK, P[k], 1);

  // =================== LAYER PHASE =========================================
  u64 Cr[16], Ci[16];
  float ct_l0, ct_l1, c0, c1;

  // --- layer 0 ---
  {
    float cc, sh; sincosf(0.5f * crx_theta[0], &sh, &cc);
    c0 = cc;
    float t0 = __fdividef(sh, cc);
    float t0u = sh;                          // t0 * c0 (exact)
    float t0d = __fdividef(sh, cc * cc);     // t0 / c0

    // CRX(0,1) on REAL state (tan): weight c0^[g0] per lane -> expval.
    {
      float thl = g0 ? -t0 : 0.0f;
      u64 thlp = pk(thl, thl);
#pragma unroll
      for (int k = 0; k < 16; ++k) {
        Cr[k] = P[k];
        Ci[k] = f2mul(thlp, P[k ^ 8]);
      }
    }

    // CRX(2,3): lane1 ctrl (tan), weight c0^[g1] per lane -> expval.
    {
      float thl = g1 ? t0 : 0.0f;
      u64 tp = pk(thl, thl), tn = pk(-thl, -thl);
#pragma unroll
      for (int k = 0; k < 16; ++k) if (!(k & 4))
        CRXT_PAIR(Cr[k], Ci[k], Cr[k+4], Ci[k+4], tp, tn);
    }

    // CRX(4,5): lane2 ctrl (tan), weight c0^[g2] per lane -> expval.
    {
      float thl = g2 ? t0 : 0.0f;
      u64 tp = pk(thl, thl), tn = pk(-thl, -thl);
#pragma unroll
      for (int k = 0; k < 16; ++k) if (!(k & 2))
        CRXT_PAIR(Cr[k], Ci[k], Cr[k+2], Ci[k+2], tp, tn);
    }

    // CRX(6,7): pack-hi ctrl (tan, masked), weight (1,c0) on pack -> expval fold.
    {
      u64 tp = pk(0.0f, t0), tn = pk(0.0f, -t0);
#pragma unroll
      for (int k = 0; k < 16; ++k) if (!(k & 1))
        CRXT_PAIR(Cr[k], Ci[k], Cr[k+1], Ci[k+1], tp, tn);
    }

    // CRX(1,2): ctrl q1 (k&8), target lane1. Ratio-adjusted th (q2 weight):
    // th = g1 ? t0/c0 : t0*c0.  Creates q1 weight -> absorbed in U3(q1).
    {
      float th12 = g1 ? t0d : t0u;
      u64 tp = pk(th12, th12), tn = pk(-th12, -th12);
#pragma unroll
      for (int k = 0; k < 16; ++k) if (k & 8) {
        u64 pr = __shfl_xor_sync(FULLMASK, Cr[k], 2);
        u64 pi = __shfl_xor_sync(FULLMASK, Ci[k], 2);
        Cr[k] = f2fma(tp, pi, Cr[k]);
        Ci[k] = f2fma(tn, pr, Ci[k]);
      }
    }

    // CRX(3,4): ctrl q3 (k&4), target lane2. Ratio-adjusted th (q4 weight):
    // th = g2 ? t0/c0 : t0*c0.  Creates q3 weight -> absorbed in U3(q3).
    {
      float th34 = g2 ? t0d : t0u;
      u64 tp = pk(th34, th34), tn = pk(-th34, -th34);
#pragma unroll
      for (int k = 0; k < 16; ++k) if (k & 4) {
        u64 pr = __shfl_xor_sync(FULLMASK, Cr[k], 4);
        u64 pi = __shfl_xor_sync(FULLMASK, Ci[k], 4);
        Cr[k] = f2fma(tp, pi, Cr[k]);
        Ci[k] = f2fma(tn, pr, Ci[k]);
      }
    }

    // CRX(5,6): ctrl q5 (k&2), target q6 (pack). Slot-adjusted th for the
    // outstanding (1,c0) q6 weight: th = (t0*c0, t0/c0).
    // Creates q5 weight -> absorbed in U3(q5).
    {
      u64 tp = pk(t0u, t0d), tn = pk(-t0u, -t0d);
#pragma unroll
      for (int k = 0; k < 16; ++k) if (k & 2) {
        u64 r = Cr[k], i = Ci[k];
        Cr[k] = f2fma(tp, swp(i), r);
        Ci[k] = f2fma(tn, swp(r), i);
      }
    }

    // U3(layer 0), tan form. q1/q3/q5 use c0-scaled v1-column (absorbs their
    // CRX control weights); q7 unscaled.
    float uth = u3_params[0], uph = u3_params[1], ulm = u3_params[2];
    float ct, st;  sincosf(0.5f * uth, &st, &ct);
    ct_l0 = ct;
    float tu = __fdividef(st, ct);
    float clm, slm; sincosf(ulm, &slm, &clm);
    float cph, sph; sincosf(uph, &sph, &cph);
    float cpl, spl; sincosf(uph + ulm, &spl, &cpl);
    float Ar = clm * tu, Ai = slm * tu;
    float Cc = cph * tu, Cs = sph * tu;
    float Er = cpl,      Ei = spl;
    u64 pCc = pk(Cc, Cc), pCsn = pk(-Cs, -Cs), pCsp = pk(Cs, Cs);
    {
      float Ars = Ar * c0, Ais = Ai * c0, Ers = Er * c0, Eis = Ei * c0;
      u64 sArn = pk(-Ars, -Ars), sAip = pk(Ais, Ais), sAin = pk(-Ais, -Ais);
      u64 sEr = pk(Ers, Ers), sEin = pk(-Eis, -Eis), sEip = pk(Eis, Eis);
#pragma unroll
      for (int k = 0; k < 16; ++k) if (!(k & 8))
        U3T_PAIR(Cr[k], Ci[k], Cr[k+8], Ci[k+8],
                 sArn, sAip, sAin, pCc, pCsn, pCsp, sEr, sEin, sEip);
#pragma unroll
      for (int k = 0; k < 16; ++k) if (!(k & 4))
        U3T_PAIR(Cr[k], Ci[k], Cr[k+4], Ci[k+4],
                 sArn, sAip, sAin, pCc, pCsn, pCsp, sEr, sEin, sEip);
#pragma unroll
      for (int k = 0; k < 16; ++k) if (!(k & 2))
        U3T_PAIR(Cr[k], Ci[k], Cr[k+2], Ci[k+2],
                 sArn, sAip, sAin, pCc, pCsn, pCsp, sEr, sEin, sEip);
    }
    {
      u64 uArn = pk(-Ar, -Ar), uAip = pk(Ai, Ai), uAin = pk(-Ai, -Ai);
      u64 uEr = pk(Er, Er), uEin = pk(-Ei, -Ei), uEip = pk(Ei, Ei);
#pragma unroll
      for (int k = 0; k < 16; ++k) if (!(k & 1))
        U3T_PAIR(Cr[k], Ci[k], Cr[k+1], Ci[k+1],
                 uArn, uAip, uAin, pCc, pCsn, pCsp, uEr, uEin, uEip);
    }
  }

  // --- layer 1 ---
  {
    float cc, sh; sincosf(0.5f * crx_theta[1], &sh, &cc);
    c1 = cc;
    float t1 = __fdividef(sh, cc);
    float t1u = sh;                          // t1 * c1 (exact)
    float t1d = __fdividef(sh, cc * cc);     // t1 / c1
    u64 tp = pk(t1, t1), tn = pk(-t1, -t1);

    // CRX(1,3): ctrl q1 (tan). Weight c1 on k&8 -> expval.
#pragma unroll
    for (int k = 0; k < 16; ++k) if ((k & 8) && !(k & 4))
      CRXT_PAIR(Cr[k], Ci[k], Cr[k+4], Ci[k+4], tp, tn);

    // CRX(5,7): ctrl q5 (tan). Weight c1 on k&2 -> survives (3,5) -> expval.
#pragma unroll
    for (int k = 0; k < 16; ++k) if ((k & 2) && !(k & 1))
      CRXT_PAIR(Cr[k], Ci[k], Cr[k+1], Ci[k+1], tp, tn);

    // CRX(3,5): ctrl q3, target q5. Split th corrects for q5 weight c1:
    // v0 (q5=0) update uses t1*c1; v1 (q5=1) update uses t1/c1.
    // Creates q3 weight c1 -> absorbed in U3(q3) below.
    {
      u64 tup = pk(t1u, t1u), tun = pk(-t1u, -t1u);
      u64 tdp = pk(t1d, t1d), tdn = pk(-t1d, -t1d);
#pragma unroll
      for (int k = 0; k < 16; ++k) if ((k & 4) && !(k & 2))
        CRXT_PAIR2(Cr[k], Ci[k], Cr[k+2], Ci[k+2], tup, tun, tdp, tdn);
    }

    float uth = u3_params[3], uph = u3_params[4], ulm = u3_params[5];
    float ct, st;  sincosf(0.5f * uth, &st, &ct);
    ct_l1 = ct;
    float tu = __fdividef(st, ct);
    float clm, slm; sincosf(ulm, &slm, &clm);
    float cph, sph; sincosf(uph, &sph, &cph);
    float cpl, spl; sincosf(uph + ulm, &spl, &cpl);
    float Ar = clm * tu, Ai = slm * tu;
    float Cc = cph * tu, Cs = sph * tu;
    float Er = cpl,      Ei = spl;
    u64 pCc = pk(Cc, Cc), pCsn = pk(-Cs, -Cs), pCsp = pk(Cs, Cs);
    {
      // U3(q3): c1-scaled column absorbs CRX(3,5) control weight.
      float Ars = Ar * c1, Ais = Ai * c1, Ers = Er * c1, Eis = Ei * c1;
      u64 sArn = pk(-Ars, -Ars), sAip = pk(Ais, Ais), sAin = pk(-Ais, -Ais);
      u64 sEr = pk(Ers, Ers), sEin = pk(-Eis, -Eis), sEip = pk(Eis, Eis);
#pragma unroll
      for (int k = 0; k < 16; ++k) if (!(k & 4))
        U3T_PAIR(Cr[k], Ci[k], Cr[k+4], Ci[k+4],
                 sArn, sAip, sAin, pCc, pCsn, pCsp, sEr, sEin, sEip);
    }
    {
      // U3(q7): unscaled.
      u64 uArn = pk(-Ar, -Ar), uAip = pk(Ai, Ai), uAin = pk(-Ai, -Ai);
      u64 uEr = pk(Er, Er), uEin = pk(-Ei, -Ei), uEip = pk(Ei, Ei);
#pragma unroll
      for (int k = 0; k < 16; ++k) if (!(k & 1))
        U3T_PAIR(Cr[k], Ci[k], Cr[k+1], Ci[k+1],
                 uArn, uAip, uAin, pCc, pCsn, pCsp, uEr, uEin, uEip);
    }
  }

  // --- expval with deferred weights ---
  // per-k: c1^2 for each of [k&8] (q1, L1 CRX(1,3)) and [k&2] (q5, L1 CRX(5,7))
  float c1sq = c1 * c1;
  float c1q  = c1sq * c1sq;
  u64 pc2 = pk(c1sq, c1sq), pc4 = pk(c1q, c1q);

  u64 acc0 = pk(0.f, 0.f), acc1 = acc0, acc2 = acc0, acc3 = acc0;
#pragma unroll
  for (int k = 0; k < 16; ++k) {
    u64 pp = f2fma(Cr[k], Cr[k], f2mul(Ci[k], Ci[k]));
    const int nb = ((k >> 3) & 1) + ((k >> 1) & 1);
    if (nb == 1)      pp = f2mul(pp, pc2);
    else if (nb == 2) pp = f2mul(pp, pc4);
    int idx = ((k & 4) ? 2 : 0) | (k & 1);
    if      (idx == 0) acc0 = f2add(acc0, pp);
    else if (idx == 1) acc1 = f2add(acc1, pp);
    else if (idx == 2) acc2 = f2add(acc2, pp);
    else               acc3 = f2add(acc3, pp);
  }
  // pack-hi weight c0^2 (q6, from CRX(6,7)) folded into lo+hi sums
  float c02 = c0 * c0;
  float l, h, s0, s1, s2, s3;
  unpk(acc0, l, h); s0 = fmaf(c02, h, l);
  unpk(acc1, l, h); s1 = fmaf(c02, h, l);
  unpk(acc2, l, h); s2 = fmaf(c02, h, l);
  unpk(acc3, l, h); s3 = fmaf(c02, h, l);
  float z3 = (s0 + s1) - (s2 + s3);
  float z7 = (s0 + s2) - (s1 + s3);

  // per-lane weight c0^{2*popcount(g)} (q0/q2/q4 controls), pre-reduction
  {
    float lw2 = 1.0f;
    if (g0) lw2 *= c02;
    if (g1) lw2 *= c02;
    if (g2) lw2 *= c02;
    z3 *= lw2;
    z7 *= lw2;
  }

  z3 += __shfl_xor_sync(FULLMASK, z3, 1);
  z3 += __shfl_xor_sync(FULLMASK, z3, 2);
  z3 += __shfl_xor_sync(FULLMASK, z3, 4);
  z7 += __shfl_xor_sync(FULLMASK, z7, 1);
  z7 += __shfl_xor_sync(FULLMASK, z7, 2);
  z7 += __shfl_xor_sync(FULLMASK, z7, 4);

  // --- MLP head (deferred U3 scale G^2, G = ct0^4 * ct1^2) ---
  if (g == 0) {
    float ct0sq = ct_l0 * ct_l0;
    float Gs = ct0sq * ct0sq * ct_l1 * ct_l1;
    float G2 = Gs * Gs;
    z3 *= G2;
    z7 *= G2;
    float o = b2[0];
#pragma unroll
    for (int j = 0; j < 10; ++j) {
      float hh = tanhf(z3 * w1[j] + z7 * w1[10 + j] + b1[j]);
      o += hh * w2[j];
    }
    out[elem] = 1.0f / (1.0f + expf(-o));
  }
}

extern "C" void kernel_launch(void* const* d_in, const int* in_sizes, int n_in,
                              void* d_out, int out_size) {
  const float* x   = (const float*)d_in[0];
  const float* crx = (const float*)d_in[1];
  const float* u3p = (const float*)d_in[2];
  const float* w1  = (const float*)d_in[3];
  const float* b1  = (const float*)d_in[4];
  const float* w2  = (const float*)d_in[5];
  const float* b2  = (const float*)d_in[6];
  float* out = (float*)d_out;

  int B = in_sizes[0] / 8;
  int threads = B * 8;
  int block = 128;
  int grid = (threads + block - 1) / block;
  qcnn_kernel<<<grid, block>>>(x, crx, u3p, w1, b1, w2, b2, out, B);
}

// round 14
// speedup vs baseline: 3.1022x; 1.0584x over previous
#include <cuda_runtime.h>
#include <math.h>

#define FULLMASK 0xffffffffu
typedef unsigned long long u64;

// ---- packed f32x2 primitives (sm_103a; ptxas won't emit these from C++) ----
__device__ __forceinline__ u64 pk(float lo, float hi) {
  u64 r; asm("mov.b64 %0, {%1,%2};" : "=l"(r) : "f"(lo), "f"(hi)); return r;
}
__device__ __forceinline__ void unpk(u64 v, float& lo, float& hi) {
  asm("mov.b64 {%0,%1}, %2;" : "=f"(lo), "=f"(hi) : "l"(v));
}
__device__ __forceinline__ u64 f2fma(u64 a, u64 b, u64 c) {
  u64 d; asm("fma.rn.f32x2 %0, %1, %2, %3;" : "=l"(d) : "l"(a), "l"(b), "l"(c)); return d;
}
__device__ __forceinline__ u64 f2mul(u64 a, u64 b) {
  u64 d; asm("mul.rn.f32x2 %0, %1, %2;" : "=l"(d) : "l"(a), "l"(b)); return d;
}
__device__ __forceinline__ u64 f2add(u64 a, u64 b) {
  u64 d; asm("add.rn.f32x2 %0, %1, %2;" : "=l"(d) : "l"(a), "l"(b)); return d;
}

// ---------------------------------------------------------------------------
// Layout: 8 lanes per element (g = tid&7).
// Lane bits: q0 -> xor 1, q2 -> xor 2, q4 -> xor 4.  PACK AXIS: q6.
// k index: bit3=q1(8), bit2=q3(4), bit1=q5(2), bit0=q7(1).
// Same algebra as R10 (passing). New here: SEL/MOV elimination:
//  - RY(reg axis)+laneCNOT fused via 4-const form (no condswap SELs)
//  - cycle-1 condswap<8> folded into the doubling factor choice
//  - cross-slot ops (pack56, q7cnot67, CRX(5,6), cycle-1 (5,6)(6,7))
//    scalarized (no swp MOVs)
// ---------------------------------------------------------------------------

// Fused RY(tan t, reg axis TMk) + conditional pair swap (lane flag folded
// into the 4 constants): slot0 = a*A + b*B ; slot1 = c*A + d*B.
template<int TMk>
__device__ __forceinline__ void ry_cnot_reg(u64 (&P)[16], u64 pa, u64 pb, u64 pg, u64 pd) {
#pragma unroll
  for (int k = 0; k < 16; ++k) if (!(k & TMk)) {
    u64 A = P[k], B = P[k + TMk];
    P[k]       = f2fma(pa, A, f2mul(pb, B));
    P[k + TMk] = f2fma(pg, A, f2mul(pd, B));
  }
}

template<int LM, int KM>
__device__ __forceinline__ void ry_lane_cnot_t(u64 (&P)[16], u64 tgg, u64 tggn) {
#pragma unroll
  for (int k = 0; k < 16; ++k) {
    u64 p = __shfl_xor_sync(FULLMASK, P[k], LM);
    if (k & KM) P[k] = f2fma(tggn, P[k], p);
    else        P[k] = f2fma(tgg, p, P[k]);
  }
}

template<int LM, int KM>
__device__ __forceinline__ void cnot_ry_lane_t(u64 (&P)[16], u64 tgg) {
#pragma unroll
  for (int k = 0; k < 16; ++k) {
    u64 p = __shfl_xor_sync(FULLMASK, P[k], LM);
    if (k & KM) P[k] = f2fma(tgg, P[k], p);
    else        P[k] = f2fma(tgg, p, P[k]);
  }
}

template<int TMk>
__device__ __forceinline__ void condswap(u64 (&P)[16], bool f) {
#pragma unroll
  for (int k = 0; k < 16; ++k) if (!(k & TMk)) {
    u64 A = P[k], B = P[k + TMk];
    P[k]       = f ? B : A;
    P[k + TMk] = f ? A : B;
  }
}

// Fused RY(q6, pack, tan t6) + CNOT(ctrl q5 = k bit 1, target q6), SCALAR:
// a = l - t6*h ; b = h + t6*l ; ctrl slots store (b,a), others (a,b).
__device__ __forceinline__ void ry_pack_cnot56_s(u64 (&P)[16], float t6) {
#pragma unroll
  for (int k = 0; k < 16; ++k) {
    float l, h; unpk(P[k], l, h);
    float a = fmaf(-t6, h, l);
    float b = fmaf(t6, l, h);
    P[k] = (k & 2) ? pk(b, a) : pk(a, b);
  }
}

// Fused RY(q7 = k bit 0, tan t7) + CNOT(ctrl q6 = pack hi, target q7), SCALAR:
// X = A - t7*B -> slot k, Y = B + t7*A -> slot k+1, with hi halves exchanged.
__device__ __forceinline__ void ry_q7_cnot67_s(u64 (&P)[16], float t7) {
#pragma unroll
  for (int k = 0; k < 16; k += 2) {
    float al, ah, bl, bh;
    unpk(P[k], al, ah); unpk(P[k + 1], bl, bh);
    float xl = fmaf(-t7, bl, al);
    float xh = fmaf(-t7, bh, ah);
    float yl = fmaf(t7, al, bl);
    float yh = fmaf(t7, ah, bh);
    P[k]     = pk(xl, yh);
    P[k + 1] = pk(yl, xh);
  }
}

// tan-form CRX pair on register target: 4 FMAs (cos deferred).
#define CRXT_PAIR(Cr0, Ci0, Cr1, Ci1, thp, thn)                     \
  {                                                                 \
    u64 _r0 = (Cr0), _i0 = (Ci0), _r1 = (Cr1), _i1 = (Ci1);         \
    (Cr0) = f2fma((thp), _i1, _r0);                                 \
    (Ci0) = f2fma((thn), _r1, _i0);                                 \
    (Cr1) = f2fma((thp), _i0, _r1);                                 \
    (Ci1) = f2fma((thn), _r0, _i1);                                 \
  }

// tan-form CRX pair with DIFFERENT th per output (weight-ratio corrected).
#define CRXT_PAIR2(Cr0, Ci0, Cr1, Ci1, tup, tun, tdp, tdn)          \
  {                                                                 \
    u64 _r0 = (Cr0), _i0 = (Ci0), _r1 = (Cr1), _i1 = (Ci1);         \
    (Cr0) = f2fma((tup), _i1, _r0);                                 \
    (Ci0) = f2fma((tun), _r1, _i0);                                 \
    (Cr1) = f2fma((tdp), _i0, _r1);                                 \
    (Ci1) = f2fma((tdn), _r0, _i1);                                 \
  }

// U3 pair in tan form; constants passed explicitly (scaled vs unscaled sets).
#define U3T_PAIR(Cr0, Ci0, Cr1, Ci1, Arn, Aip, Ain, Cc_, Csn, Csp, Er_, Ein, Eip) \
  {                                                                             \
    u64 _r0 = (Cr0), _i0 = (Ci0), _r1 = (Cr1), _i1 = (Ci1);                     \
    (Cr0) = f2fma(Arn, _r1, f2fma(Aip, _i1, _r0));                              \
    (Ci0) = f2fma(Arn, _i1, f2fma(Ain, _r1, _i0));                              \
    (Cr1) = f2fma(Cc_, _r0, f2fma(Csn, _i0, f2fma(Er_, _r1, f2mul(Ein, _i1)))); \
    (Ci1) = f2fma(Cc_, _i0, f2fma(Csp, _r0, f2fma(Er_, _i1, f2mul(Eip, _r1)))); \
  }

__global__ void __launch_bounds__(128, 5)
qcnn_kernel(const float* __restrict__ x,
            const float* __restrict__ crx_theta,
            const float* __restrict__ u3_params,
            const float* __restrict__ w1,
            const float* __restrict__ b1,
            const float* __restrict__ w2,
            const float* __restrict__ b2,
            float* __restrict__ out, int B)
{
  int tid  = blockIdx.x * blockDim.x + threadIdx.x;
  int elem = tid >> 3;
  if (elem >= B) return;
  int g = tid & 7;
  bool g0 = (g & 1) != 0;
  bool g1 = (g & 2) != 0;
  bool g2 = (g & 4) != 0;

  // --- angles ---
  float myx = x[elem * 8 + g];
  float ms, mc;
  sincosf(0.5f * myx, &ms, &mc);
  float mt = __fdividef(ms, mc);

  float tq[8];
#pragma unroll
  for (int q = 0; q < 8; ++q) tq[q] = __shfl_sync(FULLMASK, mt, q, 8);

  u64 P[16];
  {
    float cq[8], sq[8];
#pragma unroll
    for (int q = 0; q < 8; ++q) {
      cq[q] = __shfl_sync(FULLMASK, mc, q, 8);
      sq[q] = __shfl_sync(FULLMASK, ms, q, 8);
    }
    float cprod = cq[0]*cq[1]*cq[2]*cq[3]*cq[4]*cq[5]*cq[6]*cq[7];
    float F = cprod * cprod * cprod;

    float b[16];
    b[0] = F * (g0 ? sq[0] : cq[0]) * (g1 ? sq[2] : cq[2]) * (g2 ? sq[4] : cq[4]);
#pragma unroll
    for (int i = 0; i < 1; ++i) { b[i+1] = b[i]*sq[7]; b[i] *= cq[7]; }
#pragma unroll
    for (int i = 0; i < 2; ++i) { b[i+2] = b[i]*sq[5]; b[i] *= cq[5]; }
#pragma unroll
    for (int i = 0; i < 4; ++i) { b[i+4] = b[i]*sq[3]; b[i] *= cq[3]; }
    // q1 doubling with cycle-1 CNOT(0,1) pre-applied (g0 swaps sin/cos roles):
    {
      float f_lo = g0 ? sq[1] : cq[1];
      float f_hi = g0 ? cq[1] : sq[1];
#pragma unroll
      for (int i = 0; i < 8; ++i) { b[i+8] = b[i]*f_hi; b[i] *= f_lo; }
    }

    u64 c6s6 = pk(cq[6], sq[6]);
#pragma unroll
    for (int k = 0; k < 16; ++k) P[k] = f2mul(pk(b[k], b[k]), c6s6);
  }

  float tg0 = g0 ? tq[0] : -tq[0];
  float tg2 = g1 ? tq[2] : -tq[2];
  float tg4 = g2 ? tq[4] : -tq[4];

  // cycle 1 CNOT ring; (0,1) pre-applied above, (7,0) deferred into cycle 2.
#pragma unroll
  for (int k = 0; k < 16; ++k) if (k & 8)   // (1,2): q1 ctrl -> lane1
    P[k] = __shfl_xor_sync(FULLMASK, P[k], 2);
  condswap<4>(P, g1);                       // (2,3)
#pragma unroll
  for (int k = 0; k < 16; ++k) if (k & 4)   // (3,4): q3 ctrl -> lane2
    P[k] = __shfl_xor_sync(FULLMASK, P[k], 4);
  condswap<2>(P, g2);                       // (4,5)
  // (5,6) + (6,7) combined repack: (5,6) swaps pack slots for k&2; (6,7)
  // exchanges hi halves across (k, k+1).
#pragma unroll
  for (int k = 0; k < 16; k += 2) {
    float l0, h0, l1, h1;
    unpk(P[k], l0, h0); unpk(P[k+1], l1, h1);
    if (k & 2) { P[k] = pk(h0, l1); P[k+1] = pk(h1, l0); }
    else       { P[k] = pk(l0, h1); P[k+1] = pk(l1, h0); }
  }

  // --- cycles 2..4 (tan form; RY+CNOT fused everywhere) ---
  {
    u64 tgg0 = pk(tg0, tg0);
    u64 tgg2 = pk(tg2, tg2), tgg2n = pk(-tg2, -tg2);
    u64 tgg4 = pk(tg4, tg4), tgg4n = pk(-tg4, -tg4);

    // 4-const packs for fused RY(reg)+laneCNOT: f ? (t,1,1,-t) : (1,-t,t,1)
    float t1 = tq[1], t3 = tq[3], t5 = tq[5];
    u64 a1 = pk(g0?t1:1.f, g0?t1:1.f),  b1p = pk(g0?1.f:-t1, g0?1.f:-t1);
    u64 g1p = pk(g0?1.f:t1, g0?1.f:t1), d1 = pk(g0?-t1:1.f, g0?-t1:1.f);
    u64 a3 = pk(g1?t3:1.f, g1?t3:1.f),  b3p = pk(g1?1.f:-t3, g1?1.f:-t3);
    u64 g3p = pk(g1?1.f:t3, g1?1.f:t3), d3 = pk(g1?-t3:1.f, g1?-t3:1.f);
    u64 a5 = pk(g2?t5:1.f, g2?t5:1.f),  b5p = pk(g2?1.f:-t5, g2?1.f:-t5);
    u64 g5p = pk(g2?1.f:t5, g2?1.f:t5), d5 = pk(g2?-t5:1.f, g2?-t5:1.f);

    float t6 = tq[6], t7 = tq[7];

#pragma unroll
    for (int cy = 0; cy < 3; ++cy) {
      cnot_ry_lane_t<1, 1>(P, tgg0);               // CNOT(7,0)[prev] + RY q0
      ry_cnot_reg<8>(P, a1, b1p, g1p, d1);         // RY q1 + CNOT(0,1)
      ry_lane_cnot_t<2, 8>(P, tgg2, tgg2n);        // RY q2 + CNOT(1,2)
      ry_cnot_reg<4>(P, a3, b3p, g3p, d3);         // RY q3 + CNOT(2,3)
      ry_lane_cnot_t<4, 4>(P, tgg4, tgg4n);        // RY q4 + CNOT(3,4)
      ry_cnot_reg<2>(P, a5, b5p, g5p, d5);         // RY q5 + CNOT(4,5)
      ry_pack_cnot56_s(P, t6);                     // RY q6 + CNOT(5,6)
      ry_q7_cnot67_s(P, t7);                       // RY q7 + CNOT(6,7)
    }
  }

  // final standalone CNOT(7,0)
#pragma unroll
  for (int k = 0; k < 16; ++k) if (k & 1)
    P[k] = __shfl_xor_sync(FULLMASK, P[k], 1);

  // =================== LAYER PHASE (identical algebra to R10) ==============
  u64 Cr[16], Ci[16];
  float ct_l0, ct_l1, c0, c1;

  // --- layer 0 ---
  {
    float cc, sh; sincosf(0.5f * crx_theta[0], &sh, &cc);
    c0 = cc;
    float t0 = __fdividef(sh, cc);
    float t0u = sh;                          // t0 * c0 (exact)
    float t0d = __fdividef(sh, cc * cc);     // t0 / c0

    // CRX(0,1) on REAL state (tan): weight c0^[g0] per lane -> expval.
    {
      float thl = g0 ? -t0 : 0.0f;
      u64 thlp = pk(thl, thl);
#pragma unroll
      for (int k = 0; k < 16; ++k) {
        Cr[k] = P[k];
        Ci[k] = f2mul(thlp, P[k ^ 8]);
      }
    }

    // CRX(2,3): lane1 ctrl (tan), weight c0^[g1] per lane -> expval.
    {
      float thl = g1 ? t0 : 0.0f;
      u64 tp = pk(thl, thl), tn = pk(-thl, -thl);
#pragma unroll
      for (int k = 0; k < 16; ++k) if (!(k & 4))
        CRXT_PAIR(Cr[k], Ci[k], Cr[k+4], Ci[k+4], tp, tn);
    }

    // CRX(4,5): lane2 ctrl (tan), weight c0^[g2] per lane -> expval.
    {
      float thl = g2 ? t0 : 0.0f;
      u64 tp = pk(thl, thl), tn = pk(-thl, -thl);
#pragma unroll
      for (int k = 0; k < 16; ++k) if (!(k & 2))
        CRXT_PAIR(Cr[k], Ci[k], Cr[k+2], Ci[k+2], tp, tn);
    }

    // CRX(6,7): pack-hi ctrl (tan, masked), weight (1,c0) on pack -> expval fold.
    {
      u64 tp = pk(0.0f, t0), tn = pk(0.0f, -t0);
#pragma unroll
      for (int k = 0; k < 16; ++k) if (!(k & 1))
        CRXT_PAIR(Cr[k], Ci[k], Cr[k+1], Ci[k+1], tp, tn);
    }

    // CRX(1,2): ctrl q1 (k&8), target lane1. th = g1 ? t0/c0 : t0*c0.
    {
      float th12 = g1 ? t0d : t0u;
      u64 tp = pk(th12, th12), tn = pk(-th12, -th12);
#pragma unroll
      for (int k = 0; k < 16; ++k) if (k & 8) {
        u64 pr = __shfl_xor_sync(FULLMASK, Cr[k], 2);
        u64 pi = __shfl_xor_sync(FULLMASK, Ci[k], 2);
        Cr[k] = f2fma(tp, pi, Cr[k]);
        Ci[k] = f2fma(tn, pr, Ci[k]);
      }
    }

    // CRX(3,4): ctrl q3 (k&4), target lane2. th = g2 ? t0/c0 : t0*c0.
    {
      float th34 = g2 ? t0d : t0u;
      u64 tp = pk(th34, th34), tn = pk(-th34, -th34);
#pragma unroll
      for (int k = 0; k < 16; ++k) if (k & 4) {
        u64 pr = __shfl_xor_sync(FULLMASK, Cr[k], 4);
        u64 pi = __shfl_xor_sync(FULLMASK, Ci[k], 4);
        Cr[k] = f2fma(tp, pi, Cr[k]);
        Ci[k] = f2fma(tn, pr, Ci[k]);
      }
    }

    // CRX(5,6): ctrl q5 (k&2), target q6 (pack). Slot ths (t0*c0, t0/c0). SCALAR.
#pragma unroll
    for (int k = 0; k < 16; ++k) if (k & 2) {
      float rl, rh, il, ih;
      unpk(Cr[k], rl, rh); unpk(Ci[k], il, ih);
      float nrl = fmaf(t0u, ih, rl);
      float nrh = fmaf(t0d, il, rh);
      float nil = fmaf(-t0u, rh, il);
      float nih = fmaf(-t0d, rl, ih);
      Cr[k] = pk(nrl, nrh);
      Ci[k] = pk(nil, nih);
    }

    // U3(layer 0), tan form. q1/q3/q5 use c0-scaled v1-column; q7 unscaled.
    float uth = u3_params[0], uph = u3_params[1], ulm = u3_params[2];
    float ct, st;  sincosf(0.5f * uth, &st, &ct);
    ct_l0 = ct;
    float tu = __fdividef(st, ct);
    float clm, slm; sincosf(ulm, &slm, &clm);
    float cph, sph; sincosf(uph, &sph, &cph);
    float cpl, spl; sincosf(uph + ulm, &spl, &cpl);
    float Ar = clm * tu, Ai = slm * tu;
    float Cc = cph * tu, Cs = sph * tu;
    float Er = cpl,      Ei = spl;
    u64 pCc = pk(Cc, Cc), pCsn = pk(-Cs, -Cs), pCsp = pk(Cs, Cs);
    {
      float Ars = Ar * c0, Ais = Ai * c0, Ers = Er * c0, Eis = Ei * c0;
      u64 sArn = pk(-Ars, -Ars), sAip = pk(Ais, Ais), sAin = pk(-Ais, -Ais);
      u64 sEr = pk(Ers, Ers), sEin = pk(-Eis, -Eis), sEip = pk(Eis, Eis);
#pragma unroll
      for (int k = 0; k < 16; ++k) if (!(k & 8))
        U3T_PAIR(Cr[k], Ci[k], Cr[k+8], Ci[k+8],
                 sArn, sAip, sAin, pCc, pCsn, pCsp, sEr, sEin, sEip);
#pragma unroll
      for (int k = 0; k < 16; ++k) if (!(k & 4))
        U3T_PAIR(Cr[k], Ci[k], Cr[k+4], Ci[k+4],
                 sArn, sAip, sAin, pCc, pCsn, pCsp, sEr, sEin, sEip);
#pragma unroll
      for (int k = 0; k < 16; ++k) if (!(k & 2))
        U3T_PAIR(Cr[k], Ci[k], Cr[k+2], Ci[k+2],
                 sArn, sAip, sAin, pCc, pCsn, pCsp, sEr, sEin, sEip);
    }
    {
      u64 uArn = pk(-Ar, -Ar), uAip = pk(Ai, Ai), uAin = pk(-Ai, -Ai);
      u64 uEr = pk(Er, Er), uEin = pk(-Ei, -Ei), uEip = pk(Ei, Ei);
#pragma unroll
      for (int k = 0; k < 16; ++k) if (!(k & 1))
        U3T_PAIR(Cr[k], Ci[k], Cr[k+1], Ci[k+1],
                 uArn, uAip, uAin, pCc, pCsn, pCsp, uEr, uEin, uEip);
    }
  }

  // --- layer 1 ---
  {
    float cc, sh; sincosf(0.5f * crx_theta[1], &sh, &cc);
    c1 = cc;
    float t1 = __fdividef(sh, cc);
    float t1u = sh;                          // t1 * c1 (exact)
    float t1d = __fdividef(sh, cc * cc);     // t1 / c1
    u64 tp = pk(t1, t1), tn = pk(-t1, -t1);

    // CRX(1,3): ctrl q1 (tan). Weight c1 on k&8 -> expval.
#pragma unroll
    for (int k = 0; k < 16; ++k) if ((k & 8) && !(k & 4))
      CRXT_PAIR(Cr[k], Ci[k], Cr[k+4], Ci[k+4], tp, tn);

    // CRX(5,7): ctrl q5 (tan). Weight c1 on k&2 -> survives (3,5) -> expval.
#pragma unroll
    for (int k = 0; k < 16; ++k) if ((k & 2) && !(k & 1))
      CRXT_PAIR(Cr[k], Ci[k], Cr[k+1], Ci[k+1], tp, tn);

    // CRX(3,5): ctrl q3, target q5. Split th for q5 weight c1.
    {
      u64 tup = pk(t1u, t1u), tun = pk(-t1u, -t1u);
      u64 tdp = pk(t1d, t1d), tdn = pk(-t1d, -t1d);
#pragma unroll
      for (int k = 0; k < 16; ++k) if ((k & 4) && !(k & 2))
        CRXT_PAIR2(Cr[k], Ci[k], Cr[k+2], Ci[k+2], tup, tun, tdp, tdn);
    }

    float uth = u3_params[3], uph = u3_params[4], ulm = u3_params[5];
    float ct, st;  sincosf(0.5f * uth, &st, &ct);
    ct_l1 = ct;
    float tu = __fdividef(st, ct);
    float clm, slm; sincosf(ulm, &slm, &clm);
    float cph, sph; sincosf(uph, &sph, &cph);
    float cpl, spl; sincosf(uph + ulm, &spl, &cpl);
    float Ar = clm * tu, Ai = slm * tu;
    float Cc = cph * tu, Cs = sph * tu;
    float Er = cpl,      Ei = spl;
    u64 pCc = pk(Cc, Cc), pCsn = pk(-Cs, -Cs), pCsp = pk(Cs, Cs);
    {
      // U3(q3): c1-scaled column absorbs CRX(3,5) control weight.
      float Ars = Ar * c1, Ais = Ai * c1, Ers = Er * c1, Eis = Ei * c1;
      u64 sArn = pk(-Ars, -Ars), sAip = pk(Ais, Ais), sAin = pk(-Ais, -Ais);
      u64 sEr = pk(Ers, Ers), sEin = pk(-Eis, -Eis), sEip = pk(Eis, Eis);
#pragma unroll
      for (int k = 0; k < 16; ++k) if (!(k & 4))
        U3T_PAIR(Cr[k], Ci[k], Cr[k+4], Ci[k+4],
                 sArn, sAip, sAin, pCc, pCsn, pCsp, sEr, sEin, sEip);
    }
    {
      // U3(q7): unscaled.
      u64 uArn = pk(-Ar, -Ar), uAip = pk(Ai, Ai), uAin = pk(-Ai, -Ai);
      u64 uEr = pk(Er, Er), uEin = pk(-Ei, -Ei), uEip = pk(Ei, Ei);
#pragma unroll
      for (int k = 0; k < 16; ++k) if (!(k & 1))
        U3T_PAIR(Cr[k], Ci[k], Cr[k+1], Ci[k+1],
                 uArn, uAip, uAin, pCc, pCsn, pCsp, uEr, uEin, uEip);
    }
  }

  // --- expval with deferred weights (same as R10) ---
  float c1sq = c1 * c1;
  float c1q  = c1sq * c1sq;
  u64 pc2 = pk(c1sq, c1sq), pc4 = pk(c1q, c1q);

  u64 acc0 = pk(0.f, 0.f), acc1 = acc0, acc2 = acc0, acc3 = acc0;
#pragma unroll
  for (int k = 0; k < 16; ++k) {
    u64 pp = f2fma(Cr[k], Cr[k], f2mul(Ci[k], Ci[k]));
    const int nb = ((k >> 3) & 1) + ((k >> 1) & 1);
    if (nb == 1)      pp = f2mul(pp, pc2);
    else if (nb == 2) pp = f2mul(pp, pc4);
    int idx = ((k & 4) ? 2 : 0) | (k & 1);
    if      (idx == 0) acc0 = f2add(acc0, pp);
    else if (idx == 1) acc1 = f2add(acc1, pp);
    else if (idx == 2) acc2 = f2add(acc2, pp);
    else               acc3 = f2add(acc3, pp);
  }
  float c02 = c0 * c0;
  float l, h, s0, s1, s2, s3;
  unpk(acc0, l, h); s0 = fmaf(c02, h, l);
  unpk(acc1, l, h); s1 = fmaf(c02, h, l);
  unpk(acc2, l, h); s2 = fmaf(c02, h, l);
  unpk(acc3, l, h); s3 = fmaf(c02, h, l);
  float z3 = (s0 + s1) - (s2 + s3);
  float z7 = (s0 + s2) - (s1 + s3);

  {
    float lw2 = 1.0f;
    if (g0) lw2 *= c02;
    if (g1) lw2 *= c02;
    if (g2) lw2 *= c02;
    z3 *= lw2;
    z7 *= lw2;
  }

  z3 += __shfl_xor_sync(FULLMASK, z3, 1);
  z3 += __shfl_xor_sync(FULLMASK, z3, 2);
  z3 += __shfl_xor_sync(FULLMASK, z3, 4);
  z7 += __shfl_xor_sync(FULLMASK, z7, 1);
  z7 += __shfl_xor_sync(FULLMASK, z7, 2);
  z7 += __shfl_xor_sync(FULLMASK, z7, 4);

  // --- MLP head (deferred U3 scale G^2, G = ct0^4 * ct1^2) ---
  if (g == 0) {
    float ct0sq = ct_l0 * ct_l0;
    float Gs = ct0sq * ct0sq * ct_l1 * ct_l1;
    float G2 = Gs * Gs;
    z3 *= G2;
    z7 *= G2;
    float o = b2[0];
#pragma unroll
    for (int j = 0; j < 10; ++j) {
      float hh = tanhf(z3 * w1[j] + z7 * w1[10 + j] + b1[j]);
      o += hh * w2[j];
    }
    out[elem] = 1.0f / (1.0f + expf(-o));
  }
}

extern "C" void kernel_launch(void* const* d_in, const int* in_sizes, int n_in,
                              void* d_out, int out_size) {
  const float* x   = (const float*)d_in[0];
  const float* crx = (const float*)d_in[1];
  const float* u3p = (const float*)d_in[2];
  const float* w1  = (const float*)d_in[3];
  const float* b1  = (const float*)d_in[4];
  const float* w2  = (const float*)d_in[5];
  const float* b2  = (const float*)d_in[6];
  float* out = (float*)d_out;

  int B = in_sizes[0] / 8;
  int threads = B * 8;
  int block = 128;
  int grid = (threads + block - 1) / block;
  qcnn_kernel<<<grid, block>>>(x, crx, u3p, w1, b1, w2, b2, out, B);
}

// round 15
// speedup vs baseline: 3.6189x; 1.1666x over previous
#include <cuda_runtime.h>
#include <math.h>

#define FULLMASK 0xffffffffu
typedef unsigned long long u64;

// ---- packed f32x2 primitives (sm_103a; ptxas won't emit these from C++) ----
__device__ __forceinline__ u64 pk(float lo, float hi) {
  u64 r; asm("mov.b64 %0, {%1,%2};" : "=l"(r) : "f"(lo), "f"(hi)); return r;
}
__device__ __forceinline__ void unpk(u64 v, float& lo, float& hi) {
  asm("mov.b64 {%0,%1}, %2;" : "=f"(lo), "=f"(hi) : "l"(v));
}
__device__ __forceinline__ u64 f2fma(u64 a, u64 b, u64 c) {
  u64 d; asm("fma.rn.f32x2 %0, %1, %2, %3;" : "=l"(d) : "l"(a), "l"(b), "l"(c)); return d;
}
__device__ __forceinline__ u64 f2mul(u64 a, u64 b) {
  u64 d; asm("mul.rn.f32x2 %0, %1, %2;" : "=l"(d) : "l"(a), "l"(b)); return d;
}
__device__ __forceinline__ u64 f2add(u64 a, u64 b) {
  u64 d; asm("add.rn.f32x2 %0, %1, %2;" : "=l"(d) : "l"(a), "l"(b)); return d;
}

// ---------------------------------------------------------------------------
// Layout: 8 lanes per element (g = tid&7).
// Lane bits: q0 -> xor 1, q2 -> xor 2, q4 -> xor 4.  PACK AXIS: q6.
// k index: bit3=q1(8), bit2=q3(4), bit1=q5(2), bit0=q7(1).
// Same circuit algebra as the passing R14 kernel. New here:
//  - uniform trig (crx/u3 params) computed ONCE per 8-lane group (1 sincosf
//    per lane, broadcast at layer-phase entry; compound angles via identities)
//  - MLP head parallelized over the 8 lanes (2 serial tanh instead of 10)
// ---------------------------------------------------------------------------

template<int TMk>
__device__ __forceinline__ void ry_cnot_reg(u64 (&P)[16], u64 pa, u64 pb, u64 pg, u64 pd) {
#pragma unroll
  for (int k = 0; k < 16; ++k) if (!(k & TMk)) {
    u64 A = P[k], B = P[k + TMk];
    P[k]       = f2fma(pa, A, f2mul(pb, B));
    P[k + TMk] = f2fma(pg, A, f2mul(pd, B));
  }
}

template<int LM, int KM>
__device__ __forceinline__ void ry_lane_cnot_t(u64 (&P)[16], u64 tgg, u64 tggn) {
#pragma unroll
  for (int k = 0; k < 16; ++k) {
    u64 p = __shfl_xor_sync(FULLMASK, P[k], LM);
    if (k & KM) P[k] = f2fma(tggn, P[k], p);
    else        P[k] = f2fma(tgg, p, P[k]);
  }
}

template<int LM, int KM>
__device__ __forceinline__ void cnot_ry_lane_t(u64 (&P)[16], u64 tgg) {
#pragma unroll
  for (int k = 0; k < 16; ++k) {
    u64 p = __shfl_xor_sync(FULLMASK, P[k], LM);
    if (k & KM) P[k] = f2fma(tgg, P[k], p);
    else        P[k] = f2fma(tgg, p, P[k]);
  }
}

template<int TMk>
__device__ __forceinline__ void condswap(u64 (&P)[16], bool f) {
#pragma unroll
  for (int k = 0; k < 16; ++k) if (!(k & TMk)) {
    u64 A = P[k], B = P[k + TMk];
    P[k]       = f ? B : A;
    P[k + TMk] = f ? A : B;
  }
}

__device__ __forceinline__ void ry_pack_cnot56_s(u64 (&P)[16], float t6) {
#pragma unroll
  for (int k = 0; k < 16; ++k) {
    float l, h; unpk(P[k], l, h);
    float a = fmaf(-t6, h, l);
    float b = fmaf(t6, l, h);
    P[k] = (k & 2) ? pk(b, a) : pk(a, b);
  }
}

__device__ __forceinline__ void ry_q7_cnot67_s(u64 (&P)[16], float t7) {
#pragma unroll
  for (int k = 0; k < 16; k += 2) {
    float al, ah, bl, bh;
    unpk(P[k], al, ah); unpk(P[k + 1], bl, bh);
    float xl = fmaf(-t7, bl, al);
    float xh = fmaf(-t7, bh, ah);
    float yl = fmaf(t7, al, bl);
    float yh = fmaf(t7, ah, bh);
    P[k]     = pk(xl, yh);
    P[k + 1] = pk(yl, xh);
  }
}

#define CRXT_PAIR(Cr0, Ci0, Cr1, Ci1, thp, thn)                     \
  {                                                                 \
    u64 _r0 = (Cr0), _i0 = (Ci0), _r1 = (Cr1), _i1 = (Ci1);         \
    (Cr0) = f2fma((thp), _i1, _r0);                                 \
    (Ci0) = f2fma((thn), _r1, _i0);                                 \
    (Cr1) = f2fma((thp), _i0, _r1);                                 \
    (Ci1) = f2fma((thn), _r0, _i1);                                 \
  }

#define CRXT_PAIR2(Cr0, Ci0, Cr1, Ci1, tup, tun, tdp, tdn)          \
  {                                                                 \
    u64 _r0 = (Cr0), _i0 = (Ci0), _r1 = (Cr1), _i1 = (Ci1);         \
    (Cr0) = f2fma((tup), _i1, _r0);                                 \
    (Ci0) = f2fma((tun), _r1, _i0);                                 \
    (Cr1) = f2fma((tdp), _i0, _r1);                                 \
    (Ci1) = f2fma((tdn), _r0, _i1);                                 \
  }

#define U3T_PAIR(Cr0, Ci0, Cr1, Ci1, Arn, Aip, Ain, Cc_, Csn, Csp, Er_, Ein, Eip) \
  {                                                                             \
    u64 _r0 = (Cr0), _i0 = (Ci0), _r1 = (Cr1), _i1 = (Ci1);                     \
    (Cr0) = f2fma(Arn, _r1, f2fma(Aip, _i1, _r0));                              \
    (Ci0) = f2fma(Arn, _i1, f2fma(Ain, _r1, _i0));                              \
    (Cr1) = f2fma(Cc_, _r0, f2fma(Csn, _i0, f2fma(Er_, _r1, f2mul(Ein, _i1)))); \
    (Ci1) = f2fma(Cc_, _i0, f2fma(Csp, _r0, f2fma(Er_, _i1, f2mul(Eip, _r1)))); \
  }

__global__ void __launch_bounds__(128, 5)
qcnn_kernel(const float* __restrict__ x,
            const float* __restrict__ crx_theta,
            const float* __restrict__ u3_params,
            const float* __restrict__ w1,
            const float* __restrict__ b1,
            const float* __restrict__ w2,
            const float* __restrict__ b2,
            float* __restrict__ out, int B)
{
  int tid  = blockIdx.x * blockDim.x + threadIdx.x;
  int elem = tid >> 3;
  if (elem >= B) return;
  int g = tid & 7;
  bool g0 = (g & 1) != 0;
  bool g1 = (g & 2) != 0;
  bool g2 = (g & 4) != 0;

  // --- per-element angles ---
  float myx = x[elem * 8 + g];
  float ms, mc;
  sincosf(0.5f * myx, &ms, &mc);
  float mt = __fdividef(ms, mc);

  // --- uniform trig: ONE sincosf per lane (launch-uniform params) ---
  // lane 0: 0.5*crx0 | 1: 0.5*crx1 | 2: 0.5*uth0 | 3: uph0 | 4: ulm0
  // lane 5: 0.5*uth1 | 6: uph1 | 7: ulm1
  float us, ucv;
  {
    float ua = (g < 2) ? 0.5f * crx_theta[g] : u3_params[g - 2];
    if (g == 2 || g == 5) ua *= 0.5f;
    sincosf(ua, &us, &ucv);
  }

  float tq[8];
#pragma unroll
  for (int q = 0; q < 8; ++q) tq[q] = __shfl_sync(FULLMASK, mt, q, 8);

  u64 P[16];
  {
    float cq[8], sq[8];
#pragma unroll
    for (int q = 0; q < 8; ++q) {
      cq[q] = __shfl_sync(FULLMASK, mc, q, 8);
      sq[q] = __shfl_sync(FULLMASK, ms, q, 8);
    }
    float cprod = cq[0]*cq[1]*cq[2]*cq[3]*cq[4]*cq[5]*cq[6]*cq[7];
    float F = cprod * cprod * cprod;

    float b[16];
    b[0] = F * (g0 ? sq[0] : cq[0]) * (g1 ? sq[2] : cq[2]) * (g2 ? sq[4] : cq[4]);
#pragma unroll
    for (int i = 0; i < 1; ++i) { b[i+1] = b[i]*sq[7]; b[i] *= cq[7]; }
#pragma unroll
    for (int i = 0; i < 2; ++i) { b[i+2] = b[i]*sq[5]; b[i] *= cq[5]; }
#pragma unroll
    for (int i = 0; i < 4; ++i) { b[i+4] = b[i]*sq[3]; b[i] *= cq[3]; }
    {
      float f_lo = g0 ? sq[1] : cq[1];
      float f_hi = g0 ? cq[1] : sq[1];
#pragma unroll
      for (int i = 0; i < 8; ++i) { b[i+8] = b[i]*f_hi; b[i] *= f_lo; }
    }

    u64 c6s6 = pk(cq[6], sq[6]);
#pragma unroll
    for (int k = 0; k < 16; ++k) P[k] = f2mul(pk(b[k], b[k]), c6s6);
  }

  float tg0 = g0 ? tq[0] : -tq[0];
  float tg2 = g1 ? tq[2] : -tq[2];
  float tg4 = g2 ? tq[4] : -tq[4];

  // cycle 1 CNOT ring; (0,1) pre-applied, (7,0) deferred into cycle 2.
#pragma unroll
  for (int k = 0; k < 16; ++k) if (k & 8)
    P[k] = __shfl_xor_sync(FULLMASK, P[k], 2);
  condswap<4>(P, g1);
#pragma unroll
  for (int k = 0; k < 16; ++k) if (k & 4)
    P[k] = __shfl_xor_sync(FULLMASK, P[k], 4);
  condswap<2>(P, g2);
#pragma unroll
  for (int k = 0; k < 16; k += 2) {
    float l0, h0, l1, h1;
    unpk(P[k], l0, h0); unpk(P[k+1], l1, h1);
    if (k & 2) { P[k] = pk(h0, l1); P[k+1] = pk(h1, l0); }
    else       { P[k] = pk(l0, h1); P[k+1] = pk(l1, h0); }
  }

  // --- cycles 2..4 (tan form; RY+CNOT fused everywhere) ---
  {
    u64 tgg0 = pk(tg0, tg0);
    u64 tgg2 = pk(tg2, tg2), tgg2n = pk(-tg2, -tg2);
    u64 tgg4 = pk(tg4, tg4), tgg4n = pk(-tg4, -tg4);

    float t1 = tq[1], t3 = tq[3], t5 = tq[5];
    u64 a1 = pk(g0?t1:1.f, g0?t1:1.f),  b1p = pk(g0?1.f:-t1, g0?1.f:-t1);
    u64 g1p = pk(g0?1.f:t1, g0?1.f:t1), d1 = pk(g0?-t1:1.f, g0?-t1:1.f);
    u64 a3 = pk(g1?t3:1.f, g1?t3:1.f),  b3p = pk(g1?1.f:-t3, g1?1.f:-t3);
    u64 g3p = pk(g1?1.f:t3, g1?1.f:t3), d3 = pk(g1?-t3:1.f, g1?-t3:1.f);
    u64 a5 = pk(g2?t5:1.f, g2?t5:1.f),  b5p = pk(g2?1.f:-t5, g2?1.f:-t5);
    u64 g5p = pk(g2?1.f:t5, g2?1.f:t5), d5 = pk(g2?-t5:1.f, g2?-t5:1.f);

    float t6 = tq[6], t7 = tq[7];

#pragma unroll
    for (int cy = 0; cy < 3; ++cy) {
      cnot_ry_lane_t<1, 1>(P, tgg0);               // CNOT(7,0)[prev] + RY q0
      ry_cnot_reg<8>(P, a1, b1p, g1p, d1);         // RY q1 + CNOT(0,1)
      ry_lane_cnot_t<2, 8>(P, tgg2, tgg2n);        // RY q2 + CNOT(1,2)
      ry_cnot_reg<4>(P, a3, b3p, g3p, d3);         // RY q3 + CNOT(2,3)
      ry_lane_cnot_t<4, 4>(P, tgg4, tgg4n);        // RY q4 + CNOT(3,4)
      ry_cnot_reg<2>(P, a5, b5p, g5p, d5);         // RY q5 + CNOT(4,5)
      ry_pack_cnot56_s(P, t6);                     // RY q6 + CNOT(5,6)
      ry_q7_cnot67_s(P, t7);                       // RY q7 + CNOT(6,7)
    }
  }

  // final standalone CNOT(7,0)
#pragma unroll
  for (int k = 0; k < 16; ++k) if (k & 1)
    P[k] = __shfl_xor_sync(FULLMASK, P[k], 1);

  // --- broadcast uniform trig (group-wide, computed once per lane above) ---
  float sh0  = __shfl_sync(FULLMASK, us, 0, 8), cc0  = __shfl_sync(FULLMASK, ucv, 0, 8);
  float sh1  = __shfl_sync(FULLMASK, us, 1, 8), cc1  = __shfl_sync(FULLMASK, ucv, 1, 8);
  float st0  = __shfl_sync(FULLMASK, us, 2, 8), ct0  = __shfl_sync(FULLMASK, ucv, 2, 8);
  float sph0 = __shfl_sync(FULLMASK, us, 3, 8), cph0 = __shfl_sync(FULLMASK, ucv, 3, 8);
  float slm0 = __shfl_sync(FULLMASK, us, 4, 8), clm0 = __shfl_sync(FULLMASK, ucv, 4, 8);
  float st1  = __shfl_sync(FULLMASK, us, 5, 8), ct1  = __shfl_sync(FULLMASK, ucv, 5, 8);
  float sph1 = __shfl_sync(FULLMASK, us, 6, 8), cph1 = __shfl_sync(FULLMASK, ucv, 6, 8);
  float slm1 = __shfl_sync(FULLMASK, us, 7, 8), clm1 = __shfl_sync(FULLMASK, ucv, 7, 8);

  // =================== LAYER PHASE (same algebra as R14) ===================
  u64 Cr[16], Ci[16];

  // --- layer 0 ---
  {
    float cc = cc0, sh = sh0;
    float t0 = __fdividef(sh, cc);
    float t0u = sh;                          // t0 * c0 (exact)
    float t0d = __fdividef(sh, cc * cc);     // t0 / c0

    // CRX(0,1) on REAL state (tan).
    {
      float thl = g0 ? -t0 : 0.0f;
      u64 thlp = pk(thl, thl);
#pragma unroll
      for (int k = 0; k < 16; ++k) {
        Cr[k] = P[k];
        Ci[k] = f2mul(thlp, P[k ^ 8]);
      }
    }

    // CRX(2,3)
    {
      float thl = g1 ? t0 : 0.0f;
      u64 tp = pk(thl, thl), tn = pk(-thl, -thl);
#pragma unroll
      for (int k = 0; k < 16; ++k) if (!(k & 4))
        CRXT_PAIR(Cr[k], Ci[k], Cr[k+4], Ci[k+4], tp, tn);
    }

    // CRX(4,5)
    {
      float thl = g2 ? t0 : 0.0f;
      u64 tp = pk(thl, thl), tn = pk(-thl, -thl);
#pragma unroll
      for (int k = 0; k < 16; ++k) if (!(k & 2))
        CRXT_PAIR(Cr[k], Ci[k], Cr[k+2], Ci[k+2], tp, tn);
    }

    // CRX(6,7): masked th = (0, t0).
    {
      u64 tp = pk(0.0f, t0), tn = pk(0.0f, -t0);
#pragma unroll
      for (int k = 0; k < 16; ++k) if (!(k & 1))
        CRXT_PAIR(Cr[k], Ci[k], Cr[k+1], Ci[k+1], tp, tn);
    }

    // CRX(1,2)
    {
      float th12 = g1 ? t0d : t0u;
      u64 tp = pk(th12, th12), tn = pk(-th12, -th12);
#pragma unroll
      for (int k = 0; k < 16; ++k) if (k & 8) {
        u64 pr = __shfl_xor_sync(FULLMASK, Cr[k], 2);
        u64 pi = __shfl_xor_sync(FULLMASK, Ci[k], 2);
        Cr[k] = f2fma(tp, pi, Cr[k]);
        Ci[k] = f2fma(tn, pr, Ci[k]);
      }
    }

    // CRX(3,4)
    {
      float th34 = g2 ? t0d : t0u;
      u64 tp = pk(th34, th34), tn = pk(-th34, -th34);
#pragma unroll
      for (int k = 0; k < 16; ++k) if (k & 4) {
        u64 pr = __shfl_xor_sync(FULLMASK, Cr[k], 4);
        u64 pi = __shfl_xor_sync(FULLMASK, Ci[k], 4);
        Cr[k] = f2fma(tp, pi, Cr[k]);
        Ci[k] = f2fma(tn, pr, Ci[k]);
      }
    }

    // CRX(5,6): scalar slot ths (t0*c0, t0/c0).
#pragma unroll
    for (int k = 0; k < 16; ++k) if (k & 2) {
      float rl, rh, il, ih;
      unpk(Cr[k], rl, rh); unpk(Ci[k], il, ih);
      float nrl = fmaf(t0u, ih, rl);
      float nrh = fmaf(t0d, il, rh);
      float nil = fmaf(-t0u, rh, il);
      float nih = fmaf(-t0d, rl, ih);
      Cr[k] = pk(nrl, nrh);
      Ci[k] = pk(nil, nih);
    }

    // U3(layer 0), tan form (broadcast trig; compound angle by identity).
    float tu = __fdividef(st0, ct0);
    float cpl = cph0 * clm0 - sph0 * slm0;   // cos(uph0+ulm0)
    float spl = sph0 * clm0 + cph0 * slm0;   // sin(uph0+ulm0)
    float Ar = clm0 * tu, Ai = slm0 * tu;
    float Cc = cph0 * tu, Cs = sph0 * tu;
    float Er = cpl,       Ei = spl;
    u64 pCc = pk(Cc, Cc), pCsn = pk(-Cs, -Cs), pCsp = pk(Cs, Cs);
    {
      float Ars = Ar * cc, Ais = Ai * cc, Ers = Er * cc, Eis = Ei * cc;
      u64 sArn = pk(-Ars, -Ars), sAip = pk(Ais, Ais), sAin = pk(-Ais, -Ais);
      u64 sEr = pk(Ers, Ers), sEin = pk(-Eis, -Eis), sEip = pk(Eis, Eis);
#pragma unroll
      for (int k = 0; k < 16; ++k) if (!(k & 8))
        U3T_PAIR(Cr[k], Ci[k], Cr[k+8], Ci[k+8],
                 sArn, sAip, sAin, pCc, pCsn, pCsp, sEr, sEin, sEip);
#pragma unroll
      for (int k = 0; k < 16; ++k) if (!(k & 4))
        U3T_PAIR(Cr[k], Ci[k], Cr[k+4], Ci[k+4],
                 sArn, sAip, sAin, pCc, pCsn, pCsp, sEr, sEin, sEip);
#pragma unroll
      for (int k = 0; k < 16; ++k) if (!(k & 2))
        U3T_PAIR(Cr[k], Ci[k], Cr[k+2], Ci[k+2],
                 sArn, sAip, sAin, pCc, pCsn, pCsp, sEr, sEin, sEip);
    }
    {
      u64 uArn = pk(-Ar, -Ar), uAip = pk(Ai, Ai), uAin = pk(-Ai, -Ai);
      u64 uEr = pk(Er, Er), uEin = pk(-Ei, -Ei), uEip = pk(Ei, Ei);
#pragma unroll
      for (int k = 0; k < 16; ++k) if (!(k & 1))
        U3T_PAIR(Cr[k], Ci[k], Cr[k+1], Ci[k+1],
                 uArn, uAip, uAin, pCc, pCsn, pCsp, uEr, uEin, uEip);
    }
  }

  // --- layer 1 ---
  {
    float cc = cc1, sh = sh1;
    float t1 = __fdividef(sh, cc);
    float t1u = sh;
    float t1d = __fdividef(sh, cc * cc);
    u64 tp = pk(t1, t1), tn = pk(-t1, -t1);

#pragma unroll
    for (int k = 0; k < 16; ++k) if ((k & 8) && !(k & 4))     // CRX(1,3)
      CRXT_PAIR(Cr[k], Ci[k], Cr[k+4], Ci[k+4], tp, tn);
#pragma unroll
    for (int k = 0; k < 16; ++k) if ((k & 2) && !(k & 1))     // CRX(5,7)
      CRXT_PAIR(Cr[k], Ci[k], Cr[k+1], Ci[k+1], tp, tn);
    {
      u64 tup = pk(t1u, t1u), tun = pk(-t1u, -t1u);
      u64 tdp = pk(t1d, t1d), tdn = pk(-t1d, -t1d);
#pragma unroll
      for (int k = 0; k < 16; ++k) if ((k & 4) && !(k & 2))   // CRX(3,5)
        CRXT_PAIR2(Cr[k], Ci[k], Cr[k+2], Ci[k+2], tup, tun, tdp, tdn);
    }

    float tu = __fdividef(st1, ct1);
    float cpl = cph1 * clm1 - sph1 * slm1;
    float spl = sph1 * clm1 + cph1 * slm1;
    float Ar = clm1 * tu, Ai = slm1 * tu;
    float Cc = cph1 * tu, Cs = sph1 * tu;
    float Er = cpl,       Ei = spl;
    u64 pCc = pk(Cc, Cc), pCsn = pk(-Cs, -Cs), pCsp = pk(Cs, Cs);
    {
      float Ars = Ar * cc, Ais = Ai * cc, Ers = Er * cc, Eis = Ei * cc;
      u64 sArn = pk(-Ars, -Ars), sAip = pk(Ais, Ais), sAin = pk(-Ais, -Ais);
      u64 sEr = pk(Ers, Ers), sEin = pk(-Eis, -Eis), sEip = pk(Eis, Eis);
#pragma unroll
      for (int k = 0; k < 16; ++k) if (!(k & 4))              // U3 q3 (scaled)
        U3T_PAIR(Cr[k], Ci[k], Cr[k+4], Ci[k+4],
                 sArn, sAip, sAin, pCc, pCsn, pCsp, sEr, sEin, sEip);
    }
    {
      u64 uArn = pk(-Ar, -Ar), uAip = pk(Ai, Ai), uAin = pk(-Ai, -Ai);
      u64 uEr = pk(Er, Er), uEin = pk(-Ei, -Ei), uEip = pk(Ei, Ei);
#pragma unroll
      for (int k = 0; k < 16; ++k) if (!(k & 1))              // U3 q7
        U3T_PAIR(Cr[k], Ci[k], Cr[k+1], Ci[k+1],
                 uArn, uAip, uAin, pCc, pCsn, pCsp, uEr, uEin, uEip);
    }
  }

  // --- expval with deferred weights ---
  float c1sq = cc1 * cc1;
  float c1q  = c1sq * c1sq;
  u64 pc2 = pk(c1sq, c1sq), pc4 = pk(c1q, c1q);

  u64 acc0 = pk(0.f, 0.f), acc1 = acc0, acc2 = acc0, acc3 = acc0;
#pragma unroll
  for (int k = 0; k < 16; ++k) {
    u64 pp = f2fma(Cr[k], Cr[k], f2mul(Ci[k], Ci[k]));
    const int nb = ((k >> 3) & 1) + ((k >> 1) & 1);
    if (nb == 1)      pp = f2mul(pp, pc2);
    else if (nb == 2) pp = f2mul(pp, pc4);
    int idx = ((k & 4) ? 2 : 0) | (k & 1);
    if      (idx == 0) acc0 = f2add(acc0, pp);
    else if (idx == 1) acc1 = f2add(acc1, pp);
    else if (idx == 2) acc2 = f2add(acc2, pp);
    else               acc3 = f2add(acc3, pp);
  }
  float c02 = cc0 * cc0;
  float l, h, s0, s1, s2, s3;
  unpk(acc0, l, h); s0 = fmaf(c02, h, l);
  unpk(acc1, l, h); s1 = fmaf(c02, h, l);
  unpk(acc2, l, h); s2 = fmaf(c02, h, l);
  unpk(acc3, l, h); s3 = fmaf(c02, h, l);
  float z3 = (s0 + s1) - (s2 + s3);
  float z7 = (s0 + s2) - (s1 + s3);

  {
    float lw2 = 1.0f;
    if (g0) lw2 *= c02;
    if (g1) lw2 *= c02;
    if (g2) lw2 *= c02;
    z3 *= lw2;
    z7 *= lw2;
  }

  z3 += __shfl_xor_sync(FULLMASK, z3, 1);
  z3 += __shfl_xor_sync(FULLMASK, z3, 2);
  z3 += __shfl_xor_sync(FULLMASK, z3, 4);
  z7 += __shfl_xor_sync(FULLMASK, z7, 1);
  z7 += __shfl_xor_sync(FULLMASK, z7, 2);
  z7 += __shfl_xor_sync(FULLMASK, z7, 4);

  // --- MLP head, parallel over the 8 group lanes ---
  {
    // deferred U3 scale G^2, G = ct0^4 * ct1^2 (uniform; all lanes)
    float ct0sq = ct0 * ct0;
    float Gs = ct0sq * ct0sq * ct1 * ct1;
    float G2 = Gs * Gs;
    z3 *= G2;
    z7 *= G2;

    int j = g;
    float hh = tanhf(fmaf(z3, w1[j], fmaf(z7, w1[10 + j], b1[j])));
    float part = hh * w2[j];
    if (g < 2) {
      int j2 = 8 + g;
      float hh2 = tanhf(fmaf(z3, w1[j2], fmaf(z7, w1[10 + j2], b1[j2])));
      part = fmaf(hh2, w2[j2], part);
    }
    part += __shfl_xor_sync(FULLMASK, part, 1);
    part += __shfl_xor_sync(FULLMASK, part, 2);
    part += __shfl_xor_sync(FULLMASK, part, 4);

    if (g == 0)
      out[elem] = 1.0f / (1.0f + expf(-(part + b2[0])));
  }
}

extern "C" void kernel_launch(void* const* d_in, const int* in_sizes, int n_in,
                              void* d_out, int out_size) {
  const float* x   = (const float*)d_in[0];
  const float* crx = (const float*)d_in[1];
  const float* u3p = (const float*)d_in[2];
  const float* w1  = (const float*)d_in[3];
  const float* b1  = (const float*)d_in[4];
  const float* w2  = (const float*)d_in[5];
  const float* b2  = (const float*)d_in[6];
  float* out = (float*)d_out;

  int B = in_sizes[0] / 8;
  int threads = B * 8;
  int block = 128;
  int grid = (threads + block - 1) / block;
  qcnn_kernel<<<grid, block>>>(x, crx, u3p, w1, b1, w2, b2, out, B);
}